// round 8
// baseline (speedup 1.0000x reference)
#include <cuda_runtime.h>
#include <cuda_bf16.h>
#include <cstdint>

// Problem constants (fixed by the dataset)
#define NN    20000
#define MPAD  20096        // 157 * 128
#define EE    320000
#define DD    128
#define HD    256
#define YW    768          // 3 rel * 2 head * 128
#define SCALE 16.0f

// ---------------- scratch (device globals; no allocation) ----------------
__device__ float          g_qt[(size_t)NN * YW];      // fp32 transformed queries [N,768]
__device__ __nv_bfloat16  g_xh[(size_t)MPAD * DD];
__device__ __nv_bfloat16  g_xl[(size_t)MPAD * DD];
__device__ __nv_bfloat16  g_wsch[(size_t)YW * DD];    // Wsc = WK^T WQ blocks, hi/lo [768,128]
__device__ __nv_bfloat16  g_wscl[(size_t)YW * DD];
__device__ __nv_bfloat16  g_wfh[(size_t)DD * YW];     // Wfin = WO x WV blocks, hi/lo [128,768]
__device__ __nv_bfloat16  g_wfl[(size_t)DD * YW];
__device__ __nv_bfloat16  g_yh[(size_t)MPAD * YW];    // weighted-x aggregate hi/lo
__device__ __nv_bfloat16  g_yl[(size_t)MPAD * YW];
__device__ int   g_deg[NN];
__device__ int   g_rowptr[NN + 1];
__device__ int   g_cursor[NN];
__device__ int   g_pack[EE];                          // CSR-ordered src | (rel<<15)

__device__ __forceinline__ uint32_t smem_u32(const void* p) {
    uint32_t a;
    asm("{ .reg .u64 t; cvta.to.shared.u64 t, %1; cvt.u32.u64 %0, t; }" : "=r"(a) : "l"(p));
    return a;
}
__device__ __forceinline__ void ldsm_x4(uint32_t& r0, uint32_t& r1, uint32_t& r2, uint32_t& r3,
                                        uint32_t addr) {
    asm volatile("ldmatrix.sync.aligned.m8n8.x4.shared.b16 {%0,%1,%2,%3}, [%4];"
                 : "=r"(r0), "=r"(r1), "=r"(r2), "=r"(r3) : "r"(addr));
}
__device__ __forceinline__ void mma_bf16(float* d, const uint32_t* a, const uint32_t* b) {
    asm volatile(
        "mma.sync.aligned.m16n8k16.row.col.f32.bf16.bf16.f32 "
        "{%0,%1,%2,%3}, {%4,%5,%6,%7}, {%8,%9}, {%0,%1,%2,%3};"
        : "+f"(d[0]), "+f"(d[1]), "+f"(d[2]), "+f"(d[3])
        : "r"(a[0]), "r"(a[1]), "r"(a[2]), "r"(a[3]), "r"(b[0]), "r"(b[1]));
}
#define CP_ASYNC16(dst, src) \
    asm volatile("cp.async.cg.shared.global [%0], [%1], 16;\n" :: "r"(dst), "l"(src))
#define CP_COMMIT() asm volatile("cp.async.commit_group;\n" ::: "memory")
#define CP_WAIT(n)  asm volatile("cp.async.wait_group %0;\n" :: "n"(n) : "memory")

// ---------------- init ----------------
__global__ void k_init()
{
    int i = blockIdx.x * blockDim.x + threadIdx.x;
    if (i < NN) { g_deg[i] = 0; g_cursor[i] = 0; }
    int padn = (MPAD - NN) * YW;   // 73728
    if (i < padn) {
        g_yh[(size_t)NN * YW + i] = __float2bfloat16(0.0f);
        g_yl[(size_t)NN * YW + i] = __float2bfloat16(0.0f);
    }
}

// ---------------- fp32 -> bf16 hi/lo split ----------------
__global__ void k_split(const float* __restrict__ s, __nv_bfloat16* __restrict__ h,
                        __nv_bfloat16* __restrict__ l, int nreal, int ntot)
{
    int i = blockIdx.x * blockDim.x + threadIdx.x;
    if (i >= ntot) return;
    float x = (i < nreal) ? s[i] : 0.0f;
    __nv_bfloat16 hi = __float2bfloat16(x);
    float lo = x - __bfloat162float(hi);
    h[i] = hi;
    l[i] = __float2bfloat16(lo);
}

// ---------------- fused weight preprocessing (Wsc and Wfin in one launch) ----------------
// bx in [0,6):  Wsc[rh*128+k, d2] = sum_d WK[r, h*128+d, k] * WQ[h*128+d, d2]
// bx in [6,12): Wfin[o, (r*2+h)*128+k] = sum_d WO[o, h*128+d] * WV[r, h*128+d, k]
__global__ void k_wpre(const float* __restrict__ WQ, const float* __restrict__ WK,
                       const float* __restrict__ WO, const float* __restrict__ WV)
{
    int bx = blockIdx.x;
    int row = blockIdx.y;         // 0..127
    int t = threadIdx.x;          // 0..127
    if (bx < 6) {
        int rh = bx, r = rh >> 1, h = rh & 1;
        int k = row, d2 = t;
        const float* wk = WK + (size_t)r * HD * DD + (size_t)(h * 128) * DD + k;
        const float* wq = WQ + (size_t)(h * 128) * DD + d2;
        float a0 = 0.f, a1 = 0.f, a2 = 0.f, a3 = 0.f;
        #pragma unroll
        for (int d = 0; d < 128; d += 4) {
            a0 = fmaf(wk[(size_t)(d + 0) * DD], wq[(size_t)(d + 0) * DD], a0);
            a1 = fmaf(wk[(size_t)(d + 1) * DD], wq[(size_t)(d + 1) * DD], a1);
            a2 = fmaf(wk[(size_t)(d + 2) * DD], wq[(size_t)(d + 2) * DD], a2);
            a3 = fmaf(wk[(size_t)(d + 3) * DD], wq[(size_t)(d + 3) * DD], a3);
        }
        float acc = (a0 + a1) + (a2 + a3);
        size_t idx = (size_t)(rh * 128 + k) * DD + d2;
        __nv_bfloat16 hi = __float2bfloat16(acc);
        g_wsch[idx] = hi;
        g_wscl[idx] = __float2bfloat16(acc - __bfloat162float(hi));
    } else {
        int rh = bx - 6, r = rh >> 1, h = rh & 1;
        int o = row, k = t;
        const float* wo = WO + o * HD + h * 128;
        const float* wv = WV + ((size_t)(r * HD + h * 128)) * DD + k;
        float a0 = 0.f, a1 = 0.f, a2 = 0.f, a3 = 0.f;
        #pragma unroll
        for (int d = 0; d < 128; d += 4) {
            a0 = fmaf(wo[d + 0], wv[(size_t)(d + 0) * DD], a0);
            a1 = fmaf(wo[d + 1], wv[(size_t)(d + 1) * DD], a1);
            a2 = fmaf(wo[d + 2], wv[(size_t)(d + 2) * DD], a2);
            a3 = fmaf(wo[d + 3], wv[(size_t)(d + 3) * DD], a3);
        }
        float acc = (a0 + a1) + (a2 + a3);
        size_t idx = (size_t)o * YW + rh * 128 + k;
        __nv_bfloat16 hi = __float2bfloat16(acc);
        g_wfh[idx] = hi;
        g_wfl[idx] = __float2bfloat16(acc - __bfloat162float(hi));
    }
}

// ---------------- degree histogram ----------------
__global__ void k_deg(const int* __restrict__ edst, int E)
{
    int e = blockIdx.x * blockDim.x + threadIdx.x;
    if (e < E) atomicAdd(&g_deg[edst[e]], 1);
}

// ---------------- fast scan ----------------
__global__ __launch_bounds__(1024) void k_scan(int n)
{
    const int P = 20;
    __shared__ int wsum[32];
    int tid = threadIdx.x, lane = tid & 31, wid = tid >> 5;
    int base = tid * P;
    int v[P];
    int s = 0;
    #pragma unroll
    for (int i = 0; i < P; i++) {
        int idx = base + i;
        int d = (idx < n) ? g_deg[idx] : 0;
        s += d;
        v[i] = s;
    }
    int x = s;
    #pragma unroll
    for (int off = 1; off < 32; off <<= 1) {
        int t = __shfl_up_sync(0xffffffffu, x, off);
        if (lane >= off) x += t;
    }
    if (lane == 31) wsum[wid] = x;
    __syncthreads();
    if (wid == 0) {
        int y = wsum[lane];
        #pragma unroll
        for (int off = 1; off < 32; off <<= 1) {
            int t = __shfl_up_sync(0xffffffffu, y, off);
            if (lane >= off) y += t;
        }
        wsum[lane] = y;
    }
    __syncthreads();
    int offset = (wid ? wsum[wid - 1] : 0) + x - s;
    if (tid == 0) g_rowptr[0] = 0;
    #pragma unroll
    for (int i = 0; i < P; i++) {
        int idx = base + i;
        if (idx < n) g_rowptr[idx + 1] = offset + v[i];
    }
}

// ---------------- scatter packed src|rel into CSR ----------------
__global__ void k_scatter(const int* __restrict__ esrc, const int* __restrict__ edst,
                          const int* __restrict__ erel, int E)
{
    int e = blockIdx.x * blockDim.x + threadIdx.x;
    if (e >= E) return;
    int dst = edst[e];
    int pos = atomicAdd(&g_cursor[dst], 1);
    g_pack[g_rowptr[dst] + pos] = esrc[e] | (erel[e] << 15);
}

// ---------------- mma.sync GEMM, cp.async double-buffered ----------------
#define SSTR   40
#define TILEB  10240
#define STAGEB (4 * TILEB)
#define GSMEM  (2 * STAGEB)

template <int KD>
__global__ __launch_bounds__(256)
void k_mma_gemm(const __nv_bfloat16* __restrict__ Ah, const __nv_bfloat16* __restrict__ Al,
                const __nv_bfloat16* __restrict__ Bh, const __nv_bfloat16* __restrict__ Bl,
                float* __restrict__ C, int Mreal, int ldc)
{
    extern __shared__ uint8_t dsm[];
    const uint32_t sb = smem_u32(dsm);
    const int tid  = threadIdx.x;
    const int wid  = tid >> 5;
    const int lane = tid & 31;
    const int m0 = blockIdx.y * 128;
    const int j0 = blockIdx.x * 128;
    const int warp_m = (wid & 3) * 32;
    const int warp_n = (wid >> 2) * 64;

    const int ar = lane & 15;
    const int kh = (lane >> 4) << 3;

    float acc[2][8][4];
    #pragma unroll
    for (int i = 0; i < 2; i++)
        #pragma unroll
        for (int j = 0; j < 8; j++)
            #pragma unroll
            for (int q = 0; q < 4; q++) acc[i][j][q] = 0.0f;

    int rowA[2], c8A[2];
    #pragma unroll
    for (int i = 0; i < 2; i++) {
        int v = tid + i * 256;
        rowA[i] = v >> 2;
        c8A[i] = (v & 3) << 3;
    }

    auto prefetch = [&](int kt, int stage) {
        uint32_t base = sb + (uint32_t)stage * STAGEB;
        #pragma unroll
        for (int i = 0; i < 2; i++) {
            int row = rowA[i], c8 = c8A[i];
            uint32_t so = base + (uint32_t)(row * SSTR + c8) * 2;
            size_t ga = (size_t)(m0 + row) * KD + kt + c8;
            size_t gb = (size_t)(j0 + row) * KD + kt + c8;
            CP_ASYNC16(so,             Ah + ga);
            CP_ASYNC16(so + TILEB,     Al + ga);
            CP_ASYNC16(so + 2 * TILEB, Bh + gb);
            CP_ASYNC16(so + 3 * TILEB, Bl + gb);
        }
        CP_COMMIT();
    };

    constexpr int NCH = KD / 32;
    prefetch(0, 0);

    for (int ch = 0; ch < NCH; ch++) {
        if (ch + 1 < NCH) {
            prefetch((ch + 1) * 32, (ch + 1) & 1);
            CP_WAIT(1);
        } else {
            CP_WAIT(0);
        }
        __syncthreads();

        uint32_t base = sb + (uint32_t)(ch & 1) * STAGEB;
        #pragma unroll
        for (int pass = 0; pass < 3; pass++) {
            uint32_t aBase = base + (pass == 2 ? TILEB : 0u);
            uint32_t bBase = base + 2 * TILEB + (pass == 1 ? TILEB : 0u);
            #pragma unroll
            for (int k16 = 0; k16 < 2; k16++) {
                uint32_t kb = (uint32_t)((k16 * 16 + kh) * 2);
                uint32_t a[2][4];
                #pragma unroll
                for (int mi = 0; mi < 2; mi++) {
                    uint32_t ad = aBase + (uint32_t)((warp_m + mi * 16 + ar) * SSTR * 2) + kb;
                    ldsm_x4(a[mi][0], a[mi][1], a[mi][2], a[mi][3], ad);
                }
                uint32_t b[8][2];
                #pragma unroll
                for (int ng = 0; ng < 4; ng++) {
                    uint32_t r0, r1, r2, r3;
                    uint32_t bd = bBase + (uint32_t)((warp_n + ng * 16 + ar) * SSTR * 2) + kb;
                    ldsm_x4(r0, r1, r2, r3, bd);
                    b[ng * 2][0] = r0;     b[ng * 2][1] = r2;
                    b[ng * 2 + 1][0] = r1; b[ng * 2 + 1][1] = r3;
                }
                #pragma unroll
                for (int mi = 0; mi < 2; mi++)
                    #pragma unroll
                    for (int nj = 0; nj < 8; nj++)
                        mma_bf16(acc[mi][nj], a[mi], b[nj]);
            }
        }
        __syncthreads();
    }

    const int rg = lane >> 2;
    const int tg = lane & 3;
    #pragma unroll
    for (int mi = 0; mi < 2; mi++) {
        int r0 = m0 + warp_m + mi * 16 + rg;
        int r1 = r0 + 8;
        #pragma unroll
        for (int nj = 0; nj < 8; nj++) {
            int col = j0 + warp_n + nj * 8 + tg * 2;
            if (r0 < Mreal) {
                float2 v = {acc[mi][nj][0], acc[mi][nj][1]};
                *(float2*)(C + (size_t)r0 * ldc + col) = v;
            }
            if (r1 < Mreal) {
                float2 v = {acc[mi][nj][2], acc[mi][nj][3]};
                *(float2*)(C + (size_t)r1 * ldc + col) = v;
            }
        }
    }
}

// ---------------- fused node kernel: head-split layout, 4-edge pipeline ----------------
// Lanes 0-15 own head0, lanes 16-31 own head1.
// Lane l covers dims [(l&15)*8, (l&15)*8+8) of ITS head for: qt residency,
// score partial, y accumulation, y writeout. Reduction = 4-step butterfly
// within each 16-lane half (both heads reduced by the SAME shfl instructions).
// No nu/den broadcasts needed: each lane holds its own head's values.
__global__ __launch_bounds__(256)
void k_node(const float* __restrict__ X, int N)
{
    int warp = (blockIdx.x * blockDim.x + threadIdx.x) >> 5;
    int lane = threadIdx.x & 31;
    if (warp >= N) return;

    const int start = g_rowptr[warp];
    const int end   = g_rowptr[warp + 1];

    const int h  = lane >> 4;          // my head
    const int d8 = (lane & 15) * 8;    // my 8 dims

    // qt residency: 3 rels x 8 dims of my head
    float qt[3][8];
    {
        const float* qr = g_qt + (size_t)warp * YW + h * 128 + d8;
        #pragma unroll
        for (int r = 0; r < 3; r++) {
            float4 v0 = *(const float4*)(qr + r * 256);
            float4 v1 = *(const float4*)(qr + r * 256 + 4);
            qt[r][0] = v0.x; qt[r][1] = v0.y; qt[r][2] = v0.z; qt[r][3] = v0.w;
            qt[r][4] = v1.x; qt[r][5] = v1.y; qt[r][6] = v1.z; qt[r][7] = v1.w;
        }
    }

    float y[3][8];
    #pragma unroll
    for (int r = 0; r < 3; r++)
        #pragma unroll
        for (int i = 0; i < 8; i++) y[r][i] = 0.0f;

    float den = 0.0f;

    int j = start;
    int pk[4];
    #pragma unroll
    for (int i = 0; i < 4; i++) pk[i] = (j + i < end) ? g_pack[j + i] : 0;

    while (j + 3 < end) {
        int s_[4], r_[4];
        #pragma unroll
        for (int i = 0; i < 4; i++) { s_[i] = pk[i] & 0x7FFF; r_[i] = pk[i] >> 15; }
        int nj = j + 4;
        int npk[4];
        #pragma unroll
        for (int i = 0; i < 4; i++) npk[i] = (nj + i < end) ? g_pack[nj + i] : 0;

        // issue all x gathers (8 independent LDG.128)
        float xv[4][8];
        #pragma unroll
        for (int i = 0; i < 4; i++) {
            const float* xp = X + (size_t)s_[i] * DD + d8;
            float4 a = *(const float4*)(xp);
            float4 b = *(const float4*)(xp + 4);
            xv[i][0] = a.x; xv[i][1] = a.y; xv[i][2] = a.z; xv[i][3] = a.w;
            xv[i][4] = b.x; xv[i][5] = b.y; xv[i][6] = b.z; xv[i][7] = b.w;
        }

        // score partials (my head)
        float p[4] = {0.f, 0.f, 0.f, 0.f};
        #pragma unroll
        for (int i = 0; i < 4; i++)
            #pragma unroll
            for (int q = 0; q < 8; q++)
                p[i] = fmaf(qt[r_[i]][q], xv[i][q], p[i]);

        // 4-step butterfly within 16-lane halves, 4 chains interleaved
        #pragma unroll
        for (int off = 8; off >= 1; off >>= 1) {
            p[0] += __shfl_xor_sync(0xffffffffu, p[0], off);
            p[1] += __shfl_xor_sync(0xffffffffu, p[1], off);
            p[2] += __shfl_xor_sync(0xffffffffu, p[2], off);
            p[3] += __shfl_xor_sync(0xffffffffu, p[3], off);
        }

        #pragma unroll
        for (int i = 0; i < 4; i++) {
            float nu = fmaxf(p[i] * (1.0f / SCALE), 0.0f);
            nu = nu * nu + 1e-10f;
            den += nu;
            float* yr = y[r_[i]];
            #pragma unroll
            for (int q = 0; q < 8; q++)
                yr[q] = fmaf(nu, xv[i][q], yr[q]);
        }

        j = nj;
        #pragma unroll
        for (int i = 0; i < 4; i++) pk[i] = npk[i];
    }

    // remainder (<=3 edges)
    for (int i = 0; j + i < end; i++) {
        int s0 = pk[i] & 0x7FFF, r0 = pk[i] >> 15;
        const float* xp = X + (size_t)s0 * DD + d8;
        float4 a = *(const float4*)(xp);
        float4 b = *(const float4*)(xp + 4);
        float xa[8] = {a.x, a.y, a.z, a.w, b.x, b.y, b.z, b.w};
        float p = 0.f;
        #pragma unroll
        for (int q = 0; q < 8; q++) p = fmaf(qt[r0][q], xa[q], p);
        #pragma unroll
        for (int off = 8; off >= 1; off >>= 1)
            p += __shfl_xor_sync(0xffffffffu, p, off);
        float nu = fmaxf(p * (1.0f / SCALE), 0.0f);
        nu = nu * nu + 1e-10f;
        den += nu;
        #pragma unroll
        for (int q = 0; q < 8; q++) y[r0][q] = fmaf(nu, xa[q], y[r0][q]);
    }

    float inv = (den > 0.0f) ? 1.0f / den : 0.0f;

    // writeout: lane writes 8 bf16 (16B) per rel for its head
    #pragma unroll
    for (int r = 0; r < 3; r++) {
        size_t off = (size_t)warp * YW + (r * 2 + h) * 128 + d8;
        __nv_bfloat16 hv[8], lv[8];
        #pragma unroll
        for (int i = 0; i < 8; i++) {
            float val = y[r][i] * inv;
            __nv_bfloat16 hi = __float2bfloat16(val);
            hv[i] = hi;
            lv[i] = __float2bfloat16(val - __bfloat162float(hi));
        }
        *(uint4*)(g_yh + off) = *(uint4*)hv;
        *(uint4*)(g_yl + off) = *(uint4*)lv;
    }
}

// ---------------- launch ----------------
extern "C" void kernel_launch(void* const* d_in, const int* in_sizes, int n_in,
                              void* d_out, int out_size)
{
    const float* X   = (const float*)d_in[0];
    const float* WQ  = (const float*)d_in[1];
    const float* WK  = (const float*)d_in[2];
    const float* WV  = (const float*)d_in[3];
    const float* WO  = (const float*)d_in[4];
    const int*  esrc = (const int*)d_in[5];
    const int*  edst = (const int*)d_in[6];
    const int*  erel = (const int*)d_in[7];
    float* out = (float*)d_out;

    const int N = NN, E = EE;

    float* qt;
    cudaGetSymbolAddress((void**)&qt, g_qt);
    __nv_bfloat16 *xh, *xl, *wsch, *wscl, *wfh, *wfl, *yh, *yl;
    cudaGetSymbolAddress((void**)&xh,   g_xh);
    cudaGetSymbolAddress((void**)&xl,   g_xl);
    cudaGetSymbolAddress((void**)&wsch, g_wsch);
    cudaGetSymbolAddress((void**)&wscl, g_wscl);
    cudaGetSymbolAddress((void**)&wfh,  g_wfh);
    cudaGetSymbolAddress((void**)&wfl,  g_wfl);
    cudaGetSymbolAddress((void**)&yh,   g_yh);
    cudaGetSymbolAddress((void**)&yl,   g_yl);

    cudaFuncSetAttribute(k_mma_gemm<DD>, cudaFuncAttributeMaxDynamicSharedMemorySize, GSMEM);
    cudaFuncSetAttribute(k_mma_gemm<YW>, cudaFuncAttributeMaxDynamicSharedMemorySize, GSMEM);

    // 1. init + conversions + fused weights
    k_init<<<((MPAD - NN) * YW + 255) / 256, 256>>>();
    k_split<<<(MPAD * DD + 255) / 256, 256>>>(X, xh, xl, N * DD, MPAD * DD);
    {
        dim3 grid(12, 128);
        k_wpre<<<grid, 128>>>(WQ, WK, WO, WV);
    }

    // 2. CSR build
    k_deg<<<(E + 255) / 256, 256>>>(edst, E);
    k_scan<<<1, 1024>>>(N);
    k_scatter<<<(E + 255) / 256, 256>>>(esrc, edst, erel, E);

    // 3. transformed-query GEMM: [MPAD,128] x [768,128]^T -> g_qt
    {
        dim3 grid(YW / 128, MPAD / 128);
        k_mma_gemm<DD><<<grid, 256, GSMEM>>>(xh, xl, wsch, wscl, qt, N, YW);
    }

    // 4. fused node pass: scores + denom + weighted-x aggregation -> Y hi/lo
    k_node<<<(N + 7) / 8, 256>>>(X, N);

    // 5. final GEMM: [MPAD,768] x [128,768]^T -> out
    {
        dim3 grid(1, MPAD / 128);
        k_mma_gemm<YW><<<grid, 256, GSMEM>>>(yh, yl, wfh, wfl, out, N, DD);
    }
}

// round 9
// speedup vs baseline: 1.0079x; 1.0079x over previous
#include <cuda_runtime.h>
#include <cuda_bf16.h>
#include <cstdint>

// Problem constants (fixed by the dataset)
#define NN    20000
#define MPAD  20096        // 157 * 128
#define EE    320000
#define DD    128
#define HD    256
#define YW    768          // 3 rel * 2 head * 128
#define SCALE 16.0f

// ---------------- scratch (device globals; no allocation) ----------------
__device__ float          g_qt[(size_t)NN * YW];      // fp32 transformed queries [N,768]
__device__ __nv_bfloat16  g_xh[(size_t)MPAD * DD];
__device__ __nv_bfloat16  g_xl[(size_t)MPAD * DD];
__device__ __nv_bfloat16  g_wsch[(size_t)YW * DD];    // Wsc = WK^T WQ blocks, hi/lo [768,128]
__device__ __nv_bfloat16  g_wscl[(size_t)YW * DD];
__device__ __nv_bfloat16  g_wfh[(size_t)DD * YW];     // Wfin = WO x WV blocks, hi/lo [128,768]
__device__ __nv_bfloat16  g_wfl[(size_t)DD * YW];
__device__ __nv_bfloat16  g_yh[(size_t)MPAD * YW];    // weighted-x aggregate hi/lo
__device__ __nv_bfloat16  g_yl[(size_t)MPAD * YW];
__device__ int   g_deg[NN];
__device__ int   g_rowptr[NN + 1];
__device__ int   g_cursor[NN];
__device__ int   g_pack[EE];                          // CSR-ordered src | (rel<<15)

__device__ __forceinline__ uint32_t smem_u32(const void* p) {
    uint32_t a;
    asm("{ .reg .u64 t; cvta.to.shared.u64 t, %1; cvt.u32.u64 %0, t; }" : "=r"(a) : "l"(p));
    return a;
}
__device__ __forceinline__ void ldsm_x4(uint32_t& r0, uint32_t& r1, uint32_t& r2, uint32_t& r3,
                                        uint32_t addr) {
    asm volatile("ldmatrix.sync.aligned.m8n8.x4.shared.b16 {%0,%1,%2,%3}, [%4];"
                 : "=r"(r0), "=r"(r1), "=r"(r2), "=r"(r3) : "r"(addr));
}
__device__ __forceinline__ void mma_bf16(float* d, const uint32_t* a, const uint32_t* b) {
    asm volatile(
        "mma.sync.aligned.m16n8k16.row.col.f32.bf16.bf16.f32 "
        "{%0,%1,%2,%3}, {%4,%5,%6,%7}, {%8,%9}, {%0,%1,%2,%3};"
        : "+f"(d[0]), "+f"(d[1]), "+f"(d[2]), "+f"(d[3])
        : "r"(a[0]), "r"(a[1]), "r"(a[2]), "r"(a[3]), "r"(b[0]), "r"(b[1]));
}
#define CP_ASYNC16(dst, src) \
    asm volatile("cp.async.cg.shared.global [%0], [%1], 16;\n" :: "r"(dst), "l"(src))
#define CP_COMMIT() asm volatile("cp.async.commit_group;\n" ::: "memory")
#define CP_WAIT(n)  asm volatile("cp.async.wait_group %0;\n" :: "n"(n) : "memory")

// ---------------- init ----------------
__global__ void k_init()
{
    int i = blockIdx.x * blockDim.x + threadIdx.x;
    if (i < NN) { g_deg[i] = 0; g_cursor[i] = 0; }
    int padn = (MPAD - NN) * YW;   // 73728
    if (i < padn) {
        g_yh[(size_t)NN * YW + i] = __float2bfloat16(0.0f);
        g_yl[(size_t)NN * YW + i] = __float2bfloat16(0.0f);
    }
}

// ---------------- fp32 -> bf16 hi/lo split ----------------
__global__ void k_split(const float* __restrict__ s, __nv_bfloat16* __restrict__ h,
                        __nv_bfloat16* __restrict__ l, int nreal, int ntot)
{
    int i = blockIdx.x * blockDim.x + threadIdx.x;
    if (i >= ntot) return;
    float x = (i < nreal) ? s[i] : 0.0f;
    __nv_bfloat16 hi = __float2bfloat16(x);
    float lo = x - __bfloat162float(hi);
    h[i] = hi;
    l[i] = __float2bfloat16(lo);
}

// ---------------- fused weight preprocessing (Wsc and Wfin in one launch) ----------------
__global__ void k_wpre(const float* __restrict__ WQ, const float* __restrict__ WK,
                       const float* __restrict__ WO, const float* __restrict__ WV)
{
    int bx = blockIdx.x;
    int row = blockIdx.y;         // 0..127
    int t = threadIdx.x;          // 0..127
    if (bx < 6) {
        int rh = bx, r = rh >> 1, h = rh & 1;
        int k = row, d2 = t;
        const float* wk = WK + (size_t)r * HD * DD + (size_t)(h * 128) * DD + k;
        const float* wq = WQ + (size_t)(h * 128) * DD + d2;
        float a0 = 0.f, a1 = 0.f, a2 = 0.f, a3 = 0.f;
        #pragma unroll
        for (int d = 0; d < 128; d += 4) {
            a0 = fmaf(wk[(size_t)(d + 0) * DD], wq[(size_t)(d + 0) * DD], a0);
            a1 = fmaf(wk[(size_t)(d + 1) * DD], wq[(size_t)(d + 1) * DD], a1);
            a2 = fmaf(wk[(size_t)(d + 2) * DD], wq[(size_t)(d + 2) * DD], a2);
            a3 = fmaf(wk[(size_t)(d + 3) * DD], wq[(size_t)(d + 3) * DD], a3);
        }
        float acc = (a0 + a1) + (a2 + a3);
        size_t idx = (size_t)(rh * 128 + k) * DD + d2;
        __nv_bfloat16 hi = __float2bfloat16(acc);
        g_wsch[idx] = hi;
        g_wscl[idx] = __float2bfloat16(acc - __bfloat162float(hi));
    } else {
        int rh = bx - 6, r = rh >> 1, h = rh & 1;
        int o = row, k = t;
        const float* wo = WO + o * HD + h * 128;
        const float* wv = WV + ((size_t)(r * HD + h * 128)) * DD + k;
        float a0 = 0.f, a1 = 0.f, a2 = 0.f, a3 = 0.f;
        #pragma unroll
        for (int d = 0; d < 128; d += 4) {
            a0 = fmaf(wo[d + 0], wv[(size_t)(d + 0) * DD], a0);
            a1 = fmaf(wo[d + 1], wv[(size_t)(d + 1) * DD], a1);
            a2 = fmaf(wo[d + 2], wv[(size_t)(d + 2) * DD], a2);
            a3 = fmaf(wo[d + 3], wv[(size_t)(d + 3) * DD], a3);
        }
        float acc = (a0 + a1) + (a2 + a3);
        size_t idx = (size_t)o * YW + rh * 128 + k;
        __nv_bfloat16 hi = __float2bfloat16(acc);
        g_wfh[idx] = hi;
        g_wfl[idx] = __float2bfloat16(acc - __bfloat162float(hi));
    }
}

// ---------------- degree histogram ----------------
__global__ void k_deg(const int* __restrict__ edst, int E)
{
    int e = blockIdx.x * blockDim.x + threadIdx.x;
    if (e < E) atomicAdd(&g_deg[edst[e]], 1);
}

// ---------------- fast scan ----------------
__global__ __launch_bounds__(1024) void k_scan(int n)
{
    const int P = 20;
    __shared__ int wsum[32];
    int tid = threadIdx.x, lane = tid & 31, wid = tid >> 5;
    int base = tid * P;
    int v[P];
    int s = 0;
    #pragma unroll
    for (int i = 0; i < P; i++) {
        int idx = base + i;
        int d = (idx < n) ? g_deg[idx] : 0;
        s += d;
        v[i] = s;
    }
    int x = s;
    #pragma unroll
    for (int off = 1; off < 32; off <<= 1) {
        int t = __shfl_up_sync(0xffffffffu, x, off);
        if (lane >= off) x += t;
    }
    if (lane == 31) wsum[wid] = x;
    __syncthreads();
    if (wid == 0) {
        int y = wsum[lane];
        #pragma unroll
        for (int off = 1; off < 32; off <<= 1) {
            int t = __shfl_up_sync(0xffffffffu, y, off);
            if (lane >= off) y += t;
        }
        wsum[lane] = y;
    }
    __syncthreads();
    int offset = (wid ? wsum[wid - 1] : 0) + x - s;
    if (tid == 0) g_rowptr[0] = 0;
    #pragma unroll
    for (int i = 0; i < P; i++) {
        int idx = base + i;
        if (idx < n) g_rowptr[idx + 1] = offset + v[i];
    }
}

// ---------------- scatter packed src|rel into CSR ----------------
__global__ void k_scatter(const int* __restrict__ esrc, const int* __restrict__ edst,
                          const int* __restrict__ erel, int E)
{
    int e = blockIdx.x * blockDim.x + threadIdx.x;
    if (e >= E) return;
    int dst = edst[e];
    int pos = atomicAdd(&g_cursor[dst], 1);
    g_pack[g_rowptr[dst] + pos] = esrc[e] | (erel[e] << 15);
}

// ---------------- mma.sync GEMM, cp.async double-buffered ----------------
#define SSTR   40
#define TILEB  10240
#define STAGEB (4 * TILEB)
#define GSMEM  (2 * STAGEB)

template <int KD>
__global__ __launch_bounds__(256)
void k_mma_gemm(const __nv_bfloat16* __restrict__ Ah, const __nv_bfloat16* __restrict__ Al,
                const __nv_bfloat16* __restrict__ Bh, const __nv_bfloat16* __restrict__ Bl,
                float* __restrict__ C, int Mreal, int ldc)
{
    extern __shared__ uint8_t dsm[];
    const uint32_t sb = smem_u32(dsm);
    const int tid  = threadIdx.x;
    const int wid  = tid >> 5;
    const int lane = tid & 31;
    const int m0 = blockIdx.y * 128;
    const int j0 = blockIdx.x * 128;
    const int warp_m = (wid & 3) * 32;
    const int warp_n = (wid >> 2) * 64;

    const int ar = lane & 15;
    const int kh = (lane >> 4) << 3;

    float acc[2][8][4];
    #pragma unroll
    for (int i = 0; i < 2; i++)
        #pragma unroll
        for (int j = 0; j < 8; j++)
            #pragma unroll
            for (int q = 0; q < 4; q++) acc[i][j][q] = 0.0f;

    int rowA[2], c8A[2];
    #pragma unroll
    for (int i = 0; i < 2; i++) {
        int v = tid + i * 256;
        rowA[i] = v >> 2;
        c8A[i] = (v & 3) << 3;
    }

    auto prefetch = [&](int kt, int stage) {
        uint32_t base = sb + (uint32_t)stage * STAGEB;
        #pragma unroll
        for (int i = 0; i < 2; i++) {
            int row = rowA[i], c8 = c8A[i];
            uint32_t so = base + (uint32_t)(row * SSTR + c8) * 2;
            size_t ga = (size_t)(m0 + row) * KD + kt + c8;
            size_t gb = (size_t)(j0 + row) * KD + kt + c8;
            CP_ASYNC16(so,             Ah + ga);
            CP_ASYNC16(so + TILEB,     Al + ga);
            CP_ASYNC16(so + 2 * TILEB, Bh + gb);
            CP_ASYNC16(so + 3 * TILEB, Bl + gb);
        }
        CP_COMMIT();
    };

    constexpr int NCH = KD / 32;
    prefetch(0, 0);

    for (int ch = 0; ch < NCH; ch++) {
        if (ch + 1 < NCH) {
            prefetch((ch + 1) * 32, (ch + 1) & 1);
            CP_WAIT(1);
        } else {
            CP_WAIT(0);
        }
        __syncthreads();

        uint32_t base = sb + (uint32_t)(ch & 1) * STAGEB;
        #pragma unroll
        for (int pass = 0; pass < 3; pass++) {
            uint32_t aBase = base + (pass == 2 ? TILEB : 0u);
            uint32_t bBase = base + 2 * TILEB + (pass == 1 ? TILEB : 0u);
            #pragma unroll
            for (int k16 = 0; k16 < 2; k16++) {
                uint32_t kb = (uint32_t)((k16 * 16 + kh) * 2);
                uint32_t a[2][4];
                #pragma unroll
                for (int mi = 0; mi < 2; mi++) {
                    uint32_t ad = aBase + (uint32_t)((warp_m + mi * 16 + ar) * SSTR * 2) + kb;
                    ldsm_x4(a[mi][0], a[mi][1], a[mi][2], a[mi][3], ad);
                }
                uint32_t b[8][2];
                #pragma unroll
                for (int ng = 0; ng < 4; ng++) {
                    uint32_t r0, r1, r2, r3;
                    uint32_t bd = bBase + (uint32_t)((warp_n + ng * 16 + ar) * SSTR * 2) + kb;
                    ldsm_x4(r0, r1, r2, r3, bd);
                    b[ng * 2][0] = r0;     b[ng * 2][1] = r2;
                    b[ng * 2 + 1][0] = r1; b[ng * 2 + 1][1] = r3;
                }
                #pragma unroll
                for (int mi = 0; mi < 2; mi++)
                    #pragma unroll
                    for (int nj = 0; nj < 8; nj++)
                        mma_bf16(acc[mi][nj], a[mi], b[nj]);
            }
        }
        __syncthreads();
    }

    const int rg = lane >> 2;
    const int tg = lane & 3;
    #pragma unroll
    for (int mi = 0; mi < 2; mi++) {
        int r0 = m0 + warp_m + mi * 16 + rg;
        int r1 = r0 + 8;
        #pragma unroll
        for (int nj = 0; nj < 8; nj++) {
            int col = j0 + warp_n + nj * 8 + tg * 2;
            if (r0 < Mreal) {
                float2 v = {acc[mi][nj][0], acc[mi][nj][1]};
                *(float2*)(C + (size_t)r0 * ldc + col) = v;
            }
            if (r1 < Mreal) {
                float2 v = {acc[mi][nj][2], acc[mi][nj][3]};
                *(float2*)(C + (size_t)r1 * ldc + col) = v;
            }
        }
    }
}

// ---------------- fused node kernel: head-split layout, 2-edge unroll ----------------
// Lanes 0-15 own head0, lanes 16-31 own head1. Lane covers 8 dims of its head.
// Reduction: 4-step butterfly within 16-lane halves; no broadcasts needed.
__global__ __launch_bounds__(256)
void k_node(const float* __restrict__ X, int N)
{
    int warp = (blockIdx.x * blockDim.x + threadIdx.x) >> 5;
    int lane = threadIdx.x & 31;
    if (warp >= N) return;

    const int start = g_rowptr[warp];
    const int end   = g_rowptr[warp + 1];

    const int h  = lane >> 4;          // my head
    const int d8 = (lane & 15) * 8;    // my 8 dims

    float qt[3][8];
    {
        const float* qr = g_qt + (size_t)warp * YW + h * 128 + d8;
        #pragma unroll
        for (int r = 0; r < 3; r++) {
            float4 v0 = *(const float4*)(qr + r * 256);
            float4 v1 = *(const float4*)(qr + r * 256 + 4);
            qt[r][0] = v0.x; qt[r][1] = v0.y; qt[r][2] = v0.z; qt[r][3] = v0.w;
            qt[r][4] = v1.x; qt[r][5] = v1.y; qt[r][6] = v1.z; qt[r][7] = v1.w;
        }
    }

    float y[3][8];
    #pragma unroll
    for (int r = 0; r < 3; r++)
        #pragma unroll
        for (int i = 0; i < 8; i++) y[r][i] = 0.0f;

    float den = 0.0f;

    int j = start;
    int pk0 = (j < end)     ? g_pack[j]     : 0;
    int pk1 = (j + 1 < end) ? g_pack[j + 1] : 0;

    while (j + 1 < end) {
        int s0 = pk0 & 0x7FFF, r0 = pk0 >> 15;
        int s1 = pk1 & 0x7FFF, r1 = pk1 >> 15;
        int nj = j + 2;
        int npk0 = (nj < end)     ? g_pack[nj]     : 0;
        int npk1 = (nj + 1 < end) ? g_pack[nj + 1] : 0;

        const float* xp0 = X + (size_t)s0 * DD + d8;
        const float* xp1 = X + (size_t)s1 * DD + d8;
        float4 a0 = *(const float4*)(xp0);
        float4 b0 = *(const float4*)(xp0 + 4);
        float4 a1 = *(const float4*)(xp1);
        float4 b1 = *(const float4*)(xp1 + 4);
        float x0[8] = {a0.x, a0.y, a0.z, a0.w, b0.x, b0.y, b0.z, b0.w};
        float x1[8] = {a1.x, a1.y, a1.z, a1.w, b1.x, b1.y, b1.z, b1.w};

        float p0 = 0.f, p1 = 0.f;
        #pragma unroll
        for (int q = 0; q < 8; q++) {
            p0 = fmaf(qt[r0][q], x0[q], p0);
            p1 = fmaf(qt[r1][q], x1[q], p1);
        }
        #pragma unroll
        for (int off = 8; off >= 1; off >>= 1) {
            p0 += __shfl_xor_sync(0xffffffffu, p0, off);
            p1 += __shfl_xor_sync(0xffffffffu, p1, off);
        }
        float nu0 = fmaxf(p0 * (1.0f / SCALE), 0.0f); nu0 = nu0 * nu0 + 1e-10f;
        float nu1 = fmaxf(p1 * (1.0f / SCALE), 0.0f); nu1 = nu1 * nu1 + 1e-10f;
        den += nu0 + nu1;

        float* y0 = y[r0];
        #pragma unroll
        for (int q = 0; q < 8; q++) y0[q] = fmaf(nu0, x0[q], y0[q]);
        float* y1 = y[r1];
        #pragma unroll
        for (int q = 0; q < 8; q++) y1[q] = fmaf(nu1, x1[q], y1[q]);

        j = nj; pk0 = npk0; pk1 = npk1;
    }

    if (j < end) {
        int s0 = pk0 & 0x7FFF, r0 = pk0 >> 15;
        const float* xp = X + (size_t)s0 * DD + d8;
        float4 a = *(const float4*)(xp);
        float4 b = *(const float4*)(xp + 4);
        float xa[8] = {a.x, a.y, a.z, a.w, b.x, b.y, b.z, b.w};
        float p = 0.f;
        #pragma unroll
        for (int q = 0; q < 8; q++) p = fmaf(qt[r0][q], xa[q], p);
        #pragma unroll
        for (int off = 8; off >= 1; off >>= 1)
            p += __shfl_xor_sync(0xffffffffu, p, off);
        float nu = fmaxf(p * (1.0f / SCALE), 0.0f);
        nu = nu * nu + 1e-10f;
        den += nu;
        #pragma unroll
        for (int q = 0; q < 8; q++) y[r0][q] = fmaf(nu, xa[q], y[r0][q]);
    }

    float inv = (den > 0.0f) ? 1.0f / den : 0.0f;

    #pragma unroll
    for (int r = 0; r < 3; r++) {
        size_t off = (size_t)warp * YW + (r * 2 + h) * 128 + d8;
        __nv_bfloat16 hv[8], lv[8];
        #pragma unroll
        for (int i = 0; i < 8; i++) {
            float val = y[r][i] * inv;
            __nv_bfloat16 hi = __float2bfloat16(val);
            hv[i] = hi;
            lv[i] = __float2bfloat16(val - __bfloat162float(hi));
        }
        *(uint4*)(g_yh + off) = *(uint4*)hv;
        *(uint4*)(g_yl + off) = *(uint4*)lv;
    }
}

// ---------------- launch ----------------
extern "C" void kernel_launch(void* const* d_in, const int* in_sizes, int n_in,
                              void* d_out, int out_size)
{
    const float* X   = (const float*)d_in[0];
    const float* WQ  = (const float*)d_in[1];
    const float* WK  = (const float*)d_in[2];
    const float* WV  = (const float*)d_in[3];
    const float* WO  = (const float*)d_in[4];
    const int*  esrc = (const int*)d_in[5];
    const int*  edst = (const int*)d_in[6];
    const int*  erel = (const int*)d_in[7];
    float* out = (float*)d_out;

    const int N = NN, E = EE;

    float* qt;
    cudaGetSymbolAddress((void**)&qt, g_qt);
    __nv_bfloat16 *xh, *xl, *wsch, *wscl, *wfh, *wfl, *yh, *yl;
    cudaGetSymbolAddress((void**)&xh,   g_xh);
    cudaGetSymbolAddress((void**)&xl,   g_xl);
    cudaGetSymbolAddress((void**)&wsch, g_wsch);
    cudaGetSymbolAddress((void**)&wscl, g_wscl);
    cudaGetSymbolAddress((void**)&wfh,  g_wfh);
    cudaGetSymbolAddress((void**)&wfl,  g_wfl);
    cudaGetSymbolAddress((void**)&yh,   g_yh);
    cudaGetSymbolAddress((void**)&yl,   g_yl);

    cudaFuncSetAttribute(k_mma_gemm<DD>, cudaFuncAttributeMaxDynamicSharedMemorySize, GSMEM);
    cudaFuncSetAttribute(k_mma_gemm<YW>, cudaFuncAttributeMaxDynamicSharedMemorySize, GSMEM);

    // 1. init + conversions + fused weights
    k_init<<<((MPAD - NN) * YW + 255) / 256, 256>>>();
    k_split<<<(MPAD * DD + 255) / 256, 256>>>(X, xh, xl, N * DD, MPAD * DD);
    {
        dim3 grid(12, 128);
        k_wpre<<<grid, 128>>>(WQ, WK, WO, WV);
    }

    // 2. CSR build
    k_deg<<<(E + 255) / 256, 256>>>(edst, E);
    k_scan<<<1, 1024>>>(N);
    k_scatter<<<(E + 255) / 256, 256>>>(esrc, edst, erel, E);

    // 3. transformed-query GEMM: [MPAD,128] x [768,128]^T -> g_qt
    {
        dim3 grid(YW / 128, MPAD / 128);
        k_mma_gemm<DD><<<grid, 256, GSMEM>>>(xh, xl, wsch, wscl, qt, N, YW);
    }

    // 4. fused node pass: scores + denom + weighted-x aggregation -> Y hi/lo
    k_node<<<(N + 7) / 8, 256>>>(X, N);

    // 5. final GEMM: [MPAD,768] x [128,768]^T -> out
    {
        dim3 grid(1, MPAD / 128);
        k_mma_gemm<YW><<<grid, 256, GSMEM>>>(yh, yl, wfh, wfl, out, N, DD);
    }
}

// round 10
// speedup vs baseline: 1.1907x; 1.1814x over previous
#include <cuda_runtime.h>
#include <cuda_bf16.h>
#include <cstdint>

// Problem constants (fixed by the dataset)
#define NN    20000
#define MPAD  20096        // 157 * 128
#define EE    320000
#define DD    128
#define HD    256
#define YW    768          // 3 rel * 2 head * 128
#define SCALE 16.0f

// ---------------- scratch (device globals; no allocation) ----------------
__device__ float          g_qt[(size_t)NN * YW];      // fp32 transformed queries [N,768]; reused as split-K partials
__device__ __nv_bfloat16  g_xh[(size_t)MPAD * DD];
__device__ __nv_bfloat16  g_xl[(size_t)MPAD * DD];
__device__ __nv_bfloat16  g_wsch[(size_t)YW * DD];    // Wsc = WK^T WQ blocks, hi/lo [768,128]
__device__ __nv_bfloat16  g_wscl[(size_t)YW * DD];
__device__ __nv_bfloat16  g_wfh[(size_t)DD * YW];     // Wfin = WO x WV blocks, hi/lo [128,768]
__device__ __nv_bfloat16  g_wfl[(size_t)DD * YW];
__device__ __nv_bfloat16  g_yh[(size_t)MPAD * YW];    // weighted-x aggregate hi/lo
__device__ __nv_bfloat16  g_yl[(size_t)MPAD * YW];
__device__ int   g_deg[NN];
__device__ int   g_rowptr[NN + 1];
__device__ int   g_cursor[NN];
__device__ int   g_pack[EE];                          // CSR-ordered src | (rel<<15)

__device__ __forceinline__ uint32_t smem_u32(const void* p) {
    uint32_t a;
    asm("{ .reg .u64 t; cvta.to.shared.u64 t, %1; cvt.u32.u64 %0, t; }" : "=r"(a) : "l"(p));
    return a;
}
__device__ __forceinline__ void ldsm_x4(uint32_t& r0, uint32_t& r1, uint32_t& r2, uint32_t& r3,
                                        uint32_t addr) {
    asm volatile("ldmatrix.sync.aligned.m8n8.x4.shared.b16 {%0,%1,%2,%3}, [%4];"
                 : "=r"(r0), "=r"(r1), "=r"(r2), "=r"(r3) : "r"(addr));
}
__device__ __forceinline__ void mma_bf16(float* d, const uint32_t* a, const uint32_t* b) {
    asm volatile(
        "mma.sync.aligned.m16n8k16.row.col.f32.bf16.bf16.f32 "
        "{%0,%1,%2,%3}, {%4,%5,%6,%7}, {%8,%9}, {%0,%1,%2,%3};"
        : "+f"(d[0]), "+f"(d[1]), "+f"(d[2]), "+f"(d[3])
        : "r"(a[0]), "r"(a[1]), "r"(a[2]), "r"(a[3]), "r"(b[0]), "r"(b[1]));
}
#define CP_ASYNC16(dst, src) \
    asm volatile("cp.async.cg.shared.global [%0], [%1], 16;\n" :: "r"(dst), "l"(src))
#define CP_COMMIT() asm volatile("cp.async.commit_group;\n" ::: "memory")
#define CP_WAIT(n)  asm volatile("cp.async.wait_group %0;\n" :: "n"(n) : "memory")

// ---------------- init ----------------
__global__ void k_init()
{
    int i = blockIdx.x * blockDim.x + threadIdx.x;
    if (i < NN) { g_deg[i] = 0; g_cursor[i] = 0; }
    int padn = (MPAD - NN) * YW;   // 73728
    if (i < padn) {
        g_yh[(size_t)NN * YW + i] = __float2bfloat16(0.0f);
        g_yl[(size_t)NN * YW + i] = __float2bfloat16(0.0f);
    }
}

// ---------------- fp32 -> bf16 hi/lo split ----------------
__global__ void k_split(const float* __restrict__ s, __nv_bfloat16* __restrict__ h,
                        __nv_bfloat16* __restrict__ l, int nreal, int ntot)
{
    int i = blockIdx.x * blockDim.x + threadIdx.x;
    if (i >= ntot) return;
    float x = (i < nreal) ? s[i] : 0.0f;
    __nv_bfloat16 hi = __float2bfloat16(x);
    float lo = x - __bfloat162float(hi);
    h[i] = hi;
    l[i] = __float2bfloat16(lo);
}

// ---------------- fused weight preprocessing (Wsc and Wfin in one launch) ----------------
__global__ void k_wpre(const float* __restrict__ WQ, const float* __restrict__ WK,
                       const float* __restrict__ WO, const float* __restrict__ WV)
{
    int bx = blockIdx.x;
    int row = blockIdx.y;         // 0..127
    int t = threadIdx.x;          // 0..127
    if (bx < 6) {
        int rh = bx, r = rh >> 1, h = rh & 1;
        int k = row, d2 = t;
        const float* wk = WK + (size_t)r * HD * DD + (size_t)(h * 128) * DD + k;
        const float* wq = WQ + (size_t)(h * 128) * DD + d2;
        float a0 = 0.f, a1 = 0.f, a2 = 0.f, a3 = 0.f;
        #pragma unroll
        for (int d = 0; d < 128; d += 4) {
            a0 = fmaf(wk[(size_t)(d + 0) * DD], wq[(size_t)(d + 0) * DD], a0);
            a1 = fmaf(wk[(size_t)(d + 1) * DD], wq[(size_t)(d + 1) * DD], a1);
            a2 = fmaf(wk[(size_t)(d + 2) * DD], wq[(size_t)(d + 2) * DD], a2);
            a3 = fmaf(wk[(size_t)(d + 3) * DD], wq[(size_t)(d + 3) * DD], a3);
        }
        float acc = (a0 + a1) + (a2 + a3);
        size_t idx = (size_t)(rh * 128 + k) * DD + d2;
        __nv_bfloat16 hi = __float2bfloat16(acc);
        g_wsch[idx] = hi;
        g_wscl[idx] = __float2bfloat16(acc - __bfloat162float(hi));
    } else {
        int rh = bx - 6, r = rh >> 1, h = rh & 1;
        int o = row, k = t;
        const float* wo = WO + o * HD + h * 128;
        const float* wv = WV + ((size_t)(r * HD + h * 128)) * DD + k;
        float a0 = 0.f, a1 = 0.f, a2 = 0.f, a3 = 0.f;
        #pragma unroll
        for (int d = 0; d < 128; d += 4) {
            a0 = fmaf(wo[d + 0], wv[(size_t)(d + 0) * DD], a0);
            a1 = fmaf(wo[d + 1], wv[(size_t)(d + 1) * DD], a1);
            a2 = fmaf(wo[d + 2], wv[(size_t)(d + 2) * DD], a2);
            a3 = fmaf(wo[d + 3], wv[(size_t)(d + 3) * DD], a3);
        }
        float acc = (a0 + a1) + (a2 + a3);
        size_t idx = (size_t)o * YW + rh * 128 + k;
        __nv_bfloat16 hi = __float2bfloat16(acc);
        g_wfh[idx] = hi;
        g_wfl[idx] = __float2bfloat16(acc - __bfloat162float(hi));
    }
}

// ---------------- degree histogram ----------------
__global__ void k_deg(const int* __restrict__ edst, int E)
{
    int e = blockIdx.x * blockDim.x + threadIdx.x;
    if (e < E) atomicAdd(&g_deg[edst[e]], 1);
}

// ---------------- fast scan ----------------
__global__ __launch_bounds__(1024) void k_scan(int n)
{
    const int P = 20;
    __shared__ int wsum[32];
    int tid = threadIdx.x, lane = tid & 31, wid = tid >> 5;
    int base = tid * P;
    int v[P];
    int s = 0;
    #pragma unroll
    for (int i = 0; i < P; i++) {
        int idx = base + i;
        int d = (idx < n) ? g_deg[idx] : 0;
        s += d;
        v[i] = s;
    }
    int x = s;
    #pragma unroll
    for (int off = 1; off < 32; off <<= 1) {
        int t = __shfl_up_sync(0xffffffffu, x, off);
        if (lane >= off) x += t;
    }
    if (lane == 31) wsum[wid] = x;
    __syncthreads();
    if (wid == 0) {
        int y = wsum[lane];
        #pragma unroll
        for (int off = 1; off < 32; off <<= 1) {
            int t = __shfl_up_sync(0xffffffffu, y, off);
            if (lane >= off) y += t;
        }
        wsum[lane] = y;
    }
    __syncthreads();
    int offset = (wid ? wsum[wid - 1] : 0) + x - s;
    if (tid == 0) g_rowptr[0] = 0;
    #pragma unroll
    for (int i = 0; i < P; i++) {
        int idx = base + i;
        if (idx < n) g_rowptr[idx + 1] = offset + v[i];
    }
}

// ---------------- scatter packed src|rel into CSR ----------------
__global__ void k_scatter(const int* __restrict__ esrc, const int* __restrict__ edst,
                          const int* __restrict__ erel, int E)
{
    int e = blockIdx.x * blockDim.x + threadIdx.x;
    if (e >= E) return;
    int dst = edst[e];
    int pos = atomicAdd(&g_cursor[dst], 1);
    g_pack[g_rowptr[dst] + pos] = esrc[e] | (erel[e] << 15);
}

// ---------------- mma.sync GEMM, cp.async double-buffered ----------------
// KSTR = row stride (full K), KLEN = K range this CTA covers.
#define SSTR   40
#define TILEB  10240
#define STAGEB (4 * TILEB)
#define GSMEM  (2 * STAGEB)

template <int KSTR, int KLEN, bool SPLITK>
__global__ __launch_bounds__(256)
void k_mma_gemm(const __nv_bfloat16* __restrict__ Ah, const __nv_bfloat16* __restrict__ Al,
                const __nv_bfloat16* __restrict__ Bh, const __nv_bfloat16* __restrict__ Bl,
                float* __restrict__ C0, float* __restrict__ C1, int Mreal, int ldc)
{
    extern __shared__ uint8_t dsm[];
    const uint32_t sb = smem_u32(dsm);
    const int tid  = threadIdx.x;
    const int wid  = tid >> 5;
    const int lane = tid & 31;
    const int m0 = blockIdx.y * 128;
    const int j0 = SPLITK ? 0 : blockIdx.x * 128;
    const int koff = SPLITK ? blockIdx.x * KLEN : 0;
    float* C = (SPLITK && blockIdx.x) ? C1 : C0;
    const int warp_m = (wid & 3) * 32;
    const int warp_n = (wid >> 2) * 64;

    const int ar = lane & 15;
    const int kh = (lane >> 4) << 3;

    float acc[2][8][4];
    #pragma unroll
    for (int i = 0; i < 2; i++)
        #pragma unroll
        for (int j = 0; j < 8; j++)
            #pragma unroll
            for (int q = 0; q < 4; q++) acc[i][j][q] = 0.0f;

    int rowA[2], c8A[2];
    #pragma unroll
    for (int i = 0; i < 2; i++) {
        int v = tid + i * 256;
        rowA[i] = v >> 2;
        c8A[i] = (v & 3) << 3;
    }

    auto prefetch = [&](int kt, int stage) {
        uint32_t base = sb + (uint32_t)stage * STAGEB;
        #pragma unroll
        for (int i = 0; i < 2; i++) {
            int row = rowA[i], c8 = c8A[i];
            uint32_t so = base + (uint32_t)(row * SSTR + c8) * 2;
            size_t ga = (size_t)(m0 + row) * KSTR + koff + kt + c8;
            size_t gb = (size_t)(j0 + row) * KSTR + koff + kt + c8;
            CP_ASYNC16(so,             Ah + ga);
            CP_ASYNC16(so + TILEB,     Al + ga);
            CP_ASYNC16(so + 2 * TILEB, Bh + gb);
            CP_ASYNC16(so + 3 * TILEB, Bl + gb);
        }
        CP_COMMIT();
    };

    constexpr int NCH = KLEN / 32;
    prefetch(0, 0);

    for (int ch = 0; ch < NCH; ch++) {
        if (ch + 1 < NCH) {
            prefetch((ch + 1) * 32, (ch + 1) & 1);
            CP_WAIT(1);
        } else {
            CP_WAIT(0);
        }
        __syncthreads();

        uint32_t base = sb + (uint32_t)(ch & 1) * STAGEB;
        #pragma unroll
        for (int pass = 0; pass < 3; pass++) {
            uint32_t aBase = base + (pass == 2 ? TILEB : 0u);
            uint32_t bBase = base + 2 * TILEB + (pass == 1 ? TILEB : 0u);
            #pragma unroll
            for (int k16 = 0; k16 < 2; k16++) {
                uint32_t kb = (uint32_t)((k16 * 16 + kh) * 2);
                uint32_t a[2][4];
                #pragma unroll
                for (int mi = 0; mi < 2; mi++) {
                    uint32_t ad = aBase + (uint32_t)((warp_m + mi * 16 + ar) * SSTR * 2) + kb;
                    ldsm_x4(a[mi][0], a[mi][1], a[mi][2], a[mi][3], ad);
                }
                uint32_t b[8][2];
                #pragma unroll
                for (int ng = 0; ng < 4; ng++) {
                    uint32_t r0, r1, r2, r3;
                    uint32_t bd = bBase + (uint32_t)((warp_n + ng * 16 + ar) * SSTR * 2) + kb;
                    ldsm_x4(r0, r1, r2, r3, bd);
                    b[ng * 2][0] = r0;     b[ng * 2][1] = r2;
                    b[ng * 2 + 1][0] = r1; b[ng * 2 + 1][1] = r3;
                }
                #pragma unroll
                for (int mi = 0; mi < 2; mi++)
                    #pragma unroll
                    for (int nj = 0; nj < 8; nj++)
                        mma_bf16(acc[mi][nj], a[mi], b[nj]);
            }
        }
        __syncthreads();
    }

    const int rg = lane >> 2;
    const int tg = lane & 3;
    #pragma unroll
    for (int mi = 0; mi < 2; mi++) {
        int r0 = m0 + warp_m + mi * 16 + rg;
        int r1 = r0 + 8;
        #pragma unroll
        for (int nj = 0; nj < 8; nj++) {
            int col = j0 + warp_n + nj * 8 + tg * 2;
            if (r0 < Mreal) {
                float2 v = {acc[mi][nj][0], acc[mi][nj][1]};
                *(float2*)(C + (size_t)r0 * ldc + col) = v;
            }
            if (r1 < Mreal) {
                float2 v = {acc[mi][nj][2], acc[mi][nj][3]};
                *(float2*)(C + (size_t)r1 * ldc + col) = v;
            }
        }
    }
}

// ---------------- split-K partial sum -> out ----------------
__global__ void k_addout(const float* __restrict__ p0, const float* __restrict__ p1,
                         float* __restrict__ out, int n4)
{
    int i = blockIdx.x * blockDim.x + threadIdx.x;
    if (i >= n4) return;
    float4 a = ((const float4*)p0)[i];
    float4 b = ((const float4*)p1)[i];
    float4 v = {a.x + b.x, a.y + b.y, a.z + b.z, a.w + b.w};
    ((float4*)out)[i] = v;
}

// ---------------- fused node kernel (R7-proven loop) ----------------
// qt resident in registers; per edge only the 512B x row is gathered
// (used for BOTH score and aggregation). 2-edge unroll, pack prefetch.
__global__ __launch_bounds__(256)
void k_node(const float* __restrict__ X, int N)
{
    int warp = (blockIdx.x * blockDim.x + threadIdx.x) >> 5;
    int lane = threadIdx.x & 31;
    if (warp >= N) return;

    const int start = g_rowptr[warp];
    const int end   = g_rowptr[warp + 1];

    // load qt row: 6 combos (r,h) x 4 floats per lane (lane covers dims lane*4..+3)
    float qt[6][4];
    {
        const float* qr = g_qt + (size_t)warp * YW;
        #pragma unroll
        for (int c = 0; c < 6; c++) {
            float4 v = *(const float4*)(qr + c * 128 + lane * 4);
            qt[c][0] = v.x; qt[c][1] = v.y; qt[c][2] = v.z; qt[c][3] = v.w;
        }
    }

    float y[3][2][4];
    #pragma unroll
    for (int r = 0; r < 3; r++)
        #pragma unroll
        for (int h = 0; h < 2; h++)
            #pragma unroll
            for (int i = 0; i < 4; i++) y[r][h][i] = 0.0f;

    float den0 = 0.0f, den1 = 0.0f;

    int j = start;
    int pk0 = (j < end)     ? g_pack[j]     : 0;
    int pk1 = (j + 1 < end) ? g_pack[j + 1] : 0;

    while (j + 1 < end) {
        int s0 = pk0 & 0x7FFF, r0 = pk0 >> 15;
        int s1 = pk1 & 0x7FFF, r1 = pk1 >> 15;
        int nj = j + 2;
        int npk0 = (nj < end)     ? g_pack[nj]     : 0;
        int npk1 = (nj + 1 < end) ? g_pack[nj + 1] : 0;

        float4 xv0 = *(const float4*)(X + (size_t)s0 * DD + lane * 4);
        float4 xv1 = *(const float4*)(X + (size_t)s1 * DD + lane * 4);
        float xa0[4] = {xv0.x, xv0.y, xv0.z, xv0.w};
        float xa1[4] = {xv1.x, xv1.y, xv1.z, xv1.w};

        float p00 = 0.f, p01 = 0.f, p10 = 0.f, p11 = 0.f;
        #pragma unroll
        for (int i = 0; i < 4; i++) {
            p00 = fmaf(qt[r0 * 2][i],     xa0[i], p00);
            p01 = fmaf(qt[r0 * 2 + 1][i], xa0[i], p01);
            p10 = fmaf(qt[r1 * 2][i],     xa1[i], p10);
            p11 = fmaf(qt[r1 * 2 + 1][i], xa1[i], p11);
        }
        #pragma unroll
        for (int off = 16; off >= 1; off >>= 1) {
            p00 += __shfl_xor_sync(0xffffffffu, p00, off);
            p01 += __shfl_xor_sync(0xffffffffu, p01, off);
            p10 += __shfl_xor_sync(0xffffffffu, p10, off);
            p11 += __shfl_xor_sync(0xffffffffu, p11, off);
        }
        float nuA0 = fmaxf(p00 / SCALE, 0.0f); nuA0 = nuA0 * nuA0 + 1e-10f;
        float nuA1 = fmaxf(p01 / SCALE, 0.0f); nuA1 = nuA1 * nuA1 + 1e-10f;
        float nuB0 = fmaxf(p10 / SCALE, 0.0f); nuB0 = nuB0 * nuB0 + 1e-10f;
        float nuB1 = fmaxf(p11 / SCALE, 0.0f); nuB1 = nuB1 * nuB1 + 1e-10f;
        den0 += nuA0 + nuB0;
        den1 += nuA1 + nuB1;

        if (r0 == 0) {
            #pragma unroll
            for (int i = 0; i < 4; i++) { y[0][0][i] += nuA0 * xa0[i]; y[0][1][i] += nuA1 * xa0[i]; }
        } else if (r0 == 1) {
            #pragma unroll
            for (int i = 0; i < 4; i++) { y[1][0][i] += nuA0 * xa0[i]; y[1][1][i] += nuA1 * xa0[i]; }
        } else {
            #pragma unroll
            for (int i = 0; i < 4; i++) { y[2][0][i] += nuA0 * xa0[i]; y[2][1][i] += nuA1 * xa0[i]; }
        }
        if (r1 == 0) {
            #pragma unroll
            for (int i = 0; i < 4; i++) { y[0][0][i] += nuB0 * xa1[i]; y[0][1][i] += nuB1 * xa1[i]; }
        } else if (r1 == 1) {
            #pragma unroll
            for (int i = 0; i < 4; i++) { y[1][0][i] += nuB0 * xa1[i]; y[1][1][i] += nuB1 * xa1[i]; }
        } else {
            #pragma unroll
            for (int i = 0; i < 4; i++) { y[2][0][i] += nuB0 * xa1[i]; y[2][1][i] += nuB1 * xa1[i]; }
        }

        j = nj; pk0 = npk0; pk1 = npk1;
    }

    if (j < end) {
        int s0 = pk0 & 0x7FFF, r0 = pk0 >> 15;
        float4 xv = *(const float4*)(X + (size_t)s0 * DD + lane * 4);
        float xa[4] = {xv.x, xv.y, xv.z, xv.w};
        float p0 = 0.f, p1 = 0.f;
        #pragma unroll
        for (int i = 0; i < 4; i++) {
            p0 = fmaf(qt[r0 * 2][i],     xa[i], p0);
            p1 = fmaf(qt[r0 * 2 + 1][i], xa[i], p1);
        }
        #pragma unroll
        for (int off = 16; off >= 1; off >>= 1) {
            p0 += __shfl_xor_sync(0xffffffffu, p0, off);
            p1 += __shfl_xor_sync(0xffffffffu, p1, off);
        }
        float nu0 = fmaxf(p0 / SCALE, 0.0f); nu0 = nu0 * nu0 + 1e-10f;
        float nu1 = fmaxf(p1 / SCALE, 0.0f); nu1 = nu1 * nu1 + 1e-10f;
        den0 += nu0;
        den1 += nu1;
        if (r0 == 0) {
            #pragma unroll
            for (int i = 0; i < 4; i++) { y[0][0][i] += nu0 * xa[i]; y[0][1][i] += nu1 * xa[i]; }
        } else if (r0 == 1) {
            #pragma unroll
            for (int i = 0; i < 4; i++) { y[1][0][i] += nu0 * xa[i]; y[1][1][i] += nu1 * xa[i]; }
        } else {
            #pragma unroll
            for (int i = 0; i < 4; i++) { y[2][0][i] += nu0 * xa[i]; y[2][1][i] += nu1 * xa[i]; }
        }
    }

    float inv0 = (den0 > 0.0f) ? 1.0f / den0 : 0.0f;
    float inv1 = (den1 > 0.0f) ? 1.0f / den1 : 0.0f;

    #pragma unroll
    for (int r = 0; r < 3; r++)
        #pragma unroll
        for (int h = 0; h < 2; h++) {
            float sc = h ? inv1 : inv0;
            size_t off = (size_t)warp * YW + (r * 2 + h) * 128 + lane * 4;
            #pragma unroll
            for (int i = 0; i < 4; i++) {
                float val = y[r][h][i] * sc;
                __nv_bfloat16 hi = __float2bfloat16(val);
                g_yh[off + i] = hi;
                g_yl[off + i] = __float2bfloat16(val - __bfloat162float(hi));
            }
        }
}

// ---------------- launch ----------------
extern "C" void kernel_launch(void* const* d_in, const int* in_sizes, int n_in,
                              void* d_out, int out_size)
{
    const float* X   = (const float*)d_in[0];
    const float* WQ  = (const float*)d_in[1];
    const float* WK  = (const float*)d_in[2];
    const float* WV  = (const float*)d_in[3];
    const float* WO  = (const float*)d_in[4];
    const int*  esrc = (const int*)d_in[5];
    const int*  edst = (const int*)d_in[6];
    const int*  erel = (const int*)d_in[7];
    float* out = (float*)d_out;

    const int N = NN, E = EE;

    float* qt;
    cudaGetSymbolAddress((void**)&qt, g_qt);
    __nv_bfloat16 *xh, *xl, *wsch, *wscl, *wfh, *wfl, *yh, *yl;
    cudaGetSymbolAddress((void**)&xh,   g_xh);
    cudaGetSymbolAddress((void**)&xl,   g_xl);
    cudaGetSymbolAddress((void**)&wsch, g_wsch);
    cudaGetSymbolAddress((void**)&wscl, g_wscl);
    cudaGetSymbolAddress((void**)&wfh,  g_wfh);
    cudaGetSymbolAddress((void**)&wfl,  g_wfl);
    cudaGetSymbolAddress((void**)&yh,   g_yh);
    cudaGetSymbolAddress((void**)&yl,   g_yl);

    // split-K partial buffers carved out of g_qt (dead after k_node)
    float* part0 = qt;
    float* part1 = qt + (size_t)MPAD * DD;

    cudaFuncSetAttribute(k_mma_gemm<DD, DD, false>, cudaFuncAttributeMaxDynamicSharedMemorySize, GSMEM);
    cudaFuncSetAttribute(k_mma_gemm<YW, YW / 2, true>, cudaFuncAttributeMaxDynamicSharedMemorySize, GSMEM);

    // 1. init + conversions + fused weights
    k_init<<<((MPAD - NN) * YW + 255) / 256, 256>>>();
    k_split<<<(MPAD * DD + 255) / 256, 256>>>(X, xh, xl, N * DD, MPAD * DD);
    {
        dim3 grid(12, 128);
        k_wpre<<<grid, 128>>>(WQ, WK, WO, WV);
    }

    // 2. CSR build
    k_deg<<<(E + 255) / 256, 256>>>(edst, E);
    k_scan<<<1, 1024>>>(N);
    k_scatter<<<(E + 255) / 256, 256>>>(esrc, edst, erel, E);

    // 3. transformed-query GEMM: [MPAD,128] x [768,128]^T -> g_qt
    {
        dim3 grid(YW / 128, MPAD / 128);
        k_mma_gemm<DD, DD, false><<<grid, 256, GSMEM>>>(xh, xl, wsch, wscl, qt, nullptr, N, YW);
    }

    // 4. fused node pass: scores + denom + weighted-x aggregation -> Y hi/lo
    k_node<<<(N + 7) / 8, 256>>>(X, N);

    // 5. final GEMM, split-K 2-way: [MPAD,768] x [128,768]^T -> partials
    {
        dim3 grid(2, MPAD / 128);
        k_mma_gemm<YW, YW / 2, true><<<grid, 256, GSMEM>>>(yh, yl, wfh, wfl, part0, part1, N, DD);
    }

    // 6. sum partials -> out
    k_addout<<<(N * DD / 4 + 255) / 256, 256>>>(part0, part1, out, N * DD / 4);
}

// round 12
// speedup vs baseline: 1.2562x; 1.0550x over previous
#include <cuda_runtime.h>
#include <cuda_bf16.h>
#include <cstdint>

// Problem constants (fixed by the dataset)
#define NN    20000
#define MPAD  20096        // 157 * 128
#define EE    320000
#define DD    128
#define HD    256
#define YW    768          // 3 rel * 2 head * 128
#define SCALE 16.0f

// ---------------- scratch (device globals; no allocation) ----------------
__device__ float          g_qt[(size_t)NN * YW];      // fp32 transformed queries; reused as split-K partials
__device__ __nv_bfloat16  g_xh[(size_t)MPAD * DD];
__device__ __nv_bfloat16  g_xl[(size_t)MPAD * DD];
__device__ __nv_bfloat16  g_wsch[(size_t)YW * DD];    // Wsc = WK^T WQ blocks, hi/lo [768,128]
__device__ __nv_bfloat16  g_wscl[(size_t)YW * DD];
__device__ __nv_bfloat16  g_wfh[(size_t)DD * YW];     // Wfin = WO x WV blocks, hi/lo [128,768]
__device__ __nv_bfloat16  g_wfl[(size_t)DD * YW];
__device__ __nv_bfloat16  g_yh[(size_t)MPAD * YW];    // weighted-x aggregate hi/lo
__device__ __nv_bfloat16  g_yl[(size_t)MPAD * YW];
__device__ int   g_deg[NN];        // zero at load; re-zeroed by k_scan each call
__device__ int   g_rowptr[NN + 1];
__device__ int   g_cursor[NN];     // zero at load; re-zeroed by k_node each call
__device__ int   g_pack[EE];       // CSR-ordered src | (rel<<15)

__device__ __forceinline__ uint32_t smem_u32(const void* p) {
    uint32_t a;
    asm("{ .reg .u64 t; cvta.to.shared.u64 t, %1; cvt.u32.u64 %0, t; }" : "=r"(a) : "l"(p));
    return a;
}
__device__ __forceinline__ void ldsm_x4(uint32_t& r0, uint32_t& r1, uint32_t& r2, uint32_t& r3,
                                        uint32_t addr) {
    asm volatile("ldmatrix.sync.aligned.m8n8.x4.shared.b16 {%0,%1,%2,%3}, [%4];"
                 : "=r"(r0), "=r"(r1), "=r"(r2), "=r"(r3) : "r"(addr));
}
__device__ __forceinline__ void mma_bf16(float* d, const uint32_t* a, const uint32_t* b) {
    asm volatile(
        "mma.sync.aligned.m16n8k16.row.col.f32.bf16.bf16.f32 "
        "{%0,%1,%2,%3}, {%4,%5,%6,%7}, {%8,%9}, {%0,%1,%2,%3};"
        : "+f"(d[0]), "+f"(d[1]), "+f"(d[2]), "+f"(d[3])
        : "r"(a[0]), "r"(a[1]), "r"(a[2]), "r"(a[3]), "r"(b[0]), "r"(b[1]));
}
#define CP_ASYNC16(dst, src) \
    asm volatile("cp.async.cg.shared.global [%0], [%1], 16;\n" :: "r"(dst), "l"(src))
#define CP_COMMIT() asm volatile("cp.async.commit_group;\n" ::: "memory")
#define CP_WAIT(n)  asm volatile("cp.async.wait_group %0;\n" :: "n"(n) : "memory")

// ---------------- merged prologue: x split | y-pad zero | weight pre | deg histogram ----------------
// block ranges (256 threads each):
//   [0, 10048)            x hi/lo split (MPAD*DD elems)
//   [10048, 10336)        y pad-row zeroing (73728 elems)
//   [10336, 11104)        wpre: 196608 dot-products (12 sections x 128 x 128)
//   [11104, 12354)        deg histogram (E edges)
#define SPLIT_BLKS 10048
#define PAD_BLKS   288
#define WPRE_BLKS  768
#define DEG_BLKS   1250
#define PRO_BLKS   (SPLIT_BLKS + PAD_BLKS + WPRE_BLKS + DEG_BLKS)

__global__ __launch_bounds__(256)
void k_prologue(const float* __restrict__ X,
                const float* __restrict__ WQ, const float* __restrict__ WK,
                const float* __restrict__ WO, const float* __restrict__ WV,
                const int* __restrict__ edst)
{
    int blk = blockIdx.x;
    int t = threadIdx.x;

    if (blk < SPLIT_BLKS) {
        int i = blk * 256 + t;
        float x = (i < NN * DD) ? X[i] : 0.0f;
        __nv_bfloat16 hi = __float2bfloat16(x);
        g_xh[i] = hi;
        g_xl[i] = __float2bfloat16(x - __bfloat162float(hi));
        return;
    }
    blk -= SPLIT_BLKS;
    if (blk < PAD_BLKS) {
        int i = blk * 256 + t;     // < 73728
        g_yh[(size_t)NN * YW + i] = __float2bfloat16(0.0f);
        g_yl[(size_t)NN * YW + i] = __float2bfloat16(0.0f);
        return;
    }
    blk -= PAD_BLKS;
    if (blk < WPRE_BLKS) {
        int idx = blk * 256 + t;          // < 196608
        int sec = idx >> 14;              // 0..11
        int row = (idx >> 7) & 127;
        int col = idx & 127;
        if (sec < 6) {
            int rh = sec, r = rh >> 1, h = rh & 1;
            int k = row, d2 = col;
            const float* wk = WK + (size_t)r * HD * DD + (size_t)(h * 128) * DD + k;
            const float* wq = WQ + (size_t)(h * 128) * DD + d2;
            float a0 = 0.f, a1 = 0.f, a2 = 0.f, a3 = 0.f;
            #pragma unroll
            for (int d = 0; d < 128; d += 4) {
                a0 = fmaf(wk[(size_t)(d + 0) * DD], wq[(size_t)(d + 0) * DD], a0);
                a1 = fmaf(wk[(size_t)(d + 1) * DD], wq[(size_t)(d + 1) * DD], a1);
                a2 = fmaf(wk[(size_t)(d + 2) * DD], wq[(size_t)(d + 2) * DD], a2);
                a3 = fmaf(wk[(size_t)(d + 3) * DD], wq[(size_t)(d + 3) * DD], a3);
            }
            float acc = (a0 + a1) + (a2 + a3);
            size_t o = (size_t)(rh * 128 + k) * DD + d2;
            __nv_bfloat16 hi = __float2bfloat16(acc);
            g_wsch[o] = hi;
            g_wscl[o] = __float2bfloat16(acc - __bfloat162float(hi));
        } else {
            int rh = sec - 6, r = rh >> 1, h = rh & 1;
            int o = row, k = col;
            const float* wo = WO + o * HD + h * 128;
            const float* wv = WV + ((size_t)(r * HD + h * 128)) * DD + k;
            float a0 = 0.f, a1 = 0.f, a2 = 0.f, a3 = 0.f;
            #pragma unroll
            for (int d = 0; d < 128; d += 4) {
                a0 = fmaf(wo[d + 0], wv[(size_t)(d + 0) * DD], a0);
                a1 = fmaf(wo[d + 1], wv[(size_t)(d + 1) * DD], a1);
                a2 = fmaf(wo[d + 2], wv[(size_t)(d + 2) * DD], a2);
                a3 = fmaf(wo[d + 3], wv[(size_t)(d + 3) * DD], a3);
            }
            float acc = (a0 + a1) + (a2 + a3);
            size_t oidx = (size_t)o * YW + rh * 128 + k;
            __nv_bfloat16 hi = __float2bfloat16(acc);
            g_wfh[oidx] = hi;
            g_wfl[oidx] = __float2bfloat16(acc - __bfloat162float(hi));
        }
        return;
    }
    blk -= WPRE_BLKS;
    {
        int e = blk * 256 + t;
        if (e < EE) atomicAdd(&g_deg[edst[e]], 1);
    }
}

// ---------------- fast scan (also re-zeroes deg for the next replay) ----------------
__global__ __launch_bounds__(1024) void k_scan(int n)
{
    const int P = 20;
    __shared__ int wsum[32];
    int tid = threadIdx.x, lane = tid & 31, wid = tid >> 5;
    int base = tid * P;
    int v[P];
    int s = 0;
    #pragma unroll
    for (int i = 0; i < P; i++) {
        int idx = base + i;
        int d = (idx < n) ? g_deg[idx] : 0;
        if (idx < n) g_deg[idx] = 0;   // self-clean for next graph replay
        s += d;
        v[i] = s;
    }
    int x = s;
    #pragma unroll
    for (int off = 1; off < 32; off <<= 1) {
        int t = __shfl_up_sync(0xffffffffu, x, off);
        if (lane >= off) x += t;
    }
    if (lane == 31) wsum[wid] = x;
    __syncthreads();
    if (wid == 0) {
        int y = wsum[lane];
        #pragma unroll
        for (int off = 1; off < 32; off <<= 1) {
            int t = __shfl_up_sync(0xffffffffu, y, off);
            if (lane >= off) y += t;
        }
        wsum[lane] = y;
    }
    __syncthreads();
    int offset = (wid ? wsum[wid - 1] : 0) + x - s;
    if (tid == 0) g_rowptr[0] = 0;
    #pragma unroll
    for (int i = 0; i < P; i++) {
        int idx = base + i;
        if (idx < n) g_rowptr[idx + 1] = offset + v[i];
    }
}

// ---------------- scatter packed src|rel into CSR ----------------
__global__ void k_scatter(const int* __restrict__ esrc, const int* __restrict__ edst,
                          const int* __restrict__ erel, int E)
{
    int e = blockIdx.x * blockDim.x + threadIdx.x;
    if (e >= E) return;
    int dst = edst[e];
    int pos = atomicAdd(&g_cursor[dst], 1);
    g_pack[g_rowptr[dst] + pos] = esrc[e] | (erel[e] << 15);
}

// ---------------- mma.sync GEMM, cp.async double-buffered, fragment-reuse 3-pass ----------------
#define SSTR   40
#define TILEB  10240
#define STAGEB (4 * TILEB)
#define GSMEM  (2 * STAGEB)

template <int KSTR, int KLEN, bool SPLITK>
__global__ __launch_bounds__(256)
void k_mma_gemm(const __nv_bfloat16* __restrict__ Ah, const __nv_bfloat16* __restrict__ Al,
                const __nv_bfloat16* __restrict__ Bh, const __nv_bfloat16* __restrict__ Bl,
                float* __restrict__ C0, float* __restrict__ C1, int Mreal, int ldc)
{
    extern __shared__ uint8_t dsm[];
    const uint32_t sb = smem_u32(dsm);
    const int tid  = threadIdx.x;
    const int wid  = tid >> 5;
    const int lane = tid & 31;
    const int m0 = blockIdx.y * 128;
    const int j0 = SPLITK ? 0 : blockIdx.x * 128;
    const int koff = SPLITK ? blockIdx.x * KLEN : 0;
    float* C = (SPLITK && blockIdx.x) ? C1 : C0;
    const int warp_m = (wid & 3) * 32;
    const int warp_n = (wid >> 2) * 64;

    const int ar = lane & 15;
    const int kh = (lane >> 4) << 3;

    float acc[2][8][4];
    #pragma unroll
    for (int i = 0; i < 2; i++)
        #pragma unroll
        for (int j = 0; j < 8; j++)
            #pragma unroll
            for (int q = 0; q < 4; q++) acc[i][j][q] = 0.0f;

    int rowA[2], c8A[2];
    #pragma unroll
    for (int i = 0; i < 2; i++) {
        int v = tid + i * 256;
        rowA[i] = v >> 2;
        c8A[i] = (v & 3) << 3;
    }

    auto prefetch = [&](int kt, int stage) {
        uint32_t base = sb + (uint32_t)stage * STAGEB;
        #pragma unroll
        for (int i = 0; i < 2; i++) {
            int row = rowA[i], c8 = c8A[i];
            uint32_t so = base + (uint32_t)(row * SSTR + c8) * 2;
            size_t ga = (size_t)(m0 + row) * KSTR + koff + kt + c8;
            size_t gb = (size_t)(j0 + row) * KSTR + koff + kt + c8;
            CP_ASYNC16(so,             Ah + ga);
            CP_ASYNC16(so + TILEB,     Al + ga);
            CP_ASYNC16(so + 2 * TILEB, Bh + gb);
            CP_ASYNC16(so + 3 * TILEB, Bl + gb);
        }
        CP_COMMIT();
    };

    constexpr int NCH = KLEN / 32;
    prefetch(0, 0);

    for (int ch = 0; ch < NCH; ch++) {
        if (ch + 1 < NCH) {
            prefetch((ch + 1) * 32, (ch + 1) & 1);
            CP_WAIT(1);
        } else {
            CP_WAIT(0);
        }
        __syncthreads();

        uint32_t base = sb + (uint32_t)(ch & 1) * STAGEB;
        #pragma unroll
        for (int k16 = 0; k16 < 2; k16++) {
            uint32_t kb = (uint32_t)((k16 * 16 + kh) * 2);

            // load all fragments ONCE (12 ldsm instead of 18 across 3 passes)
            uint32_t ah[2][4], al[2][4];
            #pragma unroll
            for (int mi = 0; mi < 2; mi++) {
                uint32_t off = (uint32_t)((warp_m + mi * 16 + ar) * SSTR * 2) + kb;
                ldsm_x4(ah[mi][0], ah[mi][1], ah[mi][2], ah[mi][3], base + off);
                ldsm_x4(al[mi][0], al[mi][1], al[mi][2], al[mi][3], base + TILEB + off);
            }
            uint32_t bh[8][2], bl[8][2];
            #pragma unroll
            for (int ng = 0; ng < 4; ng++) {
                uint32_t off = (uint32_t)((warp_n + ng * 16 + ar) * SSTR * 2) + kb;
                uint32_t r0, r1, r2, r3;
                ldsm_x4(r0, r1, r2, r3, base + 2 * TILEB + off);
                bh[ng * 2][0] = r0;     bh[ng * 2][1] = r2;
                bh[ng * 2 + 1][0] = r1; bh[ng * 2 + 1][1] = r3;
                ldsm_x4(r0, r1, r2, r3, base + 3 * TILEB + off);
                bl[ng * 2][0] = r0;     bl[ng * 2][1] = r2;
                bl[ng * 2 + 1][0] = r1; bl[ng * 2 + 1][1] = r3;
            }

            // 3 precision passes from registers
            #pragma unroll
            for (int mi = 0; mi < 2; mi++)
                #pragma unroll
                for (int nj = 0; nj < 8; nj++)
                    mma_bf16(acc[mi][nj], ah[mi], bh[nj]);
            #pragma unroll
            for (int mi = 0; mi < 2; mi++)
                #pragma unroll
                for (int nj = 0; nj < 8; nj++)
                    mma_bf16(acc[mi][nj], ah[mi], bl[nj]);
            #pragma unroll
            for (int mi = 0; mi < 2; mi++)
                #pragma unroll
                for (int nj = 0; nj < 8; nj++)
                    mma_bf16(acc[mi][nj], al[mi], bh[nj]);
        }
        __syncthreads();
    }

    const int rg = lane >> 2;
    const int tg = lane & 3;
    #pragma unroll
    for (int mi = 0; mi < 2; mi++) {
        int r0 = m0 + warp_m + mi * 16 + rg;
        int r1 = r0 + 8;
        #pragma unroll
        for (int nj = 0; nj < 8; nj++) {
            int col = j0 + warp_n + nj * 8 + tg * 2;
            if (r0 < Mreal) {
                float2 v = {acc[mi][nj][0], acc[mi][nj][1]};
                *(float2*)(C + (size_t)r0 * ldc + col) = v;
            }
            if (r1 < Mreal) {
                float2 v = {acc[mi][nj][2], acc[mi][nj][3]};
                *(float2*)(C + (size_t)r1 * ldc + col) = v;
            }
        }
    }
}

// ---------------- split-K partial sum -> out ----------------
__global__ void k_addout(const float* __restrict__ p0, const float* __restrict__ p1,
                         float* __restrict__ out, int n4)
{
    int i = blockIdx.x * blockDim.x + threadIdx.x;
    if (i >= n4) return;
    float4 a = ((const float4*)p0)[i];
    float4 b = ((const float4*)p1)[i];
    float4 v = {a.x + b.x, a.y + b.y, a.z + b.z, a.w + b.w};
    ((float4*)out)[i] = v;
}

// ---------------- fused node kernel (R7-proven loop; also re-zeroes cursor) ----------------
__global__ __launch_bounds__(256)
void k_node(const float* __restrict__ X, int N)
{
    int warp = (blockIdx.x * blockDim.x + threadIdx.x) >> 5;
    int lane = threadIdx.x & 31;
    if (warp >= N) return;

    if (lane == 0) g_cursor[warp] = 0;   // self-clean for next graph replay

    const int start = g_rowptr[warp];
    const int end   = g_rowptr[warp + 1];

    float qt[6][4];
    {
        const float* qr = g_qt + (size_t)warp * YW;
        #pragma unroll
        for (int c = 0; c < 6; c++) {
            float4 v = *(const float4*)(qr + c * 128 + lane * 4);
            qt[c][0] = v.x; qt[c][1] = v.y; qt[c][2] = v.z; qt[c][3] = v.w;
        }
    }

    float y[3][2][4];
    #pragma unroll
    for (int r = 0; r < 3; r++)
        #pragma unroll
        for (int h = 0; h < 2; h++)
            #pragma unroll
            for (int i = 0; i < 4; i++) y[r][h][i] = 0.0f;

    float den0 = 0.0f, den1 = 0.0f;

    int j = start;
    int pk0 = (j < end)     ? g_pack[j]     : 0;
    int pk1 = (j + 1 < end) ? g_pack[j + 1] : 0;

    while (j + 1 < end) {
        int s0 = pk0 & 0x7FFF, r0 = pk0 >> 15;
        int s1 = pk1 & 0x7FFF, r1 = pk1 >> 15;
        int nj = j + 2;
        int npk0 = (nj < end)     ? g_pack[nj]     : 0;
        int npk1 = (nj + 1 < end) ? g_pack[nj + 1] : 0;

        float4 xv0 = *(const float4*)(X + (size_t)s0 * DD + lane * 4);
        float4 xv1 = *(const float4*)(X + (size_t)s1 * DD + lane * 4);
        float xa0[4] = {xv0.x, xv0.y, xv0.z, xv0.w};
        float xa1[4] = {xv1.x, xv1.y, xv1.z, xv1.w};

        float p00 = 0.f, p01 = 0.f, p10 = 0.f, p11 = 0.f;
        #pragma unroll
        for (int i = 0; i < 4; i++) {
            p00 = fmaf(qt[r0 * 2][i],     xa0[i], p00);
            p01 = fmaf(qt[r0 * 2 + 1][i], xa0[i], p01);
            p10 = fmaf(qt[r1 * 2][i],     xa1[i], p10);
            p11 = fmaf(qt[r1 * 2 + 1][i], xa1[i], p11);
        }
        #pragma unroll
        for (int off = 16; off >= 1; off >>= 1) {
            p00 += __shfl_xor_sync(0xffffffffu, p00, off);
            p01 += __shfl_xor_sync(0xffffffffu, p01, off);
            p10 += __shfl_xor_sync(0xffffffffu, p10, off);
            p11 += __shfl_xor_sync(0xffffffffu, p11, off);
        }
        float nuA0 = fmaxf(p00 / SCALE, 0.0f); nuA0 = nuA0 * nuA0 + 1e-10f;
        float nuA1 = fmaxf(p01 / SCALE, 0.0f); nuA1 = nuA1 * nuA1 + 1e-10f;
        float nuB0 = fmaxf(p10 / SCALE, 0.0f); nuB0 = nuB0 * nuB0 + 1e-10f;
        float nuB1 = fmaxf(p11 / SCALE, 0.0f); nuB1 = nuB1 * nuB1 + 1e-10f;
        den0 += nuA0 + nuB0;
        den1 += nuA1 + nuB1;

        if (r0 == 0) {
            #pragma unroll
            for (int i = 0; i < 4; i++) { y[0][0][i] += nuA0 * xa0[i]; y[0][1][i] += nuA1 * xa0[i]; }
        } else if (r0 == 1) {
            #pragma unroll
            for (int i = 0; i < 4; i++) { y[1][0][i] += nuA0 * xa0[i]; y[1][1][i] += nuA1 * xa0[i]; }
        } else {
            #pragma unroll
            for (int i = 0; i < 4; i++) { y[2][0][i] += nuA0 * xa0[i]; y[2][1][i] += nuA1 * xa0[i]; }
        }
        if (r1 == 0) {
            #pragma unroll
            for (int i = 0; i < 4; i++) { y[0][0][i] += nuB0 * xa1[i]; y[0][1][i] += nuB1 * xa1[i]; }
        } else if (r1 == 1) {
            #pragma unroll
            for (int i = 0; i < 4; i++) { y[1][0][i] += nuB0 * xa1[i]; y[1][1][i] += nuB1 * xa1[i]; }
        } else {
            #pragma unroll
            for (int i = 0; i < 4; i++) { y[2][0][i] += nuB0 * xa1[i]; y[2][1][i] += nuB1 * xa1[i]; }
        }

        j = nj; pk0 = npk0; pk1 = npk1;
    }

    if (j < end) {
        int s0 = pk0 & 0x7FFF, r0 = pk0 >> 15;
        float4 xv = *(const float4*)(X + (size_t)s0 * DD + lane * 4);
        float xa[4] = {xv.x, xv.y, xv.z, xv.w};
        float p0 = 0.f, p1 = 0.f;
        #pragma unroll
        for (int i = 0; i < 4; i++) {
            p0 = fmaf(qt[r0 * 2][i],     xa[i], p0);
            p1 = fmaf(qt[r0 * 2 + 1][i], xa[i], p1);
        }
        #pragma unroll
        for (int off = 16; off >= 1; off >>= 1) {
            p0 += __shfl_xor_sync(0xffffffffu, p0, off);
            p1 += __shfl_xor_sync(0xffffffffu, p1, off);
        }
        float nu0 = fmaxf(p0 / SCALE, 0.0f); nu0 = nu0 * nu0 + 1e-10f;
        float nu1 = fmaxf(p1 / SCALE, 0.0f); nu1 = nu1 * nu1 + 1e-10f;
        den0 += nu0;
        den1 += nu1;
        if (r0 == 0) {
            #pragma unroll
            for (int i = 0; i < 4; i++) { y[0][0][i] += nu0 * xa[i]; y[0][1][i] += nu1 * xa[i]; }
        } else if (r0 == 1) {
            #pragma unroll
            for (int i = 0; i < 4; i++) { y[1][0][i] += nu0 * xa[i]; y[1][1][i] += nu1 * xa[i]; }
        } else {
            #pragma unroll
            for (int i = 0; i < 4; i++) { y[2][0][i] += nu0 * xa[i]; y[2][1][i] += nu1 * xa[i]; }
        }
    }

    float inv0 = (den0 > 0.0f) ? 1.0f / den0 : 0.0f;
    float inv1 = (den1 > 0.0f) ? 1.0f / den1 : 0.0f;

    #pragma unroll
    for (int r = 0; r < 3; r++)
        #pragma unroll
        for (int h = 0; h < 2; h++) {
            float sc = h ? inv1 : inv0;
            size_t off = (size_t)warp * YW + (r * 2 + h) * 128 + lane * 4;
            #pragma unroll
            for (int i = 0; i < 4; i++) {
                float val = y[r][h][i] * sc;
                __nv_bfloat16 hi = __float2bfloat16(val);
                g_yh[off + i] = hi;
                g_yl[off + i] = __float2bfloat16(val - __bfloat162float(hi));
            }
        }
}

// ---------------- launch ----------------
extern "C" void kernel_launch(void* const* d_in, const int* in_sizes, int n_in,
                              void* d_out, int out_size)
{
    const float* X   = (const float*)d_in[0];
    const float* WQ  = (const float*)d_in[1];
    const float* WK  = (const float*)d_in[2];
    const float* WV  = (const float*)d_in[3];
    const float* WO  = (const float*)d_in[4];
    const int*  esrc = (const int*)d_in[5];
    const int*  edst = (const int*)d_in[6];
    const int*  erel = (const int*)d_in[7];
    float* out = (float*)d_out;

    const int N = NN, E = EE;

    float* qt;
    cudaGetSymbolAddress((void**)&qt, g_qt);
    __nv_bfloat16 *xh, *xl, *wsch, *wscl, *wfh, *wfl, *yh, *yl;
    cudaGetSymbolAddress((void**)&xh,   g_xh);
    cudaGetSymbolAddress((void**)&xl,   g_xl);
    cudaGetSymbolAddress((void**)&wsch, g_wsch);
    cudaGetSymbolAddress((void**)&wscl, g_wscl);
    cudaGetSymbolAddress((void**)&wfh,  g_wfh);
    cudaGetSymbolAddress((void**)&wfl,  g_wfl);
    cudaGetSymbolAddress((void**)&yh,   g_yh);
    cudaGetSymbolAddress((void**)&yl,   g_yl);

    // split-K partial buffers carved out of g_qt (dead after k_node)
    float* part0 = qt;
    float* part1 = qt + (size_t)MPAD * DD;

    cudaFuncSetAttribute(k_mma_gemm<DD, DD, false>, cudaFuncAttributeMaxDynamicSharedMemorySize, GSMEM);
    cudaFuncSetAttribute(k_mma_gemm<YW, YW / 2, true>, cudaFuncAttributeMaxDynamicSharedMemorySize, GSMEM);

    // 1. merged prologue: x split + y-pad zero + weight preprocessing + deg histogram
    k_prologue<<<PRO_BLKS, 256>>>(X, WQ, WK, WO, WV, edst);

    // 2. scan degrees -> rowptr (re-zeroes deg)
    k_scan<<<1, 1024>>>(N);

    // 3. scatter packed src|rel into CSR
    k_scatter<<<(E + 255) / 256, 256>>>(esrc, edst, erel, E);

    // 4. transformed-query GEMM: [MPAD,128] x [768,128]^T -> g_qt
    {
        dim3 grid(YW / 128, MPAD / 128);
        k_mma_gemm<DD, DD, false><<<grid, 256, GSMEM>>>(xh, xl, wsch, wscl, qt, nullptr, N, YW);
    }

    // 5. fused node pass (re-zeroes cursor): scores + denom + weighted-x agg -> Y hi/lo
    k_node<<<(N + 7) / 8, 256>>>(X, N);

    // 6. final GEMM, split-K 2-way: [MPAD,768] x [128,768]^T -> partials
    {
        dim3 grid(2, MPAD / 128);
        k_mma_gemm<YW, YW / 2, true><<<grid, 256, GSMEM>>>(yh, yl, wfh, wfl, part0, part1, N, DD);
    }

    // 7. sum partials -> out
    k_addout<<<(N * DD / 4 + 255) / 256, 256>>>(part0, part1, out, N * DD / 4);
}

// round 13
// speedup vs baseline: 1.5396x; 1.2256x over previous
#include <cuda_runtime.h>
#include <cuda_bf16.h>
#include <cuda_fp16.h>
#include <cstdint>

// Problem constants (fixed by the dataset)
#define NN    20000
#define MPAD  20096        // 157 * 128
#define EE    320000
#define DD    128
#define HD    256
#define YW    768          // 3 rel * 2 head * 128
// weights pre-scaled by 256 -> score scale = 16*256, output scale 1/256
#define SCALE2 4096.0f
#define OSCALE (1.0f / 256.0f)

// ---------------- scratch (device globals; no allocation) ----------------
__device__ float   g_qt[(size_t)NN * YW];        // fp32 transformed queries (x256); reused as split-K partials
__device__ __half  g_xf[(size_t)MPAD * DD];      // x in fp16 (single limb)
__device__ __half  g_wsch[(size_t)YW * DD];      // Wsc*256 = WK^T WQ blocks, fp16 hi/lo [768,128]
__device__ __half  g_wscl[(size_t)YW * DD];
__device__ __half  g_wfh[(size_t)DD * YW];       // Wfin*256 = WO x WV blocks, fp16 hi/lo [128,768]
__device__ __half  g_wfl[(size_t)DD * YW];
__device__ __half  g_yf[(size_t)MPAD * YW];      // weighted-x aggregate, fp16 single limb
__device__ int   g_deg[NN];        // zero at load; re-zeroed by k_scan each call
__device__ int   g_rowptr[NN + 1];
__device__ int   g_cursor[NN];     // zero at load; re-zeroed by k_node each call
__device__ int   g_pack[EE];       // CSR-ordered src | (rel<<15)

__device__ __forceinline__ uint32_t smem_u32(const void* p) {
    uint32_t a;
    asm("{ .reg .u64 t; cvta.to.shared.u64 t, %1; cvt.u32.u64 %0, t; }" : "=r"(a) : "l"(p));
    return a;
}
__device__ __forceinline__ void ldsm_x4(uint32_t& r0, uint32_t& r1, uint32_t& r2, uint32_t& r3,
                                        uint32_t addr) {
    asm volatile("ldmatrix.sync.aligned.m8n8.x4.shared.b16 {%0,%1,%2,%3}, [%4];"
                 : "=r"(r0), "=r"(r1), "=r"(r2), "=r"(r3) : "r"(addr));
}
__device__ __forceinline__ void mma_f16(float* d, const uint32_t* a, const uint32_t* b) {
    asm volatile(
        "mma.sync.aligned.m16n8k16.row.col.f32.f16.f16.f32 "
        "{%0,%1,%2,%3}, {%4,%5,%6,%7}, {%8,%9}, {%0,%1,%2,%3};"
        : "+f"(d[0]), "+f"(d[1]), "+f"(d[2]), "+f"(d[3])
        : "r"(a[0]), "r"(a[1]), "r"(a[2]), "r"(a[3]), "r"(b[0]), "r"(b[1]));
}
#define CP_ASYNC16(dst, src) \
    asm volatile("cp.async.cg.shared.global [%0], [%1], 16;\n" :: "r"(dst), "l"(src))
#define CP_COMMIT() asm volatile("cp.async.commit_group;\n" ::: "memory")
#define CP_WAIT(n)  asm volatile("cp.async.wait_group %0;\n" :: "n"(n) : "memory")

// ---------------- merged prologue: x fp16 | y-pad zero | weight pre | deg histogram ----------------
#define SPLIT_BLKS 10048
#define PAD_BLKS   288
#define WPRE_BLKS  768
#define DEG_BLKS   1250
#define PRO_BLKS   (SPLIT_BLKS + PAD_BLKS + WPRE_BLKS + DEG_BLKS)

__global__ __launch_bounds__(256)
void k_prologue(const float* __restrict__ X,
                const float* __restrict__ WQ, const float* __restrict__ WK,
                const float* __restrict__ WO, const float* __restrict__ WV,
                const int* __restrict__ edst)
{
    int blk = blockIdx.x;
    int t = threadIdx.x;

    if (blk < SPLIT_BLKS) {
        int i = blk * 256 + t;
        float x = (i < NN * DD) ? X[i] : 0.0f;
        g_xf[i] = __float2half(x);
        return;
    }
    blk -= SPLIT_BLKS;
    if (blk < PAD_BLKS) {
        int i = blk * 256 + t;     // < 73728
        g_yf[(size_t)NN * YW + i] = __float2half(0.0f);
        return;
    }
    blk -= PAD_BLKS;
    if (blk < WPRE_BLKS) {
        int idx = blk * 256 + t;          // < 196608
        int sec = idx >> 14;              // 0..11
        int row = (idx >> 7) & 127;
        int col = idx & 127;
        if (sec < 6) {
            int rh = sec, r = rh >> 1, h = rh & 1;
            int k = row, d2 = col;
            const float* wk = WK + (size_t)r * HD * DD + (size_t)(h * 128) * DD + k;
            const float* wq = WQ + (size_t)(h * 128) * DD + d2;
            float a0 = 0.f, a1 = 0.f, a2 = 0.f, a3 = 0.f;
            #pragma unroll
            for (int d = 0; d < 128; d += 4) {
                a0 = fmaf(wk[(size_t)(d + 0) * DD], wq[(size_t)(d + 0) * DD], a0);
                a1 = fmaf(wk[(size_t)(d + 1) * DD], wq[(size_t)(d + 1) * DD], a1);
                a2 = fmaf(wk[(size_t)(d + 2) * DD], wq[(size_t)(d + 2) * DD], a2);
                a3 = fmaf(wk[(size_t)(d + 3) * DD], wq[(size_t)(d + 3) * DD], a3);
            }
            float acc = ((a0 + a1) + (a2 + a3)) * 256.0f;   // scale up -> fp16 lo limb stays normal
            size_t o = (size_t)(rh * 128 + k) * DD + d2;
            __half hi = __float2half(acc);
            g_wsch[o] = hi;
            g_wscl[o] = __float2half(acc - __half2float(hi));
        } else {
            int rh = sec - 6, r = rh >> 1, h = rh & 1;
            int o = row, k = col;
            const float* wo = WO + o * HD + h * 128;
            const float* wv = WV + ((size_t)(r * HD + h * 128)) * DD + k;
            float a0 = 0.f, a1 = 0.f, a2 = 0.f, a3 = 0.f;
            #pragma unroll
            for (int d = 0; d < 128; d += 4) {
                a0 = fmaf(wo[d + 0], wv[(size_t)(d + 0) * DD], a0);
                a1 = fmaf(wo[d + 1], wv[(size_t)(d + 1) * DD], a1);
                a2 = fmaf(wo[d + 2], wv[(size_t)(d + 2) * DD], a2);
                a3 = fmaf(wo[d + 3], wv[(size_t)(d + 3) * DD], a3);
            }
            float acc = ((a0 + a1) + (a2 + a3)) * 256.0f;
            size_t oidx = (size_t)o * YW + rh * 128 + k;
            __half hi = __float2half(acc);
            g_wfh[oidx] = hi;
            g_wfl[oidx] = __float2half(acc - __half2float(hi));
        }
        return;
    }
    blk -= WPRE_BLKS;
    {
        int e = blk * 256 + t;
        if (e < EE) atomicAdd(&g_deg[edst[e]], 1);
    }
}

// ---------------- fast scan (also re-zeroes deg for the next replay) ----------------
__global__ __launch_bounds__(1024) void k_scan(int n)
{
    const int P = 20;
    __shared__ int wsum[32];
    int tid = threadIdx.x, lane = tid & 31, wid = tid >> 5;
    int base = tid * P;
    int v[P];
    int s = 0;
    #pragma unroll
    for (int i = 0; i < P; i++) {
        int idx = base + i;
        int d = (idx < n) ? g_deg[idx] : 0;
        if (idx < n) g_deg[idx] = 0;   // self-clean for next graph replay
        s += d;
        v[i] = s;
    }
    int x = s;
    #pragma unroll
    for (int off = 1; off < 32; off <<= 1) {
        int t = __shfl_up_sync(0xffffffffu, x, off);
        if (lane >= off) x += t;
    }
    if (lane == 31) wsum[wid] = x;
    __syncthreads();
    if (wid == 0) {
        int y = wsum[lane];
        #pragma unroll
        for (int off = 1; off < 32; off <<= 1) {
            int t = __shfl_up_sync(0xffffffffu, y, off);
            if (lane >= off) y += t;
        }
        wsum[lane] = y;
    }
    __syncthreads();
    int offset = (wid ? wsum[wid - 1] : 0) + x - s;
    if (tid == 0) g_rowptr[0] = 0;
    #pragma unroll
    for (int i = 0; i < P; i++) {
        int idx = base + i;
        if (idx < n) g_rowptr[idx + 1] = offset + v[i];
    }
}

// ---------------- scatter packed src|rel into CSR ----------------
__global__ void k_scatter(const int* __restrict__ esrc, const int* __restrict__ edst,
                          const int* __restrict__ erel, int E)
{
    int e = blockIdx.x * blockDim.x + threadIdx.x;
    if (e >= E) return;
    int dst = edst[e];
    int pos = atomicAdd(&g_cursor[dst], 1);
    g_pack[g_rowptr[dst] + pos] = esrc[e] | (erel[e] << 15);
}

// ---------------- mma.sync GEMM: fp16, A single limb, B hi/lo, 2 passes ----------------
#define SSTR   40
#define TILEB  10240
#define STAGEB (3 * TILEB)       // A, Bh, Bl
#define GSMEM  (2 * STAGEB)      // 61440 B

template <int KSTR, int KLEN, bool SPLITK>
__global__ __launch_bounds__(256)
void k_mma_gemm(const __half* __restrict__ A,
                const __half* __restrict__ Bh, const __half* __restrict__ Bl,
                float* __restrict__ C0, float* __restrict__ C1, int Mreal, int ldc)
{
    extern __shared__ uint8_t dsm[];
    const uint32_t sb = smem_u32(dsm);
    const int tid  = threadIdx.x;
    const int wid  = tid >> 5;
    const int lane = tid & 31;
    const int m0 = blockIdx.y * 128;
    const int j0 = SPLITK ? 0 : blockIdx.x * 128;
    const int koff = SPLITK ? blockIdx.x * KLEN : 0;
    float* C = (SPLITK && blockIdx.x) ? C1 : C0;
    const int warp_m = (wid & 3) * 32;
    const int warp_n = (wid >> 2) * 64;

    const int ar = lane & 15;
    const int kh = (lane >> 4) << 3;

    float acc[2][8][4];
    #pragma unroll
    for (int i = 0; i < 2; i++)
        #pragma unroll
        for (int j = 0; j < 8; j++)
            #pragma unroll
            for (int q = 0; q < 4; q++) acc[i][j][q] = 0.0f;

    int rowA[2], c8A[2];
    #pragma unroll
    for (int i = 0; i < 2; i++) {
        int v = tid + i * 256;
        rowA[i] = v >> 2;
        c8A[i] = (v & 3) << 3;
    }

    auto prefetch = [&](int kt, int stage) {
        uint32_t base = sb + (uint32_t)stage * STAGEB;
        #pragma unroll
        for (int i = 0; i < 2; i++) {
            int row = rowA[i], c8 = c8A[i];
            uint32_t so = base + (uint32_t)(row * SSTR + c8) * 2;
            size_t ga = (size_t)(m0 + row) * KSTR + koff + kt + c8;
            size_t gb = (size_t)(j0 + row) * KSTR + koff + kt + c8;
            CP_ASYNC16(so,             A  + ga);
            CP_ASYNC16(so + TILEB,     Bh + gb);
            CP_ASYNC16(so + 2 * TILEB, Bl + gb);
        }
        CP_COMMIT();
    };

    constexpr int NCH = KLEN / 32;
    prefetch(0, 0);

    for (int ch = 0; ch < NCH; ch++) {
        if (ch + 1 < NCH) {
            prefetch((ch + 1) * 32, (ch + 1) & 1);
            CP_WAIT(1);
        } else {
            CP_WAIT(0);
        }
        __syncthreads();

        uint32_t base = sb + (uint32_t)(ch & 1) * STAGEB;
        #pragma unroll
        for (int k16 = 0; k16 < 2; k16++) {
            uint32_t kb = (uint32_t)((k16 * 16 + kh) * 2);

            uint32_t a[2][4];
            #pragma unroll
            for (int mi = 0; mi < 2; mi++) {
                uint32_t off = (uint32_t)((warp_m + mi * 16 + ar) * SSTR * 2) + kb;
                ldsm_x4(a[mi][0], a[mi][1], a[mi][2], a[mi][3], base + off);
            }
            uint32_t bh[8][2], bl[8][2];
            #pragma unroll
            for (int ng = 0; ng < 4; ng++) {
                uint32_t off = (uint32_t)((warp_n + ng * 16 + ar) * SSTR * 2) + kb;
                uint32_t r0, r1, r2, r3;
                ldsm_x4(r0, r1, r2, r3, base + TILEB + off);
                bh[ng * 2][0] = r0;     bh[ng * 2][1] = r2;
                bh[ng * 2 + 1][0] = r1; bh[ng * 2 + 1][1] = r3;
                ldsm_x4(r0, r1, r2, r3, base + 2 * TILEB + off);
                bl[ng * 2][0] = r0;     bl[ng * 2][1] = r2;
                bl[ng * 2 + 1][0] = r1; bl[ng * 2 + 1][1] = r3;
            }

            #pragma unroll
            for (int mi = 0; mi < 2; mi++)
                #pragma unroll
                for (int nj = 0; nj < 8; nj++)
                    mma_f16(acc[mi][nj], a[mi], bh[nj]);
            #pragma unroll
            for (int mi = 0; mi < 2; mi++)
                #pragma unroll
                for (int nj = 0; nj < 8; nj++)
                    mma_f16(acc[mi][nj], a[mi], bl[nj]);
        }
        __syncthreads();
    }

    const int rg = lane >> 2;
    const int tg = lane & 3;
    #pragma unroll
    for (int mi = 0; mi < 2; mi++) {
        int r0 = m0 + warp_m + mi * 16 + rg;
        int r1 = r0 + 8;
        #pragma unroll
        for (int nj = 0; nj < 8; nj++) {
            int col = j0 + warp_n + nj * 8 + tg * 2;
            if (r0 < Mreal) {
                float2 v = {acc[mi][nj][0], acc[mi][nj][1]};
                *(float2*)(C + (size_t)r0 * ldc + col) = v;
            }
            if (r1 < Mreal) {
                float2 v = {acc[mi][nj][2], acc[mi][nj][3]};
                *(float2*)(C + (size_t)r1 * ldc + col) = v;
            }
        }
    }
}

// ---------------- split-K partial sum -> out (undo x256 weight scaling) ----------------
__global__ void k_addout(const float* __restrict__ p0, const float* __restrict__ p1,
                         float* __restrict__ out, int n4)
{
    int i = blockIdx.x * blockDim.x + threadIdx.x;
    if (i >= n4) return;
    float4 a = ((const float4*)p0)[i];
    float4 b = ((const float4*)p1)[i];
    float4 v = {(a.x + b.x) * OSCALE, (a.y + b.y) * OSCALE,
                (a.z + b.z) * OSCALE, (a.w + b.w) * OSCALE};
    ((float4*)out)[i] = v;
}

// ---------------- fused node kernel (R7-proven loop; re-zeroes cursor) ----------------
__global__ __launch_bounds__(256)
void k_node(const float* __restrict__ X, int N)
{
    int warp = (blockIdx.x * blockDim.x + threadIdx.x) >> 5;
    int lane = threadIdx.x & 31;
    if (warp >= N) return;

    if (lane == 0) g_cursor[warp] = 0;   // self-clean for next graph replay

    const int start = g_rowptr[warp];
    const int end   = g_rowptr[warp + 1];

    float qt[6][4];
    {
        const float* qr = g_qt + (size_t)warp * YW;
        #pragma unroll
        for (int c = 0; c < 6; c++) {
            float4 v = *(const float4*)(qr + c * 128 + lane * 4);
            qt[c][0] = v.x; qt[c][1] = v.y; qt[c][2] = v.z; qt[c][3] = v.w;
        }
    }

    float y[3][2][4];
    #pragma unroll
    for (int r = 0; r < 3; r++)
        #pragma unroll
        for (int h = 0; h < 2; h++)
            #pragma unroll
            for (int i = 0; i < 4; i++) y[r][h][i] = 0.0f;

    float den0 = 0.0f, den1 = 0.0f;

    int j = start;
    int pk0 = (j < end)     ? g_pack[j]     : 0;
    int pk1 = (j + 1 < end) ? g_pack[j + 1] : 0;

    while (j + 1 < end) {
        int s0 = pk0 & 0x7FFF, r0 = pk0 >> 15;
        int s1 = pk1 & 0x7FFF, r1 = pk1 >> 15;
        int nj = j + 2;
        int npk0 = (nj < end)     ? g_pack[nj]     : 0;
        int npk1 = (nj + 1 < end) ? g_pack[nj + 1] : 0;

        float4 xv0 = *(const float4*)(X + (size_t)s0 * DD + lane * 4);
        float4 xv1 = *(const float4*)(X + (size_t)s1 * DD + lane * 4);
        float xa0[4] = {xv0.x, xv0.y, xv0.z, xv0.w};
        float xa1[4] = {xv1.x, xv1.y, xv1.z, xv1.w};

        float p00 = 0.f, p01 = 0.f, p10 = 0.f, p11 = 0.f;
        #pragma unroll
        for (int i = 0; i < 4; i++) {
            p00 = fmaf(qt[r0 * 2][i],     xa0[i], p00);
            p01 = fmaf(qt[r0 * 2 + 1][i], xa0[i], p01);
            p10 = fmaf(qt[r1 * 2][i],     xa1[i], p10);
            p11 = fmaf(qt[r1 * 2 + 1][i], xa1[i], p11);
        }
        #pragma unroll
        for (int off = 16; off >= 1; off >>= 1) {
            p00 += __shfl_xor_sync(0xffffffffu, p00, off);
            p01 += __shfl_xor_sync(0xffffffffu, p01, off);
            p10 += __shfl_xor_sync(0xffffffffu, p10, off);
            p11 += __shfl_xor_sync(0xffffffffu, p11, off);
        }
        float nuA0 = fmaxf(p00 / SCALE2, 0.0f); nuA0 = nuA0 * nuA0 + 1e-10f;
        float nuA1 = fmaxf(p01 / SCALE2, 0.0f); nuA1 = nuA1 * nuA1 + 1e-10f;
        float nuB0 = fmaxf(p10 / SCALE2, 0.0f); nuB0 = nuB0 * nuB0 + 1e-10f;
        float nuB1 = fmaxf(p11 / SCALE2, 0.0f); nuB1 = nuB1 * nuB1 + 1e-10f;
        den0 += nuA0 + nuB0;
        den1 += nuA1 + nuB1;

        if (r0 == 0) {
            #pragma unroll
            for (int i = 0; i < 4; i++) { y[0][0][i] += nuA0 * xa0[i]; y[0][1][i] += nuA1 * xa0[i]; }
        } else if (r0 == 1) {
            #pragma unroll
            for (int i = 0; i < 4; i++) { y[1][0][i] += nuA0 * xa0[i]; y[1][1][i] += nuA1 * xa0[i]; }
        } else {
            #pragma unroll
            for (int i = 0; i < 4; i++) { y[2][0][i] += nuA0 * xa0[i]; y[2][1][i] += nuA1 * xa0[i]; }
        }
        if (r1 == 0) {
            #pragma unroll
            for (int i = 0; i < 4; i++) { y[0][0][i] += nuB0 * xa1[i]; y[0][1][i] += nuB1 * xa1[i]; }
        } else if (r1 == 1) {
            #pragma unroll
            for (int i = 0; i < 4; i++) { y[1][0][i] += nuB0 * xa1[i]; y[1][1][i] += nuB1 * xa1[i]; }
        } else {
            #pragma unroll
            for (int i = 0; i < 4; i++) { y[2][0][i] += nuB0 * xa1[i]; y[2][1][i] += nuB1 * xa1[i]; }
        }

        j = nj; pk0 = npk0; pk1 = npk1;
    }

    if (j < end) {
        int s0 = pk0 & 0x7FFF, r0 = pk0 >> 15;
        float4 xv = *(const float4*)(X + (size_t)s0 * DD + lane * 4);
        float xa[4] = {xv.x, xv.y, xv.z, xv.w};
        float p0 = 0.f, p1 = 0.f;
        #pragma unroll
        for (int i = 0; i < 4; i++) {
            p0 = fmaf(qt[r0 * 2][i],     xa[i], p0);
            p1 = fmaf(qt[r0 * 2 + 1][i], xa[i], p1);
        }
        #pragma unroll
        for (int off = 16; off >= 1; off >>= 1) {
            p0 += __shfl_xor_sync(0xffffffffu, p0, off);
            p1 += __shfl_xor_sync(0xffffffffu, p1, off);
        }
        float nu0 = fmaxf(p0 / SCALE2, 0.0f); nu0 = nu0 * nu0 + 1e-10f;
        float nu1 = fmaxf(p1 / SCALE2, 0.0f); nu1 = nu1 * nu1 + 1e-10f;
        den0 += nu0;
        den1 += nu1;
        if (r0 == 0) {
            #pragma unroll
            for (int i = 0; i < 4; i++) { y[0][0][i] += nu0 * xa[i]; y[0][1][i] += nu1 * xa[i]; }
        } else if (r0 == 1) {
            #pragma unroll
            for (int i = 0; i < 4; i++) { y[1][0][i] += nu0 * xa[i]; y[1][1][i] += nu1 * xa[i]; }
        } else {
            #pragma unroll
            for (int i = 0; i < 4; i++) { y[2][0][i] += nu0 * xa[i]; y[2][1][i] += nu1 * xa[i]; }
        }
    }

    float inv0 = (den0 > 0.0f) ? 1.0f / den0 : 0.0f;
    float inv1 = (den1 > 0.0f) ? 1.0f / den1 : 0.0f;

    // writeout: single fp16 limb, 4 halfs (8B) per (r,h) per lane
    #pragma unroll
    for (int r = 0; r < 3; r++)
        #pragma unroll
        for (int h = 0; h < 2; h++) {
            float sc = h ? inv1 : inv0;
            size_t off = (size_t)warp * YW + (r * 2 + h) * 128 + lane * 4;
            __half hv[4];
            #pragma unroll
            for (int i = 0; i < 4; i++)
                hv[i] = __float2half(y[r][h][i] * sc);
            *(uint2*)(g_yf + off) = *(uint2*)hv;
        }
}

// ---------------- launch ----------------
extern "C" void kernel_launch(void* const* d_in, const int* in_sizes, int n_in,
                              void* d_out, int out_size)
{
    const float* X   = (const float*)d_in[0];
    const float* WQ  = (const float*)d_in[1];
    const float* WK  = (const float*)d_in[2];
    const float* WV  = (const float*)d_in[3];
    const float* WO  = (const float*)d_in[4];
    const int*  esrc = (const int*)d_in[5];
    const int*  edst = (const int*)d_in[6];
    const int*  erel = (const int*)d_in[7];
    float* out = (float*)d_out;

    const int N = NN, E = EE;

    float* qt;
    cudaGetSymbolAddress((void**)&qt, g_qt);
    __half *xf, *wsch, *wscl, *wfh, *wfl, *yf;
    cudaGetSymbolAddress((void**)&xf,   g_xf);
    cudaGetSymbolAddress((void**)&wsch, g_wsch);
    cudaGetSymbolAddress((void**)&wscl, g_wscl);
    cudaGetSymbolAddress((void**)&wfh,  g_wfh);
    cudaGetSymbolAddress((void**)&wfl,  g_wfl);
    cudaGetSymbolAddress((void**)&yf,   g_yf);

    // split-K partial buffers carved out of g_qt (dead after k_node)
    float* part0 = qt;
    float* part1 = qt + (size_t)MPAD * DD;

    cudaFuncSetAttribute(k_mma_gemm<DD, DD, false>, cudaFuncAttributeMaxDynamicSharedMemorySize, GSMEM);
    cudaFuncSetAttribute(k_mma_gemm<YW, YW / 2, true>, cudaFuncAttributeMaxDynamicSharedMemorySize, GSMEM);

    // 1. merged prologue: x fp16 + y-pad zero + weight preprocessing (x256) + deg histogram
    k_prologue<<<PRO_BLKS, 256>>>(X, WQ, WK, WO, WV, edst);

    // 2. scan degrees -> rowptr (re-zeroes deg)
    k_scan<<<1, 1024>>>(N);

    // 3. scatter packed src|rel into CSR
    k_scatter<<<(E + 255) / 256, 256>>>(esrc, edst, erel, E);

    // 4. transformed-query GEMM: [MPAD,128] x [768,128]^T -> g_qt (values x256)
    {
        dim3 grid(YW / 128, MPAD / 128);
        k_mma_gemm<DD, DD, false><<<grid, 256, GSMEM>>>(xf, wsch, wscl, qt, nullptr, N, YW);
    }

    // 5. fused node pass (re-zeroes cursor): scores + denom + weighted-x agg -> yf
    k_node<<<(N + 7) / 8, 256>>>(X, N);

    // 6. final GEMM, split-K 2-way: [MPAD,768] x [128,768]^T -> partials (x256)
    {
        dim3 grid(2, MPAD / 128);
        k_mma_gemm<YW, YW / 2, true><<<grid, 256, GSMEM>>>(yf, wfh, wfl, part0, part1, N, DD);
    }

    // 7. sum partials, scale by 1/256 -> out
    k_addout<<<(N * DD / 4 + 255) / 256, 256>>>(part0, part1, out, N * DD / 4);
}

// round 14
// speedup vs baseline: 1.6880x; 1.0964x over previous
#include <cuda_runtime.h>
#include <cuda_bf16.h>
#include <cuda_fp16.h>
#include <cstdint>

// Problem constants (fixed by the dataset)
#define NN    20000
#define MPAD  20096        // 157 * 128
#define EE    320000
#define DD    128
#define HD    256
#define YW    768          // 3 rel * 2 head * 128
// weights pre-scaled by 256 -> score scale = 16*256, output scale 1/256
#define SCALE2 4096.0f
#define OSCALE (1.0f / 256.0f)

// ---------------- scratch (device globals; no allocation) ----------------
__device__ float   g_qt[(size_t)NN * YW];        // fp32 transformed queries (x256); reused as split-K partials
__device__ __half  g_xf[(size_t)MPAD * DD];      // x in fp16 (single limb)
__device__ __half  g_wsch[(size_t)YW * DD];      // Wsc*256 = WK^T WQ blocks, fp16 hi/lo [768,128]
__device__ __half  g_wscl[(size_t)YW * DD];
__device__ __half  g_wfh[(size_t)DD * YW];       // Wfin*256 = WO x WV blocks, fp16 single limb [128,768]
__device__ __half  g_yf[(size_t)MPAD * YW];      // weighted-x aggregate, fp16 single limb
__device__ int   g_deg[NN];        // zero at load; re-zeroed by k_scan each call
__device__ int   g_rowptr[NN + 1];
__device__ int   g_cursor[NN];     // zero at load; re-zeroed by k_node each call
__device__ int   g_pack[EE];       // CSR-ordered src | (rel<<15)

__device__ __forceinline__ uint32_t smem_u32(const void* p) {
    uint32_t a;
    asm("{ .reg .u64 t; cvta.to.shared.u64 t, %1; cvt.u32.u64 %0, t; }" : "=r"(a) : "l"(p));
    return a;
}
__device__ __forceinline__ void ldsm_x4(uint32_t& r0, uint32_t& r1, uint32_t& r2, uint32_t& r3,
                                        uint32_t addr) {
    asm volatile("ldmatrix.sync.aligned.m8n8.x4.shared.b16 {%0,%1,%2,%3}, [%4];"
                 : "=r"(r0), "=r"(r1), "=r"(r2), "=r"(r3) : "r"(addr));
}
__device__ __forceinline__ void mma_f16(float* d, const uint32_t* a, const uint32_t* b) {
    asm volatile(
        "mma.sync.aligned.m16n8k16.row.col.f32.f16.f16.f32 "
        "{%0,%1,%2,%3}, {%4,%5,%6,%7}, {%8,%9}, {%0,%1,%2,%3};"
        : "+f"(d[0]), "+f"(d[1]), "+f"(d[2]), "+f"(d[3])
        : "r"(a[0]), "r"(a[1]), "r"(a[2]), "r"(a[3]), "r"(b[0]), "r"(b[1]));
}
#define CP_ASYNC16(dst, src) \
    asm volatile("cp.async.cg.shared.global [%0], [%1], 16;\n" :: "r"(dst), "l"(src))
#define CP_COMMIT() asm volatile("cp.async.commit_group;\n" ::: "memory")
#define CP_WAIT(n)  asm volatile("cp.async.wait_group %0;\n" :: "n"(n) : "memory")

// ---------------- merged prologue: x fp16 | y-pad zero | weight pre | deg histogram ----------------
#define SPLIT_BLKS 10048
#define PAD_BLKS   288
#define WPRE_BLKS  768
#define DEG_BLKS   1250
#define PRO_BLKS   (SPLIT_BLKS + PAD_BLKS + WPRE_BLKS + DEG_BLKS)

__global__ __launch_bounds__(256)
void k_prologue(const float* __restrict__ X,
                const float* __restrict__ WQ, const float* __restrict__ WK,
                const float* __restrict__ WO, const float* __restrict__ WV,
                const int* __restrict__ edst)
{
    int blk = blockIdx.x;
    int t = threadIdx.x;

    if (blk < SPLIT_BLKS) {
        int i = blk * 256 + t;
        float x = (i < NN * DD) ? X[i] : 0.0f;
        g_xf[i] = __float2half(x);
        return;
    }
    blk -= SPLIT_BLKS;
    if (blk < PAD_BLKS) {
        int i = blk * 256 + t;     // < 73728
        g_yf[(size_t)NN * YW + i] = __float2half(0.0f);
        return;
    }
    blk -= PAD_BLKS;
    if (blk < WPRE_BLKS) {
        int idx = blk * 256 + t;          // < 196608
        int sec = idx >> 14;              // 0..11
        int row = (idx >> 7) & 127;
        int col = idx & 127;
        if (sec < 6) {
            int rh = sec, r = rh >> 1, h = rh & 1;
            int k = row, d2 = col;
            const float* wk = WK + (size_t)r * HD * DD + (size_t)(h * 128) * DD + k;
            const float* wq = WQ + (size_t)(h * 128) * DD + d2;
            float a0 = 0.f, a1 = 0.f, a2 = 0.f, a3 = 0.f;
            #pragma unroll
            for (int d = 0; d < 128; d += 4) {
                a0 = fmaf(wk[(size_t)(d + 0) * DD], wq[(size_t)(d + 0) * DD], a0);
                a1 = fmaf(wk[(size_t)(d + 1) * DD], wq[(size_t)(d + 1) * DD], a1);
                a2 = fmaf(wk[(size_t)(d + 2) * DD], wq[(size_t)(d + 2) * DD], a2);
                a3 = fmaf(wk[(size_t)(d + 3) * DD], wq[(size_t)(d + 3) * DD], a3);
            }
            float acc = ((a0 + a1) + (a2 + a3)) * 256.0f;   // scale up -> fp16 lo limb stays normal
            size_t o = (size_t)(rh * 128 + k) * DD + d2;
            __half hi = __float2half(acc);
            g_wsch[o] = hi;
            g_wscl[o] = __float2half(acc - __half2float(hi));
        } else {
            int rh = sec - 6, r = rh >> 1, h = rh & 1;
            int o = row, k = col;
            const float* wo = WO + o * HD + h * 128;
            const float* wv = WV + ((size_t)(r * HD + h * 128)) * DD + k;
            float a0 = 0.f, a1 = 0.f, a2 = 0.f, a3 = 0.f;
            #pragma unroll
            for (int d = 0; d < 128; d += 4) {
                a0 = fmaf(wo[d + 0], wv[(size_t)(d + 0) * DD], a0);
                a1 = fmaf(wo[d + 1], wv[(size_t)(d + 1) * DD], a1);
                a2 = fmaf(wo[d + 2], wv[(size_t)(d + 2) * DD], a2);
                a3 = fmaf(wo[d + 3], wv[(size_t)(d + 3) * DD], a3);
            }
            float acc = ((a0 + a1) + (a2 + a3)) * 256.0f;
            g_wfh[(size_t)o * YW + rh * 128 + k] = __float2half(acc);   // single limb
        }
        return;
    }
    blk -= WPRE_BLKS;
    {
        int e = blk * 256 + t;
        if (e < EE) atomicAdd(&g_deg[edst[e]], 1);
    }
}

// ---------------- fast scan (also re-zeroes deg for the next replay) ----------------
__global__ __launch_bounds__(1024) void k_scan(int n)
{
    const int P = 20;
    __shared__ int wsum[32];
    int tid = threadIdx.x, lane = tid & 31, wid = tid >> 5;
    int base = tid * P;
    int v[P];
    int s = 0;
    #pragma unroll
    for (int i = 0; i < P; i++) {
        int idx = base + i;
        int d = (idx < n) ? g_deg[idx] : 0;
        if (idx < n) g_deg[idx] = 0;   // self-clean for next graph replay
        s += d;
        v[i] = s;
    }
    int x = s;
    #pragma unroll
    for (int off = 1; off < 32; off <<= 1) {
        int t = __shfl_up_sync(0xffffffffu, x, off);
        if (lane >= off) x += t;
    }
    if (lane == 31) wsum[wid] = x;
    __syncthreads();
    if (wid == 0) {
        int y = wsum[lane];
        #pragma unroll
        for (int off = 1; off < 32; off <<= 1) {
            int t = __shfl_up_sync(0xffffffffu, y, off);
            if (lane >= off) y += t;
        }
        wsum[lane] = y;
    }
    __syncthreads();
    int offset = (wid ? wsum[wid - 1] : 0) + x - s;
    if (tid == 0) g_rowptr[0] = 0;
    #pragma unroll
    for (int i = 0; i < P; i++) {
        int idx = base + i;
        if (idx < n) g_rowptr[idx + 1] = offset + v[i];
    }
}

// ---------------- scatter packed src|rel into CSR ----------------
__global__ void k_scatter(const int* __restrict__ esrc, const int* __restrict__ edst,
                          const int* __restrict__ erel, int E)
{
    int e = blockIdx.x * blockDim.x + threadIdx.x;
    if (e >= E) return;
    int dst = edst[e];
    int pos = atomicAdd(&g_cursor[dst], 1);
    g_pack[g_rowptr[dst] + pos] = esrc[e] | (erel[e] << 15);
}

// ---------------- mma.sync GEMM: fp16, A single limb, B hi(/lo), 3-stage pipeline ----------------
#define SSTR   40
#define TILEB  10240

template <int KSTR, int KLEN, bool SPLITK, bool BLO>
__global__ __launch_bounds__(256)
void k_mma_gemm(const __half* __restrict__ A,
                const __half* __restrict__ Bh, const __half* __restrict__ Bl,
                float* __restrict__ C0, float* __restrict__ C1, int Mreal, int ldc)
{
    constexpr uint32_t SMSTAGE = (BLO ? 3 : 2) * TILEB;
    extern __shared__ uint8_t dsm[];
    const uint32_t sb = smem_u32(dsm);
    const int tid  = threadIdx.x;
    const int wid  = tid >> 5;
    const int lane = tid & 31;
    const int m0 = blockIdx.y * 128;
    const int j0 = SPLITK ? 0 : blockIdx.x * 128;
    const int koff = SPLITK ? blockIdx.x * KLEN : 0;
    float* C = (SPLITK && blockIdx.x) ? C1 : C0;
    const int warp_m = (wid & 3) * 32;
    const int warp_n = (wid >> 2) * 64;

    const int ar = lane & 15;
    const int kh = (lane >> 4) << 3;

    float acc[2][8][4];
    #pragma unroll
    for (int i = 0; i < 2; i++)
        #pragma unroll
        for (int j = 0; j < 8; j++)
            #pragma unroll
            for (int q = 0; q < 4; q++) acc[i][j][q] = 0.0f;

    int rowA[2], c8A[2];
    #pragma unroll
    for (int i = 0; i < 2; i++) {
        int v = tid + i * 256;
        rowA[i] = v >> 2;
        c8A[i] = (v & 3) << 3;
    }

    auto prefetch = [&](int ch) {
        uint32_t base = sb + (uint32_t)(ch % 3) * SMSTAGE;
        int kt = ch * 32;
        #pragma unroll
        for (int i = 0; i < 2; i++) {
            int row = rowA[i], c8 = c8A[i];
            uint32_t so = base + (uint32_t)(row * SSTR + c8) * 2;
            size_t ga = (size_t)(m0 + row) * KSTR + koff + kt + c8;
            size_t gb = (size_t)(j0 + row) * KSTR + koff + kt + c8;
            CP_ASYNC16(so,         A  + ga);
            CP_ASYNC16(so + TILEB, Bh + gb);
            if (BLO) CP_ASYNC16(so + 2 * TILEB, Bl + gb);
        }
        CP_COMMIT();
    };

    constexpr int NCH = KLEN / 32;
    prefetch(0);
    if (NCH > 1) prefetch(1);

    for (int ch = 0; ch < NCH; ch++) {
        if (ch == NCH - 1) { CP_WAIT(0); } else { CP_WAIT(1); }
        __syncthreads();
        if (ch + 2 < NCH) prefetch(ch + 2);

        uint32_t base = sb + (uint32_t)(ch % 3) * SMSTAGE;
        #pragma unroll
        for (int k16 = 0; k16 < 2; k16++) {
            uint32_t kb = (uint32_t)((k16 * 16 + kh) * 2);

            uint32_t a[2][4];
            #pragma unroll
            for (int mi = 0; mi < 2; mi++) {
                uint32_t off = (uint32_t)((warp_m + mi * 16 + ar) * SSTR * 2) + kb;
                ldsm_x4(a[mi][0], a[mi][1], a[mi][2], a[mi][3], base + off);
            }
            uint32_t bh[8][2];
            #pragma unroll
            for (int ng = 0; ng < 4; ng++) {
                uint32_t off = (uint32_t)((warp_n + ng * 16 + ar) * SSTR * 2) + kb;
                uint32_t r0, r1, r2, r3;
                ldsm_x4(r0, r1, r2, r3, base + TILEB + off);
                bh[ng * 2][0] = r0;     bh[ng * 2][1] = r2;
                bh[ng * 2 + 1][0] = r1; bh[ng * 2 + 1][1] = r3;
            }
            #pragma unroll
            for (int mi = 0; mi < 2; mi++)
                #pragma unroll
                for (int nj = 0; nj < 8; nj++)
                    mma_f16(acc[mi][nj], a[mi], bh[nj]);

            if (BLO) {
                uint32_t bl[8][2];
                #pragma unroll
                for (int ng = 0; ng < 4; ng++) {
                    uint32_t off = (uint32_t)((warp_n + ng * 16 + ar) * SSTR * 2) + kb;
                    uint32_t r0, r1, r2, r3;
                    ldsm_x4(r0, r1, r2, r3, base + 2 * TILEB + off);
                    bl[ng * 2][0] = r0;     bl[ng * 2][1] = r2;
                    bl[ng * 2 + 1][0] = r1; bl[ng * 2 + 1][1] = r3;
                }
                #pragma unroll
                for (int mi = 0; mi < 2; mi++)
                    #pragma unroll
                    for (int nj = 0; nj < 8; nj++)
                        mma_f16(acc[mi][nj], a[mi], bl[nj]);
            }
        }
        // no trailing sync: stage rewrite happens >=2 barriers later
    }

    const int rg = lane >> 2;
    const int tg = lane & 3;
    #pragma unroll
    for (int mi = 0; mi < 2; mi++) {
        int r0 = m0 + warp_m + mi * 16 + rg;
        int r1 = r0 + 8;
        #pragma unroll
        for (int nj = 0; nj < 8; nj++) {
            int col = j0 + warp_n + nj * 8 + tg * 2;
            if (r0 < Mreal) {
                float2 v = {acc[mi][nj][0], acc[mi][nj][1]};
                *(float2*)(C + (size_t)r0 * ldc + col) = v;
            }
            if (r1 < Mreal) {
                float2 v = {acc[mi][nj][2], acc[mi][nj][3]};
                *(float2*)(C + (size_t)r1 * ldc + col) = v;
            }
        }
    }
}

// ---------------- split-K partial sum -> out (undo x256 weight scaling) ----------------
__global__ void k_addout(const float* __restrict__ p0, const float* __restrict__ p1,
                         float* __restrict__ out, int n4)
{
    int i = blockIdx.x * blockDim.x + threadIdx.x;
    if (i >= n4) return;
    float4 a = ((const float4*)p0)[i];
    float4 b = ((const float4*)p1)[i];
    float4 v = {(a.x + b.x) * OSCALE, (a.y + b.y) * OSCALE,
                (a.z + b.z) * OSCALE, (a.w + b.w) * OSCALE};
    ((float4*)out)[i] = v;
}

// ---------------- fused node kernel (R7-proven loop; re-zeroes cursor) ----------------
__global__ __launch_bounds__(256)
void k_node(const float* __restrict__ X, int N)
{
    int warp = (blockIdx.x * blockDim.x + threadIdx.x) >> 5;
    int lane = threadIdx.x & 31;
    if (warp >= N) return;

    if (lane == 0) g_cursor[warp] = 0;   // self-clean for next graph replay

    const int start = g_rowptr[warp];
    const int end   = g_rowptr[warp + 1];

    float qt[6][4];
    {
        const float* qr = g_qt + (size_t)warp * YW;
        #pragma unroll
        for (int c = 0; c < 6; c++) {
            float4 v = *(const float4*)(qr + c * 128 + lane * 4);
            qt[c][0] = v.x; qt[c][1] = v.y; qt[c][2] = v.z; qt[c][3] = v.w;
        }
    }

    float y[3][2][4];
    #pragma unroll
    for (int r = 0; r < 3; r++)
        #pragma unroll
        for (int h = 0; h < 2; h++)
            #pragma unroll
            for (int i = 0; i < 4; i++) y[r][h][i] = 0.0f;

    float den0 = 0.0f, den1 = 0.0f;

    int j = start;
    int pk0 = (j < end)     ? g_pack[j]     : 0;
    int pk1 = (j + 1 < end) ? g_pack[j + 1] : 0;

    while (j + 1 < end) {
        int s0 = pk0 & 0x7FFF, r0 = pk0 >> 15;
        int s1 = pk1 & 0x7FFF, r1 = pk1 >> 15;
        int nj = j + 2;
        int npk0 = (nj < end)     ? g_pack[nj]     : 0;
        int npk1 = (nj + 1 < end) ? g_pack[nj + 1] : 0;

        float4 xv0 = *(const float4*)(X + (size_t)s0 * DD + lane * 4);
        float4 xv1 = *(const float4*)(X + (size_t)s1 * DD + lane * 4);
        float xa0[4] = {xv0.x, xv0.y, xv0.z, xv0.w};
        float xa1[4] = {xv1.x, xv1.y, xv1.z, xv1.w};

        float p00 = 0.f, p01 = 0.f, p10 = 0.f, p11 = 0.f;
        #pragma unroll
        for (int i = 0; i < 4; i++) {
            p00 = fmaf(qt[r0 * 2][i],     xa0[i], p00);
            p01 = fmaf(qt[r0 * 2 + 1][i], xa0[i], p01);
            p10 = fmaf(qt[r1 * 2][i],     xa1[i], p10);
            p11 = fmaf(qt[r1 * 2 + 1][i], xa1[i], p11);
        }
        #pragma unroll
        for (int off = 16; off >= 1; off >>= 1) {
            p00 += __shfl_xor_sync(0xffffffffu, p00, off);
            p01 += __shfl_xor_sync(0xffffffffu, p01, off);
            p10 += __shfl_xor_sync(0xffffffffu, p10, off);
            p11 += __shfl_xor_sync(0xffffffffu, p11, off);
        }
        float nuA0 = fmaxf(p00 / SCALE2, 0.0f); nuA0 = nuA0 * nuA0 + 1e-10f;
        float nuA1 = fmaxf(p01 / SCALE2, 0.0f); nuA1 = nuA1 * nuA1 + 1e-10f;
        float nuB0 = fmaxf(p10 / SCALE2, 0.0f); nuB0 = nuB0 * nuB0 + 1e-10f;
        float nuB1 = fmaxf(p11 / SCALE2, 0.0f); nuB1 = nuB1 * nuB1 + 1e-10f;
        den0 += nuA0 + nuB0;
        den1 += nuA1 + nuB1;

        if (r0 == 0) {
            #pragma unroll
            for (int i = 0; i < 4; i++) { y[0][0][i] += nuA0 * xa0[i]; y[0][1][i] += nuA1 * xa0[i]; }
        } else if (r0 == 1) {
            #pragma unroll
            for (int i = 0; i < 4; i++) { y[1][0][i] += nuA0 * xa0[i]; y[1][1][i] += nuA1 * xa0[i]; }
        } else {
            #pragma unroll
            for (int i = 0; i < 4; i++) { y[2][0][i] += nuA0 * xa0[i]; y[2][1][i] += nuA1 * xa0[i]; }
        }
        if (r1 == 0) {
            #pragma unroll
            for (int i = 0; i < 4; i++) { y[0][0][i] += nuB0 * xa1[i]; y[0][1][i] += nuB1 * xa1[i]; }
        } else if (r1 == 1) {
            #pragma unroll
            for (int i = 0; i < 4; i++) { y[1][0][i] += nuB0 * xa1[i]; y[1][1][i] += nuB1 * xa1[i]; }
        } else {
            #pragma unroll
            for (int i = 0; i < 4; i++) { y[2][0][i] += nuB0 * xa1[i]; y[2][1][i] += nuB1 * xa1[i]; }
        }

        j = nj; pk0 = npk0; pk1 = npk1;
    }

    if (j < end) {
        int s0 = pk0 & 0x7FFF, r0 = pk0 >> 15;
        float4 xv = *(const float4*)(X + (size_t)s0 * DD + lane * 4);
        float xa[4] = {xv.x, xv.y, xv.z, xv.w};
        float p0 = 0.f, p1 = 0.f;
        #pragma unroll
        for (int i = 0; i < 4; i++) {
            p0 = fmaf(qt[r0 * 2][i],     xa[i], p0);
            p1 = fmaf(qt[r0 * 2 + 1][i], xa[i], p1);
        }
        #pragma unroll
        for (int off = 16; off >= 1; off >>= 1) {
            p0 += __shfl_xor_sync(0xffffffffu, p0, off);
            p1 += __shfl_xor_sync(0xffffffffu, p1, off);
        }
        float nu0 = fmaxf(p0 / SCALE2, 0.0f); nu0 = nu0 * nu0 + 1e-10f;
        float nu1 = fmaxf(p1 / SCALE2, 0.0f); nu1 = nu1 * nu1 + 1e-10f;
        den0 += nu0;
        den1 += nu1;
        if (r0 == 0) {
            #pragma unroll
            for (int i = 0; i < 4; i++) { y[0][0][i] += nu0 * xa[i]; y[0][1][i] += nu1 * xa[i]; }
        } else if (r0 == 1) {
            #pragma unroll
            for (int i = 0; i < 4; i++) { y[1][0][i] += nu0 * xa[i]; y[1][1][i] += nu1 * xa[i]; }
        } else {
            #pragma unroll
            for (int i = 0; i < 4; i++) { y[2][0][i] += nu0 * xa[i]; y[2][1][i] += nu1 * xa[i]; }
        }
    }

    float inv0 = (den0 > 0.0f) ? 1.0f / den0 : 0.0f;
    float inv1 = (den1 > 0.0f) ? 1.0f / den1 : 0.0f;

    // writeout: single fp16 limb, 4 halfs (8B) per (r,h) per lane
    #pragma unroll
    for (int r = 0; r < 3; r++)
        #pragma unroll
        for (int h = 0; h < 2; h++) {
            float sc = h ? inv1 : inv0;
            size_t off = (size_t)warp * YW + (r * 2 + h) * 128 + lane * 4;
            __half hv[4];
            #pragma unroll
            for (int i = 0; i < 4; i++)
                hv[i] = __float2half(y[r][h][i] * sc);
            *(uint2*)(g_yf + off) = *(uint2*)hv;
        }
}

// ---------------- launch ----------------
extern "C" void kernel_launch(void* const* d_in, const int* in_sizes, int n_in,
                              void* d_out, int out_size)
{
    const float* X   = (const float*)d_in[0];
    const float* WQ  = (const float*)d_in[1];
    const float* WK  = (const float*)d_in[2];
    const float* WV  = (const float*)d_in[3];
    const float* WO  = (const float*)d_in[4];
    const int*  esrc = (const int*)d_in[5];
    const int*  edst = (const int*)d_in[6];
    const int*  erel = (const int*)d_in[7];
    float* out = (float*)d_out;

    const int N = NN, E = EE;

    float* qt;
    cudaGetSymbolAddress((void**)&qt, g_qt);
    __half *xf, *wsch, *wscl, *wfh, *yf;
    cudaGetSymbolAddress((void**)&xf,   g_xf);
    cudaGetSymbolAddress((void**)&wsch, g_wsch);
    cudaGetSymbolAddress((void**)&wscl, g_wscl);
    cudaGetSymbolAddress((void**)&wfh,  g_wfh);
    cudaGetSymbolAddress((void**)&yf,   g_yf);

    // split-K partial buffers carved out of g_qt (dead after k_node)
    float* part0 = qt;
    float* part1 = qt + (size_t)MPAD * DD;

    const int GS_QT  = 3 * 3 * TILEB;   // 3 stages x (A,Bh,Bl)
    const int GS_FIN = 3 * 2 * TILEB;   // 3 stages x (A,Bh)
    cudaFuncSetAttribute(k_mma_gemm<DD, DD, false, true>,
                         cudaFuncAttributeMaxDynamicSharedMemorySize, GS_QT);
    cudaFuncSetAttribute(k_mma_gemm<YW, YW / 2, true, false>,
                         cudaFuncAttributeMaxDynamicSharedMemorySize, GS_FIN);

    // 1. merged prologue: x fp16 + y-pad zero + weight preprocessing (x256) + deg histogram
    k_prologue<<<PRO_BLKS, 256>>>(X, WQ, WK, WO, WV, edst);

    // 2. scan degrees -> rowptr (re-zeroes deg)
    k_scan<<<1, 1024>>>(N);

    // 3. scatter packed src|rel into CSR
    k_scatter<<<(E + 255) / 256, 256>>>(esrc, edst, erel, E);

    // 4. transformed-query GEMM: [MPAD,128] x [768,128]^T -> g_qt (values x256)
    {
        dim3 grid(YW / 128, MPAD / 128);
        k_mma_gemm<DD, DD, false, true><<<grid, 256, GS_QT>>>(xf, wsch, wscl, qt, nullptr, N, YW);
    }

    // 5. fused node pass (re-zeroes cursor): scores + denom + weighted-x agg -> yf
    k_node<<<(N + 7) / 8, 256>>>(X, N);

    // 6. final GEMM, split-K 2-way, single-limb Wfin: [MPAD,768] x [128,768]^T -> partials (x256)
    {
        dim3 grid(2, MPAD / 128);
        k_mma_gemm<YW, YW / 2, true, false><<<grid, 256, GS_FIN>>>(yf, wfh, nullptr, part0, part1, N, DD);
    }

    // 7. sum partials, scale by 1/256 -> out
    k_addout<<<(N * DD / 4 + 255) / 256, 256>>>(part0, part1, out, N * DD / 4);
}

// round 15
// speedup vs baseline: 1.7835x; 1.0566x over previous
#include <cuda_runtime.h>
#include <cuda_bf16.h>
#include <cuda_fp16.h>
#include <cstdint>

// Problem constants (fixed by the dataset)
#define NN    20000
#define MPAD  20096        // 157 * 128
#define EE    320000
#define DD    128
#define HD    256
#define YW    768          // 3 rel * 2 head * 128
#define SCALE 16.0f

// ---------------- scratch (device globals; no allocation) ----------------
__device__ float   g_qt[(size_t)NN * YW];        // fp32 transformed queries; reused as split-K partials
__device__ __half  g_xf[(size_t)MPAD * DD];      // x in fp16 (single limb)
__device__ __half  g_wsc[(size_t)YW * DD];       // Wsc = WK^T WQ blocks, fp16 [768,128]
__device__ __half  g_wf[(size_t)DD * YW];        // Wfin = WO x WV blocks, fp16 [128,768]
__device__ __half  g_yf[(size_t)MPAD * YW];      // weighted-x aggregate, fp16
__device__ int   g_deg[NN];        // zero at load; re-zeroed by k_scan each call
__device__ int   g_rowptr[NN + 1];
__device__ int   g_cursor[NN];     // zero at load; re-zeroed by k_node each call
__device__ int   g_pack[EE];       // CSR-ordered src | (rel<<15)

__device__ __forceinline__ uint32_t smem_u32(const void* p) {
    uint32_t a;
    asm("{ .reg .u64 t; cvta.to.shared.u64 t, %1; cvt.u32.u64 %0, t; }" : "=r"(a) : "l"(p));
    return a;
}
__device__ __forceinline__ void ldsm_x4(uint32_t& r0, uint32_t& r1, uint32_t& r2, uint32_t& r3,
                                        uint32_t addr) {
    asm volatile("ldmatrix.sync.aligned.m8n8.x4.shared.b16 {%0,%1,%2,%3}, [%4];"
                 : "=r"(r0), "=r"(r1), "=r"(r2), "=r"(r3) : "r"(addr));
}
__device__ __forceinline__ void mma_f16(float* d, const uint32_t* a, const uint32_t* b) {
    asm volatile(
        "mma.sync.aligned.m16n8k16.row.col.f32.f16.f16.f32 "
        "{%0,%1,%2,%3}, {%4,%5,%6,%7}, {%8,%9}, {%0,%1,%2,%3};"
        : "+f"(d[0]), "+f"(d[1]), "+f"(d[2]), "+f"(d[3])
        : "r"(a[0]), "r"(a[1]), "r"(a[2]), "r"(a[3]), "r"(b[0]), "r"(b[1]));
}
#define CP_ASYNC16(dst, src) \
    asm volatile("cp.async.cg.shared.global [%0], [%1], 16;\n" :: "r"(dst), "l"(src))
#define CP_COMMIT() asm volatile("cp.async.commit_group;\n" ::: "memory")
#define CP_WAIT(n)  asm volatile("cp.async.wait_group %0;\n" :: "n"(n) : "memory")

// ---------------- merged prologue: x fp16 | y-pad zero | weight pre | deg histogram ----------------
#define SPLIT_BLKS 10048
#define PAD_BLKS   288
#define WPRE_BLKS  768
#define DEG_BLKS   1250
#define PRO_BLKS   (SPLIT_BLKS + PAD_BLKS + WPRE_BLKS + DEG_BLKS)

__global__ __launch_bounds__(256)
void k_prologue(const float* __restrict__ X,
                const float* __restrict__ WQ, const float* __restrict__ WK,
                const float* __restrict__ WO, const float* __restrict__ WV,
                const int* __restrict__ edst)
{
    int blk = blockIdx.x;
    int t = threadIdx.x;

    if (blk < SPLIT_BLKS) {
        int i = blk * 256 + t;
        float x = (i < NN * DD) ? X[i] : 0.0f;
        g_xf[i] = __float2half(x);
        return;
    }
    blk -= SPLIT_BLKS;
    if (blk < PAD_BLKS) {
        int i = blk * 256 + t;     // < 73728
        g_yf[(size_t)NN * YW + i] = __float2half(0.0f);
        return;
    }
    blk -= PAD_BLKS;
    if (blk < WPRE_BLKS) {
        int idx = blk * 256 + t;          // < 196608
        int sec = idx >> 14;              // 0..11
        int row = (idx >> 7) & 127;
        int col = idx & 127;
        if (sec < 6) {
            int rh = sec, r = rh >> 1, h = rh & 1;
            int k = row, d2 = col;
            const float* wk = WK + (size_t)r * HD * DD + (size_t)(h * 128) * DD + k;
            const float* wq = WQ + (size_t)(h * 128) * DD + d2;
            float a0 = 0.f, a1 = 0.f, a2 = 0.f, a3 = 0.f;
            #pragma unroll
            for (int d = 0; d < 128; d += 4) {
                a0 = fmaf(wk[(size_t)(d + 0) * DD], wq[(size_t)(d + 0) * DD], a0);
                a1 = fmaf(wk[(size_t)(d + 1) * DD], wq[(size_t)(d + 1) * DD], a1);
                a2 = fmaf(wk[(size_t)(d + 2) * DD], wq[(size_t)(d + 2) * DD], a2);
                a3 = fmaf(wk[(size_t)(d + 3) * DD], wq[(size_t)(d + 3) * DD], a3);
            }
            float acc = (a0 + a1) + (a2 + a3);
            g_wsc[(size_t)(rh * 128 + k) * DD + d2] = __float2half(acc);
        } else {
            int rh = sec - 6, r = rh >> 1, h = rh & 1;
            int o = row, k = col;
            const float* wo = WO + o * HD + h * 128;
            const float* wv = WV + ((size_t)(r * HD + h * 128)) * DD + k;
            float a0 = 0.f, a1 = 0.f, a2 = 0.f, a3 = 0.f;
            #pragma unroll
            for (int d = 0; d < 128; d += 4) {
                a0 = fmaf(wo[d + 0], wv[(size_t)(d + 0) * DD], a0);
                a1 = fmaf(wo[d + 1], wv[(size_t)(d + 1) * DD], a1);
                a2 = fmaf(wo[d + 2], wv[(size_t)(d + 2) * DD], a2);
                a3 = fmaf(wo[d + 3], wv[(size_t)(d + 3) * DD], a3);
            }
            float acc = (a0 + a1) + (a2 + a3);
            g_wf[(size_t)o * YW + rh * 128 + k] = __float2half(acc);
        }
        return;
    }
    blk -= WPRE_BLKS;
    {
        int e = blk * 256 + t;
        if (e < EE) atomicAdd(&g_deg[edst[e]], 1);
    }
}

// ---------------- fast scan (also re-zeroes deg for the next replay) ----------------
__global__ __launch_bounds__(1024) void k_scan(int n)
{
    const int P = 20;
    __shared__ int wsum[32];
    int tid = threadIdx.x, lane = tid & 31, wid = tid >> 5;
    int base = tid * P;
    int v[P];
    int s = 0;
    #pragma unroll
    for (int i = 0; i < P; i++) {
        int idx = base + i;
        int d = (idx < n) ? g_deg[idx] : 0;
        if (idx < n) g_deg[idx] = 0;   // self-clean for next graph replay
        s += d;
        v[i] = s;
    }
    int x = s;
    #pragma unroll
    for (int off = 1; off < 32; off <<= 1) {
        int t = __shfl_up_sync(0xffffffffu, x, off);
        if (lane >= off) x += t;
    }
    if (lane == 31) wsum[wid] = x;
    __syncthreads();
    if (wid == 0) {
        int y = wsum[lane];
        #pragma unroll
        for (int off = 1; off < 32; off <<= 1) {
            int t = __shfl_up_sync(0xffffffffu, y, off);
            if (lane >= off) y += t;
        }
        wsum[lane] = y;
    }
    __syncthreads();
    int offset = (wid ? wsum[wid - 1] : 0) + x - s;
    if (tid == 0) g_rowptr[0] = 0;
    #pragma unroll
    for (int i = 0; i < P; i++) {
        int idx = base + i;
        if (idx < n) g_rowptr[idx + 1] = offset + v[i];
    }
}

// ---------------- scatter packed src|rel into CSR ----------------
__global__ void k_scatter(const int* __restrict__ esrc, const int* __restrict__ edst,
                          const int* __restrict__ erel, int E)
{
    int e = blockIdx.x * blockDim.x + threadIdx.x;
    if (e >= E) return;
    int dst = edst[e];
    int pos = atomicAdd(&g_cursor[dst], 1);
    g_pack[g_rowptr[dst] + pos] = esrc[e] | (erel[e] << 15);
}

// ---------------- mma.sync GEMM: fp16 single-limb A and B, 3-stage cp.async pipeline ----------------
#define SSTR   40
#define TILEB  10240
#define SMSTAGE (2 * TILEB)        // A, B
#define GSMEM   (3 * SMSTAGE)      // 61440 B

template <int KSTR, int KLEN, bool SPLITK>
__global__ __launch_bounds__(256)
void k_mma_gemm(const __half* __restrict__ A, const __half* __restrict__ B,
                float* __restrict__ C0, float* __restrict__ C1, int Mreal, int ldc)
{
    extern __shared__ uint8_t dsm[];
    const uint32_t sb = smem_u32(dsm);
    const int tid  = threadIdx.x;
    const int wid  = tid >> 5;
    const int lane = tid & 31;
    const int m0 = blockIdx.y * 128;
    const int j0 = SPLITK ? 0 : blockIdx.x * 128;
    const int koff = SPLITK ? blockIdx.x * KLEN : 0;
    float* C = (SPLITK && blockIdx.x) ? C1 : C0;
    const int warp_m = (wid & 3) * 32;
    const int warp_n = (wid >> 2) * 64;

    const int ar = lane & 15;
    const int kh = (lane >> 4) << 3;

    float acc[2][8][4];
    #pragma unroll
    for (int i = 0; i < 2; i++)
        #pragma unroll
        for (int j = 0; j < 8; j++)
            #pragma unroll
            for (int q = 0; q < 4; q++) acc[i][j][q] = 0.0f;

    int rowA[2], c8A[2];
    #pragma unroll
    for (int i = 0; i < 2; i++) {
        int v = tid + i * 256;
        rowA[i] = v >> 2;
        c8A[i] = (v & 3) << 3;
    }

    auto prefetch = [&](int ch) {
        uint32_t base = sb + (uint32_t)(ch % 3) * SMSTAGE;
        int kt = ch * 32;
        #pragma unroll
        for (int i = 0; i < 2; i++) {
            int row = rowA[i], c8 = c8A[i];
            uint32_t so = base + (uint32_t)(row * SSTR + c8) * 2;
            size_t ga = (size_t)(m0 + row) * KSTR + koff + kt + c8;
            size_t gb = (size_t)(j0 + row) * KSTR + koff + kt + c8;
            CP_ASYNC16(so,         A + ga);
            CP_ASYNC16(so + TILEB, B + gb);
        }
        CP_COMMIT();
    };

    constexpr int NCH = KLEN / 32;
    prefetch(0);
    if (NCH > 1) prefetch(1);

    for (int ch = 0; ch < NCH; ch++) {
        if (ch == NCH - 1) { CP_WAIT(0); } else { CP_WAIT(1); }
        __syncthreads();
        if (ch + 2 < NCH) prefetch(ch + 2);

        uint32_t base = sb + (uint32_t)(ch % 3) * SMSTAGE;
        #pragma unroll
        for (int k16 = 0; k16 < 2; k16++) {
            uint32_t kb = (uint32_t)((k16 * 16 + kh) * 2);

            uint32_t a[2][4];
            #pragma unroll
            for (int mi = 0; mi < 2; mi++) {
                uint32_t off = (uint32_t)((warp_m + mi * 16 + ar) * SSTR * 2) + kb;
                ldsm_x4(a[mi][0], a[mi][1], a[mi][2], a[mi][3], base + off);
            }
            uint32_t b[8][2];
            #pragma unroll
            for (int ng = 0; ng < 4; ng++) {
                uint32_t off = (uint32_t)((warp_n + ng * 16 + ar) * SSTR * 2) + kb;
                uint32_t r0, r1, r2, r3;
                ldsm_x4(r0, r1, r2, r3, base + TILEB + off);
                b[ng * 2][0] = r0;     b[ng * 2][1] = r2;
                b[ng * 2 + 1][0] = r1; b[ng * 2 + 1][1] = r3;
            }
            #pragma unroll
            for (int mi = 0; mi < 2; mi++)
                #pragma unroll
                for (int nj = 0; nj < 8; nj++)
                    mma_f16(acc[mi][nj], a[mi], b[nj]);
        }
        // no trailing sync: stage rewrite happens >=2 barriers later
    }

    const int rg = lane >> 2;
    const int tg = lane & 3;
    #pragma unroll
    for (int mi = 0; mi < 2; mi++) {
        int r0 = m0 + warp_m + mi * 16 + rg;
        int r1 = r0 + 8;
        #pragma unroll
        for (int nj = 0; nj < 8; nj++) {
            int col = j0 + warp_n + nj * 8 + tg * 2;
            if (r0 < Mreal) {
                float2 v = {acc[mi][nj][0], acc[mi][nj][1]};
                *(float2*)(C + (size_t)r0 * ldc + col) = v;
            }
            if (r1 < Mreal) {
                float2 v = {acc[mi][nj][2], acc[mi][nj][3]};
                *(float2*)(C + (size_t)r1 * ldc + col) = v;
            }
        }
    }
}

// ---------------- split-K partial sum -> out ----------------
__global__ void k_addout(const float* __restrict__ p0, const float* __restrict__ p1,
                         float* __restrict__ out, int n4)
{
    int i = blockIdx.x * blockDim.x + threadIdx.x;
    if (i >= n4) return;
    float4 a = ((const float4*)p0)[i];
    float4 b = ((const float4*)p1)[i];
    float4 v = {a.x + b.x, a.y + b.y, a.z + b.z, a.w + b.w};
    ((float4*)out)[i] = v;
}

// ---------------- fused node kernel (R7-proven loop; re-zeroes cursor) ----------------
__global__ __launch_bounds__(256)
void k_node(const float* __restrict__ X, int N)
{
    int warp = (blockIdx.x * blockDim.x + threadIdx.x) >> 5;
    int lane = threadIdx.x & 31;
    if (warp >= N) return;

    if (lane == 0) g_cursor[warp] = 0;   // self-clean for next graph replay

    const int start = g_rowptr[warp];
    const int end   = g_rowptr[warp + 1];

    float qt[6][4];
    {
        const float* qr = g_qt + (size_t)warp * YW;
        #pragma unroll
        for (int c = 0; c < 6; c++) {
            float4 v = *(const float4*)(qr + c * 128 + lane * 4);
            qt[c][0] = v.x; qt[c][1] = v.y; qt[c][2] = v.z; qt[c][3] = v.w;
        }
    }

    float y[3][2][4];
    #pragma unroll
    for (int r = 0; r < 3; r++)
        #pragma unroll
        for (int h = 0; h < 2; h++)
            #pragma unroll
            for (int i = 0; i < 4; i++) y[r][h][i] = 0.0f;

    float den0 = 0.0f, den1 = 0.0f;

    int j = start;
    int pk0 = (j < end)     ? g_pack[j]     : 0;
    int pk1 = (j + 1 < end) ? g_pack[j + 1] : 0;

    while (j + 1 < end) {
        int s0 = pk0 & 0x7FFF, r0 = pk0 >> 15;
        int s1 = pk1 & 0x7FFF, r1 = pk1 >> 15;
        int nj = j + 2;
        int npk0 = (nj < end)     ? g_pack[nj]     : 0;
        int npk1 = (nj + 1 < end) ? g_pack[nj + 1] : 0;

        float4 xv0 = *(const float4*)(X + (size_t)s0 * DD + lane * 4);
        float4 xv1 = *(const float4*)(X + (size_t)s1 * DD + lane * 4);
        float xa0[4] = {xv0.x, xv0.y, xv0.z, xv0.w};
        float xa1[4] = {xv1.x, xv1.y, xv1.z, xv1.w};

        float p00 = 0.f, p01 = 0.f, p10 = 0.f, p11 = 0.f;
        #pragma unroll
        for (int i = 0; i < 4; i++) {
            p00 = fmaf(qt[r0 * 2][i],     xa0[i], p00);
            p01 = fmaf(qt[r0 * 2 + 1][i], xa0[i], p01);
            p10 = fmaf(qt[r1 * 2][i],     xa1[i], p10);
            p11 = fmaf(qt[r1 * 2 + 1][i], xa1[i], p11);
        }
        #pragma unroll
        for (int off = 16; off >= 1; off >>= 1) {
            p00 += __shfl_xor_sync(0xffffffffu, p00, off);
            p01 += __shfl_xor_sync(0xffffffffu, p01, off);
            p10 += __shfl_xor_sync(0xffffffffu, p10, off);
            p11 += __shfl_xor_sync(0xffffffffu, p11, off);
        }
        float nuA0 = fmaxf(p00 / SCALE, 0.0f); nuA0 = nuA0 * nuA0 + 1e-10f;
        float nuA1 = fmaxf(p01 / SCALE, 0.0f); nuA1 = nuA1 * nuA1 + 1e-10f;
        float nuB0 = fmaxf(p10 / SCALE, 0.0f); nuB0 = nuB0 * nuB0 + 1e-10f;
        float nuB1 = fmaxf(p11 / SCALE, 0.0f); nuB1 = nuB1 * nuB1 + 1e-10f;
        den0 += nuA0 + nuB0;
        den1 += nuA1 + nuB1;

        if (r0 == 0) {
            #pragma unroll
            for (int i = 0; i < 4; i++) { y[0][0][i] += nuA0 * xa0[i]; y[0][1][i] += nuA1 * xa0[i]; }
        } else if (r0 == 1) {
            #pragma unroll
            for (int i = 0; i < 4; i++) { y[1][0][i] += nuA0 * xa0[i]; y[1][1][i] += nuA1 * xa0[i]; }
        } else {
            #pragma unroll
            for (int i = 0; i < 4; i++) { y[2][0][i] += nuA0 * xa0[i]; y[2][1][i] += nuA1 * xa0[i]; }
        }
        if (r1 == 0) {
            #pragma unroll
            for (int i = 0; i < 4; i++) { y[0][0][i] += nuB0 * xa1[i]; y[0][1][i] += nuB1 * xa1[i]; }
        } else if (r1 == 1) {
            #pragma unroll
            for (int i = 0; i < 4; i++) { y[1][0][i] += nuB0 * xa1[i]; y[1][1][i] += nuB1 * xa1[i]; }
        } else {
            #pragma unroll
            for (int i = 0; i < 4; i++) { y[2][0][i] += nuB0 * xa1[i]; y[2][1][i] += nuB1 * xa1[i]; }
        }

        j = nj; pk0 = npk0; pk1 = npk1;
    }

    if (j < end) {
        int s0 = pk0 & 0x7FFF, r0 = pk0 >> 15;
        float4 xv = *(const float4*)(X + (size_t)s0 * DD + lane * 4);
        float xa[4] = {xv.x, xv.y, xv.z, xv.w};
        float p0 = 0.f, p1 = 0.f;
        #pragma unroll
        for (int i = 0; i < 4; i++) {
            p0 = fmaf(qt[r0 * 2][i],     xa[i], p0);
            p1 = fmaf(qt[r0 * 2 + 1][i], xa[i], p1);
        }
        #pragma unroll
        for (int off = 16; off >= 1; off >>= 1) {
            p0 += __shfl_xor_sync(0xffffffffu, p0, off);
            p1 += __shfl_xor_sync(0xffffffffu, p1, off);
        }
        float nu0 = fmaxf(p0 / SCALE, 0.0f); nu0 = nu0 * nu0 + 1e-10f;
        float nu1 = fmaxf(p1 / SCALE, 0.0f); nu1 = nu1 * nu1 + 1e-10f;
        den0 += nu0;
        den1 += nu1;
        if (r0 == 0) {
            #pragma unroll
            for (int i = 0; i < 4; i++) { y[0][0][i] += nu0 * xa[i]; y[0][1][i] += nu1 * xa[i]; }
        } else if (r0 == 1) {
            #pragma unroll
            for (int i = 0; i < 4; i++) { y[1][0][i] += nu0 * xa[i]; y[1][1][i] += nu1 * xa[i]; }
        } else {
            #pragma unroll
            for (int i = 0; i < 4; i++) { y[2][0][i] += nu0 * xa[i]; y[2][1][i] += nu1 * xa[i]; }
        }
    }

    float inv0 = (den0 > 0.0f) ? 1.0f / den0 : 0.0f;
    float inv1 = (den1 > 0.0f) ? 1.0f / den1 : 0.0f;

    // writeout: single fp16 limb, 4 halfs (8B) per (r,h) per lane
    #pragma unroll
    for (int r = 0; r < 3; r++)
        #pragma unroll
        for (int h = 0; h < 2; h++) {
            float sc = h ? inv1 : inv0;
            size_t off = (size_t)warp * YW + (r * 2 + h) * 128 + lane * 4;
            __half hv[4];
            #pragma unroll
            for (int i = 0; i < 4; i++)
                hv[i] = __float2half(y[r][h][i] * sc);
            *(uint2*)(g_yf + off) = *(uint2*)hv;
        }
}

// ---------------- launch ----------------
extern "C" void kernel_launch(void* const* d_in, const int* in_sizes, int n_in,
                              void* d_out, int out_size)
{
    const float* X   = (const float*)d_in[0];
    const float* WQ  = (const float*)d_in[1];
    const float* WK  = (const float*)d_in[2];
    const float* WV  = (const float*)d_in[3];
    const float* WO  = (const float*)d_in[4];
    const int*  esrc = (const int*)d_in[5];
    const int*  edst = (const int*)d_in[6];
    const int*  erel = (const int*)d_in[7];
    float* out = (float*)d_out;

    const int N = NN, E = EE;

    float* qt;
    cudaGetSymbolAddress((void**)&qt, g_qt);
    __half *xf, *wsc, *wf, *yf;
    cudaGetSymbolAddress((void**)&xf,  g_xf);
    cudaGetSymbolAddress((void**)&wsc, g_wsc);
    cudaGetSymbolAddress((void**)&wf,  g_wf);
    cudaGetSymbolAddress((void**)&yf,  g_yf);

    // split-K partial buffers carved out of g_qt (dead after k_node)
    float* part0 = qt;
    float* part1 = qt + (size_t)MPAD * DD;

    cudaFuncSetAttribute(k_mma_gemm<DD, DD, false>,
                         cudaFuncAttributeMaxDynamicSharedMemorySize, GSMEM);
    cudaFuncSetAttribute(k_mma_gemm<YW, YW / 2, true>,
                         cudaFuncAttributeMaxDynamicSharedMemorySize, GSMEM);

    // 1. merged prologue: x fp16 + y-pad zero + weight preprocessing + deg histogram
    k_prologue<<<PRO_BLKS, 256>>>(X, WQ, WK, WO, WV, edst);

    // 2. scan degrees -> rowptr (re-zeroes deg)
    k_scan<<<1, 1024>>>(N);

    // 3. scatter packed src|rel into CSR
    k_scatter<<<(E + 255) / 256, 256>>>(esrc, edst, erel, E);

    // 4. transformed-query GEMM: [MPAD,128] x [768,128]^T -> g_qt
    {
        dim3 grid(YW / 128, MPAD / 128);
        k_mma_gemm<DD, DD, false><<<grid, 256, GSMEM>>>(xf, wsc, qt, nullptr, N, YW);
    }

    // 5. fused node pass (re-zeroes cursor): scores + denom + weighted-x agg -> yf
    k_node<<<(N + 7) / 8, 256>>>(X, N);

    // 6. final GEMM, split-K 2-way: [MPAD,768] x [128,768]^T -> partials
    {
        dim3 grid(2, MPAD / 128);
        k_mma_gemm<YW, YW / 2, true><<<grid, 256, GSMEM>>>(yf, wf, part0, part1, N, DD);
    }

    // 7. sum partials -> out
    k_addout<<<(N * DD / 4 + 255) / 256, 256>>>(part0, part1, out, N * DD / 4);
}

// round 16
// speedup vs baseline: 1.8148x; 1.0175x over previous
#include <cuda_runtime.h>
#include <cuda_bf16.h>
#include <cuda_fp16.h>
#include <cstdint>

// Problem constants (fixed by the dataset)
#define NN    20000
#define MPAD  20096        // 157 * 128
#define EE    320000
#define DD    128
#define HD    256
#define YW    768          // 3 rel * 2 head * 128
#define SCALE 16.0f

// ---------------- scratch (device globals; no allocation) ----------------
__device__ float   g_qt[(size_t)NN * YW];        // fp32 transformed queries; reused as split-K partials
__device__ __half  g_xf[(size_t)MPAD * DD];      // x in fp16
__device__ __half  g_wsc[(size_t)YW * DD];       // Wsc = WK^T WQ blocks, fp16 [768,128]
__device__ __half  g_wf[(size_t)DD * YW];        // Wfin = WO x WV blocks, fp16 [128,768]
__device__ __half  g_yf[(size_t)MPAD * YW];      // weighted-x aggregate, fp16
__device__ int   g_deg[NN];        // zero at load; re-zeroed by k_scan each call
__device__ int   g_rowptr[NN + 1];
__device__ int   g_cursor[NN];     // zero at load; re-zeroed by k_node each call
__device__ int   g_pack[EE];       // CSR-ordered src | (rel<<15)

__device__ __forceinline__ uint32_t smem_u32(const void* p) {
    uint32_t a;
    asm("{ .reg .u64 t; cvta.to.shared.u64 t, %1; cvt.u32.u64 %0, t; }" : "=r"(a) : "l"(p));
    return a;
}
__device__ __forceinline__ void ldsm_x4(uint32_t& r0, uint32_t& r1, uint32_t& r2, uint32_t& r3,
                                        uint32_t addr) {
    asm volatile("ldmatrix.sync.aligned.m8n8.x4.shared.b16 {%0,%1,%2,%3}, [%4];"
                 : "=r"(r0), "=r"(r1), "=r"(r2), "=r"(r3) : "r"(addr));
}
__device__ __forceinline__ void mma_f16(float* d, const uint32_t* a, const uint32_t* b) {
    asm volatile(
        "mma.sync.aligned.m16n8k16.row.col.f32.f16.f16.f32 "
        "{%0,%1,%2,%3}, {%4,%5,%6,%7}, {%8,%9}, {%0,%1,%2,%3};"
        : "+f"(d[0]), "+f"(d[1]), "+f"(d[2]), "+f"(d[3])
        : "r"(a[0]), "r"(a[1]), "r"(a[2]), "r"(a[3]), "r"(b[0]), "r"(b[1]));
}
#define CP_ASYNC16(dst, src) \
    asm volatile("cp.async.cg.shared.global [%0], [%1], 16;\n" :: "r"(dst), "l"(src))
#define CP_COMMIT() asm volatile("cp.async.commit_group;\n" ::: "memory")
#define CP_WAIT(n)  asm volatile("cp.async.wait_group %0;\n" :: "n"(n) : "memory")

// ---------------- merged prologue: x fp16 | y-pad zero | weight pre | deg histogram ----------------
#define SPLIT_BLKS 10048
#define PAD_BLKS   288
#define WPRE_BLKS  768
#define DEG_BLKS   1250
#define PRO_BLKS   (SPLIT_BLKS + PAD_BLKS + WPRE_BLKS + DEG_BLKS)

__global__ __launch_bounds__(256)
void k_prologue(const float* __restrict__ X,
                const float* __restrict__ WQ, const float* __restrict__ WK,
                const float* __restrict__ WO, const float* __restrict__ WV,
                const int* __restrict__ edst)
{
    int blk = blockIdx.x;
    int t = threadIdx.x;

    if (blk < SPLIT_BLKS) {
        int i = blk * 256 + t;
        float x = (i < NN * DD) ? X[i] : 0.0f;
        g_xf[i] = __float2half(x);
        return;
    }
    blk -= SPLIT_BLKS;
    if (blk < PAD_BLKS) {
        int i = blk * 256 + t;     // < 73728
        g_yf[(size_t)NN * YW + i] = __float2half(0.0f);
        return;
    }
    blk -= PAD_BLKS;
    if (blk < WPRE_BLKS) {
        int idx = blk * 256 + t;          // < 196608
        int sec = idx >> 14;              // 0..11
        int row = (idx >> 7) & 127;
        int col = idx & 127;
        if (sec < 6) {
            int rh = sec, r = rh >> 1, h = rh & 1;
            int k = row, d2 = col;
            const float* wk = WK + (size_t)r * HD * DD + (size_t)(h * 128) * DD + k;
            const float* wq = WQ + (size_t)(h * 128) * DD + d2;
            float a0 = 0.f, a1 = 0.f, a2 = 0.f, a3 = 0.f;
            #pragma unroll
            for (int d = 0; d < 128; d += 4) {
                a0 = fmaf(wk[(size_t)(d + 0) * DD], wq[(size_t)(d + 0) * DD], a0);
                a1 = fmaf(wk[(size_t)(d + 1) * DD], wq[(size_t)(d + 1) * DD], a1);
                a2 = fmaf(wk[(size_t)(d + 2) * DD], wq[(size_t)(d + 2) * DD], a2);
                a3 = fmaf(wk[(size_t)(d + 3) * DD], wq[(size_t)(d + 3) * DD], a3);
            }
            float acc = (a0 + a1) + (a2 + a3);
            g_wsc[(size_t)(rh * 128 + k) * DD + d2] = __float2half(acc);
        } else {
            int rh = sec - 6, r = rh >> 1, h = rh & 1;
            int o = row, k = col;
            const float* wo = WO + o * HD + h * 128;
            const float* wv = WV + ((size_t)(r * HD + h * 128)) * DD + k;
            float a0 = 0.f, a1 = 0.f, a2 = 0.f, a3 = 0.f;
            #pragma unroll
            for (int d = 0; d < 128; d += 4) {
                a0 = fmaf(wo[d + 0], wv[(size_t)(d + 0) * DD], a0);
                a1 = fmaf(wo[d + 1], wv[(size_t)(d + 1) * DD], a1);
                a2 = fmaf(wo[d + 2], wv[(size_t)(d + 2) * DD], a2);
                a3 = fmaf(wo[d + 3], wv[(size_t)(d + 3) * DD], a3);
            }
            float acc = (a0 + a1) + (a2 + a3);
            g_wf[(size_t)o * YW + rh * 128 + k] = __float2half(acc);
        }
        return;
    }
    blk -= WPRE_BLKS;
    {
        int e = blk * 256 + t;
        if (e < EE) atomicAdd(&g_deg[edst[e]], 1);
    }
}

// ---------------- fast scan (also re-zeroes deg for the next replay) ----------------
__global__ __launch_bounds__(1024) void k_scan(int n)
{
    const int P = 20;
    __shared__ int wsum[32];
    int tid = threadIdx.x, lane = tid & 31, wid = tid >> 5;
    int base = tid * P;
    int v[P];
    int s = 0;
    #pragma unroll
    for (int i = 0; i < P; i++) {
        int idx = base + i;
        int d = (idx < n) ? g_deg[idx] : 0;
        if (idx < n) g_deg[idx] = 0;   // self-clean for next graph replay
        s += d;
        v[i] = s;
    }
    int x = s;
    #pragma unroll
    for (int off = 1; off < 32; off <<= 1) {
        int t = __shfl_up_sync(0xffffffffu, x, off);
        if (lane >= off) x += t;
    }
    if (lane == 31) wsum[wid] = x;
    __syncthreads();
    if (wid == 0) {
        int y = wsum[lane];
        #pragma unroll
        for (int off = 1; off < 32; off <<= 1) {
            int t = __shfl_up_sync(0xffffffffu, y, off);
            if (lane >= off) y += t;
        }
        wsum[lane] = y;
    }
    __syncthreads();
    int offset = (wid ? wsum[wid - 1] : 0) + x - s;
    if (tid == 0) g_rowptr[0] = 0;
    #pragma unroll
    for (int i = 0; i < P; i++) {
        int idx = base + i;
        if (idx < n) g_rowptr[idx + 1] = offset + v[i];
    }
}

// ---------------- mma.sync GEMM: fp16, 4-stage cp.async pipeline ----------------
// FSCAT: the first SC_BY rows of blockIdx.y do the CSR scatter instead (overlapped;
// scheduled FIRST so they run concurrently with early GEMM tiles).
#define SSTR   40
#define TILEB  10240
#define SMSTAGE (2 * TILEB)        // A, B
#define GSMEM   (4 * SMSTAGE)      // 81920 B
#define SC_BY   50                 // 50 * gridDim.x(6) = 300 scatter blocks

template <int KSTR, int KLEN, bool SPLITK, bool FSCAT>
__global__ __launch_bounds__(256)
void k_mma_gemm(const __half* __restrict__ A, const __half* __restrict__ B,
                float* __restrict__ C0, float* __restrict__ C1, int Mreal, int ldc,
                const int* __restrict__ esrc, const int* __restrict__ edst,
                const int* __restrict__ erel)
{
    if (FSCAT && blockIdx.y < SC_BY) {
        // fused CSR scatter (independent of the GEMM; overlaps with it)
        int nthr = SC_BY * gridDim.x * 256;
        int idx = (blockIdx.y * gridDim.x + blockIdx.x) * 256 + threadIdx.x;
        for (int e = idx; e < EE; e += nthr) {
            int dst = edst[e];
            int pos = atomicAdd(&g_cursor[dst], 1);
            g_pack[g_rowptr[dst] + pos] = esrc[e] | (erel[e] << 15);
        }
        return;
    }

    extern __shared__ uint8_t dsm[];
    const uint32_t sb = smem_u32(dsm);
    const int tid  = threadIdx.x;
    const int wid  = tid >> 5;
    const int lane = tid & 31;
    const int by = FSCAT ? (blockIdx.y - SC_BY) : blockIdx.y;
    const int m0 = by * 128;
    const int j0 = SPLITK ? 0 : blockIdx.x * 128;
    const int koff = SPLITK ? blockIdx.x * KLEN : 0;
    float* C = (SPLITK && blockIdx.x) ? C1 : C0;
    const int warp_m = (wid & 3) * 32;
    const int warp_n = (wid >> 2) * 64;

    const int ar = lane & 15;
    const int kh = (lane >> 4) << 3;

    float acc[2][8][4];
    #pragma unroll
    for (int i = 0; i < 2; i++)
        #pragma unroll
        for (int j = 0; j < 8; j++)
            #pragma unroll
            for (int q = 0; q < 4; q++) acc[i][j][q] = 0.0f;

    int rowA[2], c8A[2];
    #pragma unroll
    for (int i = 0; i < 2; i++) {
        int v = tid + i * 256;
        rowA[i] = v >> 2;
        c8A[i] = (v & 3) << 3;
    }

    auto prefetch = [&](int ch) {
        uint32_t base = sb + (uint32_t)(ch & 3) * SMSTAGE;
        int kt = ch * 32;
        #pragma unroll
        for (int i = 0; i < 2; i++) {
            int row = rowA[i], c8 = c8A[i];
            uint32_t so = base + (uint32_t)(row * SSTR + c8) * 2;
            size_t ga = (size_t)(m0 + row) * KSTR + koff + kt + c8;
            size_t gb = (size_t)(j0 + row) * KSTR + koff + kt + c8;
            CP_ASYNC16(so,         A + ga);
            CP_ASYNC16(so + TILEB, B + gb);
        }
        CP_COMMIT();
    };

    constexpr int NCH = KLEN / 32;
    prefetch(0);
    if (NCH > 1) prefetch(1);
    if (NCH > 2) prefetch(2);

    for (int ch = 0; ch < NCH; ch++) {
        if (ch >= NCH - 1)      { CP_WAIT(0); }
        else if (ch == NCH - 2) { CP_WAIT(1); }
        else                    { CP_WAIT(2); }
        __syncthreads();
        if (ch + 3 < NCH) prefetch(ch + 3);

        uint32_t base = sb + (uint32_t)(ch & 3) * SMSTAGE;
        #pragma unroll
        for (int k16 = 0; k16 < 2; k16++) {
            uint32_t kb = (uint32_t)((k16 * 16 + kh) * 2);

            uint32_t a[2][4];
            #pragma unroll
            for (int mi = 0; mi < 2; mi++) {
                uint32_t off = (uint32_t)((warp_m + mi * 16 + ar) * SSTR * 2) + kb;
                ldsm_x4(a[mi][0], a[mi][1], a[mi][2], a[mi][3], base + off);
            }
            uint32_t b[8][2];
            #pragma unroll
            for (int ng = 0; ng < 4; ng++) {
                uint32_t off = (uint32_t)((warp_n + ng * 16 + ar) * SSTR * 2) + kb;
                uint32_t r0, r1, r2, r3;
                ldsm_x4(r0, r1, r2, r3, base + TILEB + off);
                b[ng * 2][0] = r0;     b[ng * 2][1] = r2;
                b[ng * 2 + 1][0] = r1; b[ng * 2 + 1][1] = r3;
            }
            #pragma unroll
            for (int mi = 0; mi < 2; mi++)
                #pragma unroll
                for (int nj = 0; nj < 8; nj++)
                    mma_f16(acc[mi][nj], a[mi], b[nj]);
        }
        // no trailing sync: stage rewrite happens >=3 barriers later
    }

    const int rg = lane >> 2;
    const int tg = lane & 3;
    #pragma unroll
    for (int mi = 0; mi < 2; mi++) {
        int r0 = m0 + warp_m + mi * 16 + rg;
        int r1 = r0 + 8;
        #pragma unroll
        for (int nj = 0; nj < 8; nj++) {
            int col = j0 + warp_n + nj * 8 + tg * 2;
            if (r0 < Mreal) {
                float2 v = {acc[mi][nj][0], acc[mi][nj][1]};
                *(float2*)(C + (size_t)r0 * ldc + col) = v;
            }
            if (r1 < Mreal) {
                float2 v = {acc[mi][nj][2], acc[mi][nj][3]};
                *(float2*)(C + (size_t)r1 * ldc + col) = v;
            }
        }
    }
}

// ---------------- split-K partial sum -> out ----------------
__global__ void k_addout(const float* __restrict__ p0, const float* __restrict__ p1,
                         float* __restrict__ out, int n4)
{
    int i = blockIdx.x * blockDim.x + threadIdx.x;
    if (i >= n4) return;
    float4 a = ((const float4*)p0)[i];
    float4 b = ((const float4*)p1)[i];
    float4 v = {a.x + b.x, a.y + b.y, a.z + b.z, a.w + b.w};
    ((float4*)out)[i] = v;
}

// ---------------- fused node kernel (R7-proven loop; re-zeroes cursor) ----------------
__global__ __launch_bounds__(256)
void k_node(const float* __restrict__ X, int N)
{
    int warp = (blockIdx.x * blockDim.x + threadIdx.x) >> 5;
    int lane = threadIdx.x & 31;
    if (warp >= N) return;

    if (lane == 0) g_cursor[warp] = 0;   // self-clean for next graph replay

    const int start = g_rowptr[warp];
    const int end   = g_rowptr[warp + 1];

    float qt[6][4];
    {
        const float* qr = g_qt + (size_t)warp * YW;
        #pragma unroll
        for (int c = 0; c < 6; c++) {
            float4 v = *(const float4*)(qr + c * 128 + lane * 4);
            qt[c][0] = v.x; qt[c][1] = v.y; qt[c][2] = v.z; qt[c][3] = v.w;
        }
    }

    float y[3][2][4];
    #pragma unroll
    for (int r = 0; r < 3; r++)
        #pragma unroll
        for (int h = 0; h < 2; h++)
            #pragma unroll
            for (int i = 0; i < 4; i++) y[r][h][i] = 0.0f;

    float den0 = 0.0f, den1 = 0.0f;

    int j = start;
    int pk0 = (j < end)     ? g_pack[j]     : 0;
    int pk1 = (j + 1 < end) ? g_pack[j + 1] : 0;

    while (j + 1 < end) {
        int s0 = pk0 & 0x7FFF, r0 = pk0 >> 15;
        int s1 = pk1 & 0x7FFF, r1 = pk1 >> 15;
        int nj = j + 2;
        int npk0 = (nj < end)     ? g_pack[nj]     : 0;
        int npk1 = (nj + 1 < end) ? g_pack[nj + 1] : 0;

        float4 xv0 = *(const float4*)(X + (size_t)s0 * DD + lane * 4);
        float4 xv1 = *(const float4*)(X + (size_t)s1 * DD + lane * 4);
        float xa0[4] = {xv0.x, xv0.y, xv0.z, xv0.w};
        float xa1[4] = {xv1.x, xv1.y, xv1.z, xv1.w};

        float p00 = 0.f, p01 = 0.f, p10 = 0.f, p11 = 0.f;
        #pragma unroll
        for (int i = 0; i < 4; i++) {
            p00 = fmaf(qt[r0 * 2][i],     xa0[i], p00);
            p01 = fmaf(qt[r0 * 2 + 1][i], xa0[i], p01);
            p10 = fmaf(qt[r1 * 2][i],     xa1[i], p10);
            p11 = fmaf(qt[r1 * 2 + 1][i], xa1[i], p11);
        }
        #pragma unroll
        for (int off = 16; off >= 1; off >>= 1) {
            p00 += __shfl_xor_sync(0xffffffffu, p00, off);
            p01 += __shfl_xor_sync(0xffffffffu, p01, off);
            p10 += __shfl_xor_sync(0xffffffffu, p10, off);
            p11 += __shfl_xor_sync(0xffffffffu, p11, off);
        }
        float nuA0 = fmaxf(p00 / SCALE, 0.0f); nuA0 = nuA0 * nuA0 + 1e-10f;
        float nuA1 = fmaxf(p01 / SCALE, 0.0f); nuA1 = nuA1 * nuA1 + 1e-10f;
        float nuB0 = fmaxf(p10 / SCALE, 0.0f); nuB0 = nuB0 * nuB0 + 1e-10f;
        float nuB1 = fmaxf(p11 / SCALE, 0.0f); nuB1 = nuB1 * nuB1 + 1e-10f;
        den0 += nuA0 + nuB0;
        den1 += nuA1 + nuB1;

        if (r0 == 0) {
            #pragma unroll
            for (int i = 0; i < 4; i++) { y[0][0][i] += nuA0 * xa0[i]; y[0][1][i] += nuA1 * xa0[i]; }
        } else if (r0 == 1) {
            #pragma unroll
            for (int i = 0; i < 4; i++) { y[1][0][i] += nuA0 * xa0[i]; y[1][1][i] += nuA1 * xa0[i]; }
        } else {
            #pragma unroll
            for (int i = 0; i < 4; i++) { y[2][0][i] += nuA0 * xa0[i]; y[2][1][i] += nuA1 * xa0[i]; }
        }
        if (r1 == 0) {
            #pragma unroll
            for (int i = 0; i < 4; i++) { y[0][0][i] += nuB0 * xa1[i]; y[0][1][i] += nuB1 * xa1[i]; }
        } else if (r1 == 1) {
            #pragma unroll
            for (int i = 0; i < 4; i++) { y[1][0][i] += nuB0 * xa1[i]; y[1][1][i] += nuB1 * xa1[i]; }
        } else {
            #pragma unroll
            for (int i = 0; i < 4; i++) { y[2][0][i] += nuB0 * xa1[i]; y[2][1][i] += nuB1 * xa1[i]; }
        }

        j = nj; pk0 = npk0; pk1 = npk1;
    }

    if (j < end) {
        int s0 = pk0 & 0x7FFF, r0 = pk0 >> 15;
        float4 xv = *(const float4*)(X + (size_t)s0 * DD + lane * 4);
        float xa[4] = {xv.x, xv.y, xv.z, xv.w};
        float p0 = 0.f, p1 = 0.f;
        #pragma unroll
        for (int i = 0; i < 4; i++) {
            p0 = fmaf(qt[r0 * 2][i],     xa[i], p0);
            p1 = fmaf(qt[r0 * 2 + 1][i], xa[i], p1);
        }
        #pragma unroll
        for (int off = 16; off >= 1; off >>= 1) {
            p0 += __shfl_xor_sync(0xffffffffu, p0, off);
            p1 += __shfl_xor_sync(0xffffffffu, p1, off);
        }
        float nu0 = fmaxf(p0 / SCALE, 0.0f); nu0 = nu0 * nu0 + 1e-10f;
        float nu1 = fmaxf(p1 / SCALE, 0.0f); nu1 = nu1 * nu1 + 1e-10f;
        den0 += nu0;
        den1 += nu1;
        if (r0 == 0) {
            #pragma unroll
            for (int i = 0; i < 4; i++) { y[0][0][i] += nu0 * xa[i]; y[0][1][i] += nu1 * xa[i]; }
        } else if (r0 == 1) {
            #pragma unroll
            for (int i = 0; i < 4; i++) { y[1][0][i] += nu0 * xa[i]; y[1][1][i] += nu1 * xa[i]; }
        } else {
            #pragma unroll
            for (int i = 0; i < 4; i++) { y[2][0][i] += nu0 * xa[i]; y[2][1][i] += nu1 * xa[i]; }
        }
    }

    float inv0 = (den0 > 0.0f) ? 1.0f / den0 : 0.0f;
    float inv1 = (den1 > 0.0f) ? 1.0f / den1 : 0.0f;

    // writeout: single fp16 limb, 4 halfs (8B) per (r,h) per lane
    #pragma unroll
    for (int r = 0; r < 3; r++)
        #pragma unroll
        for (int h = 0; h < 2; h++) {
            float sc = h ? inv1 : inv0;
            size_t off = (size_t)warp * YW + (r * 2 + h) * 128 + lane * 4;
            __half hv[4];
            #pragma unroll
            for (int i = 0; i < 4; i++)
                hv[i] = __float2half(y[r][h][i] * sc);
            *(uint2*)(g_yf + off) = *(uint2*)hv;
        }
}

// ---------------- launch ----------------
extern "C" void kernel_launch(void* const* d_in, const int* in_sizes, int n_in,
                              void* d_out, int out_size)
{
    const float* X   = (const float*)d_in[0];
    const float* WQ  = (const float*)d_in[1];
    const float* WK  = (const float*)d_in[2];
    const float* WV  = (const float*)d_in[3];
    const float* WO  = (const float*)d_in[4];
    const int*  esrc = (const int*)d_in[5];
    const int*  edst = (const int*)d_in[6];
    const int*  erel = (const int*)d_in[7];
    float* out = (float*)d_out;

    const int N = NN;

    float* qt;
    cudaGetSymbolAddress((void**)&qt, g_qt);
    __half *xf, *wsc, *wf, *yf;
    cudaGetSymbolAddress((void**)&xf,  g_xf);
    cudaGetSymbolAddress((void**)&wsc, g_wsc);
    cudaGetSymbolAddress((void**)&wf,  g_wf);
    cudaGetSymbolAddress((void**)&yf,  g_yf);

    // split-K partial buffers carved out of g_qt (dead after k_node)
    float* part0 = qt;
    float* part1 = qt + (size_t)MPAD * DD;

    cudaFuncSetAttribute(k_mma_gemm<DD, DD, false, true>,
                         cudaFuncAttributeMaxDynamicSharedMemorySize, GSMEM);
    cudaFuncSetAttribute(k_mma_gemm<YW, YW / 2, true, false>,
                         cudaFuncAttributeMaxDynamicSharedMemorySize, GSMEM);

    // 1. merged prologue: x fp16 + y-pad zero + weight preprocessing + deg histogram
    k_prologue<<<PRO_BLKS, 256>>>(X, WQ, WK, WO, WV, edst);

    // 2. scan degrees -> rowptr (re-zeroes deg)
    k_scan<<<1, 1024>>>(N);

    // 3. transformed-query GEMM + fused CSR scatter (scatter blocks scheduled first)
    {
        dim3 grid(YW / 128, SC_BY + MPAD / 128);
        k_mma_gemm<DD, DD, false, true><<<grid, 256, GSMEM>>>(
            xf, wsc, qt, nullptr, N, YW, esrc, edst, erel);
    }

    // 4. fused node pass (re-zeroes cursor): scores + denom + weighted-x agg -> yf
    k_node<<<(N + 7) / 8, 256>>>(X, N);

    // 5. final GEMM, split-K 2-way: [MPAD,768] x [128,768]^T -> partials
    {
        dim3 grid(2, MPAD / 128);
        k_mma_gemm<YW, YW / 2, true, false><<<grid, 256, GSMEM>>>(
            yf, wf, part0, part1, N, DD, nullptr, nullptr, nullptr);
    }

    // 6. sum partials -> out
    k_addout<<<(N * DD / 4 + 255) / 256, 256>>>(part0, part1, out, N * DD / 4);
}

// round 17
// speedup vs baseline: 1.9557x; 1.0776x over previous
#include <cuda_runtime.h>
#include <cuda_bf16.h>
#include <cuda_fp16.h>
#include <cstdint>

// Problem constants (fixed by the dataset)
#define NN    20000
#define MPAD  20096        // 157 * 128
#define EE    320000
#define DD    128
#define HD    256
#define YW    768          // 3 rel * 2 head * 128
#define SCALE 16.0f

// ---------------- scratch (device globals; no allocation) ----------------
__device__ float   g_qt[(size_t)NN * YW];        // fp32 transformed queries; reused as split-K partials
__device__ __half  g_xf[(size_t)MPAD * DD];      // x in fp16
__device__ __half  g_wsc[(size_t)YW * DD];       // Wsc = WK^T WQ blocks, fp16 [768,128]
__device__ __half  g_wf[(size_t)DD * YW];        // Wfin = WO x WV blocks, fp16 [128,768]
__device__ __half  g_yf[(size_t)MPAD * YW];      // weighted-x aggregate, fp16
__device__ int   g_deg[NN];        // zero at load; re-zeroed by k_scan each call
__device__ int   g_rowptr[NN + 1];
__device__ int   g_cursor[NN];     // zero at load; re-zeroed by k_node each call
__device__ int   g_pack[EE];       // CSR-ordered src | (rel<<15)

__device__ __forceinline__ uint32_t smem_u32(const void* p) {
    uint32_t a;
    asm("{ .reg .u64 t; cvta.to.shared.u64 t, %1; cvt.u32.u64 %0, t; }" : "=r"(a) : "l"(p));
    return a;
}
__device__ __forceinline__ void ldsm_x4(uint32_t& r0, uint32_t& r1, uint32_t& r2, uint32_t& r3,
                                        uint32_t addr) {
    asm volatile("ldmatrix.sync.aligned.m8n8.x4.shared.b16 {%0,%1,%2,%3}, [%4];"
                 : "=r"(r0), "=r"(r1), "=r"(r2), "=r"(r3) : "r"(addr));
}
__device__ __forceinline__ void mma_f16(float* d, const uint32_t* a, const uint32_t* b) {
    asm volatile(
        "mma.sync.aligned.m16n8k16.row.col.f32.f16.f16.f32 "
        "{%0,%1,%2,%3}, {%4,%5,%6,%7}, {%8,%9}, {%0,%1,%2,%3};"
        : "+f"(d[0]), "+f"(d[1]), "+f"(d[2]), "+f"(d[3])
        : "r"(a[0]), "r"(a[1]), "r"(a[2]), "r"(a[3]), "r"(b[0]), "r"(b[1]));
}
#define CP_ASYNC16(dst, src) \
    asm volatile("cp.async.cg.shared.global [%0], [%1], 16;\n" :: "r"(dst), "l"(src))
#define CP_COMMIT() asm volatile("cp.async.commit_group;\n" ::: "memory")
#define CP_WAIT(n)  asm volatile("cp.async.wait_group %0;\n" :: "n"(n) : "memory")

// ---------------- merged prologue: x fp16 (vec4) | y-pad zero | weight pre | deg histogram ----------------
#define SPLIT_BLKS 2512            // MPAD*DD/4 elems, 4 per thread
#define PAD_BLKS   288
#define WPRE_BLKS  768
#define DEG_BLKS   1250
#define PRO_BLKS   (SPLIT_BLKS + PAD_BLKS + WPRE_BLKS + DEG_BLKS)

__global__ __launch_bounds__(256)
void k_prologue(const float* __restrict__ X,
                const float* __restrict__ WQ, const float* __restrict__ WK,
                const float* __restrict__ WO, const float* __restrict__ WV,
                const int* __restrict__ edst)
{
    int blk = blockIdx.x;
    int t = threadIdx.x;

    if (blk < SPLIT_BLKS) {
        int i4 = blk * 256 + t;            // index of 4-elem group
        int i = i4 * 4;
        float4 xv;
        if (i < NN * DD) {
            xv = *(const float4*)(X + i);
        } else {
            xv = make_float4(0.f, 0.f, 0.f, 0.f);
        }
        __half2 h0 = __floats2half2_rn(xv.x, xv.y);
        __half2 h1 = __floats2half2_rn(xv.z, xv.w);
        uint2 u;
        u.x = *(uint32_t*)&h0;
        u.y = *(uint32_t*)&h1;
        *(uint2*)(g_xf + i) = u;
        return;
    }
    blk -= SPLIT_BLKS;
    if (blk < PAD_BLKS) {
        int i = blk * 256 + t;     // < 73728
        g_yf[(size_t)NN * YW + i] = __float2half(0.0f);
        return;
    }
    blk -= PAD_BLKS;
    if (blk < WPRE_BLKS) {
        int idx = blk * 256 + t;          // < 196608
        int sec = idx >> 14;              // 0..11
        int row = (idx >> 7) & 127;
        int col = idx & 127;
        if (sec < 6) {
            int rh = sec, r = rh >> 1, h = rh & 1;
            int k = row, d2 = col;
            const float* wk = WK + (size_t)r * HD * DD + (size_t)(h * 128) * DD + k;
            const float* wq = WQ + (size_t)(h * 128) * DD + d2;
            float a0 = 0.f, a1 = 0.f, a2 = 0.f, a3 = 0.f;
            #pragma unroll
            for (int d = 0; d < 128; d += 4) {
                a0 = fmaf(wk[(size_t)(d + 0) * DD], wq[(size_t)(d + 0) * DD], a0);
                a1 = fmaf(wk[(size_t)(d + 1) * DD], wq[(size_t)(d + 1) * DD], a1);
                a2 = fmaf(wk[(size_t)(d + 2) * DD], wq[(size_t)(d + 2) * DD], a2);
                a3 = fmaf(wk[(size_t)(d + 3) * DD], wq[(size_t)(d + 3) * DD], a3);
            }
            float acc = (a0 + a1) + (a2 + a3);
            g_wsc[(size_t)(rh * 128 + k) * DD + d2] = __float2half(acc);
        } else {
            int rh = sec - 6, r = rh >> 1, h = rh & 1;
            int o = row, k = col;
            const float* wo = WO + o * HD + h * 128;
            const float* wv = WV + ((size_t)(r * HD + h * 128)) * DD + k;
            float a0 = 0.f, a1 = 0.f, a2 = 0.f, a3 = 0.f;
            #pragma unroll
            for (int d = 0; d < 128; d += 4) {
                a0 = fmaf(wo[d + 0], wv[(size_t)(d + 0) * DD], a0);
                a1 = fmaf(wo[d + 1], wv[(size_t)(d + 1) * DD], a1);
                a2 = fmaf(wo[d + 2], wv[(size_t)(d + 2) * DD], a2);
                a3 = fmaf(wo[d + 3], wv[(size_t)(d + 3) * DD], a3);
            }
            float acc = (a0 + a1) + (a2 + a3);
            g_wf[(size_t)o * YW + rh * 128 + k] = __float2half(acc);
        }
        return;
    }
    blk -= WPRE_BLKS;
    {
        int e = blk * 256 + t;
        if (e < EE) atomicAdd(&g_deg[edst[e]], 1);
    }
}

// ---------------- fast scan (also re-zeroes deg for the next replay) ----------------
__global__ __launch_bounds__(1024) void k_scan(int n)
{
    const int P = 20;
    __shared__ int wsum[32];
    int tid = threadIdx.x, lane = tid & 31, wid = tid >> 5;
    int base = tid * P;
    int v[P];
    int s = 0;
    #pragma unroll
    for (int i = 0; i < P; i++) {
        int idx = base + i;
        int d = (idx < n) ? g_deg[idx] : 0;
        if (idx < n) g_deg[idx] = 0;   // self-clean for next graph replay
        s += d;
        v[i] = s;
    }
    int x = s;
    #pragma unroll
    for (int off = 1; off < 32; off <<= 1) {
        int t = __shfl_up_sync(0xffffffffu, x, off);
        if (lane >= off) x += t;
    }
    if (lane == 31) wsum[wid] = x;
    __syncthreads();
    if (wid == 0) {
        int y = wsum[lane];
        #pragma unroll
        for (int off = 1; off < 32; off <<= 1) {
            int t = __shfl_up_sync(0xffffffffu, y, off);
            if (lane >= off) y += t;
        }
        wsum[lane] = y;
    }
    __syncthreads();
    int offset = (wid ? wsum[wid - 1] : 0) + x - s;
    if (tid == 0) g_rowptr[0] = 0;
    #pragma unroll
    for (int i = 0; i < P; i++) {
        int idx = base + i;
        if (idx < n) g_rowptr[idx + 1] = offset + v[i];
    }
}

// ---------------- mma.sync GEMM: fp16, 4-stage cp.async pipeline ----------------
// FSCAT: the first SC_BY rows of blockIdx.y do the CSR scatter instead (overlapped).
#define SSTR   40
#define TILEB  10240
#define SMSTAGE (2 * TILEB)        // A, B
#define GSMEM   (4 * SMSTAGE)      // 81920 B
#define SC_BY   50                 // 50 * gridDim.x(6) = 300 scatter blocks

template <int KSTR, int KLEN, bool SPLITK, bool FSCAT>
__global__ __launch_bounds__(256)
void k_mma_gemm(const __half* __restrict__ A, const __half* __restrict__ B,
                float* __restrict__ C0, float* __restrict__ C1, int Mreal, int ldc,
                const int* __restrict__ esrc, const int* __restrict__ edst,
                const int* __restrict__ erel)
{
    if (FSCAT && blockIdx.y < SC_BY) {
        int nthr = SC_BY * gridDim.x * 256;
        int idx = (blockIdx.y * gridDim.x + blockIdx.x) * 256 + threadIdx.x;
        for (int e = idx; e < EE; e += nthr) {
            int dst = edst[e];
            int pos = atomicAdd(&g_cursor[dst], 1);
            g_pack[g_rowptr[dst] + pos] = esrc[e] | (erel[e] << 15);
        }
        return;
    }

    extern __shared__ uint8_t dsm[];
    const uint32_t sb = smem_u32(dsm);
    const int tid  = threadIdx.x;
    const int wid  = tid >> 5;
    const int lane = tid & 31;
    const int by = FSCAT ? (blockIdx.y - SC_BY) : blockIdx.y;
    const int m0 = by * 128;
    const int j0 = SPLITK ? 0 : blockIdx.x * 128;
    const int koff = SPLITK ? blockIdx.x * KLEN : 0;
    float* C = (SPLITK && blockIdx.x) ? C1 : C0;
    const int warp_m = (wid & 3) * 32;
    const int warp_n = (wid >> 2) * 64;

    const int ar = lane & 15;
    const int kh = (lane >> 4) << 3;

    float acc[2][8][4];
    #pragma unroll
    for (int i = 0; i < 2; i++)
        #pragma unroll
        for (int j = 0; j < 8; j++)
            #pragma unroll
            for (int q = 0; q < 4; q++) acc[i][j][q] = 0.0f;

    int rowA[2], c8A[2];
    #pragma unroll
    for (int i = 0; i < 2; i++) {
        int v = tid + i * 256;
        rowA[i] = v >> 2;
        c8A[i] = (v & 3) << 3;
    }

    auto prefetch = [&](int ch) {
        uint32_t base = sb + (uint32_t)(ch & 3) * SMSTAGE;
        int kt = ch * 32;
        #pragma unroll
        for (int i = 0; i < 2; i++) {
            int row = rowA[i], c8 = c8A[i];
            uint32_t so = base + (uint32_t)(row * SSTR + c8) * 2;
            size_t ga = (size_t)(m0 + row) * KSTR + koff + kt + c8;
            size_t gb = (size_t)(j0 + row) * KSTR + koff + kt + c8;
            CP_ASYNC16(so,         A + ga);
            CP_ASYNC16(so + TILEB, B + gb);
        }
        CP_COMMIT();
    };

    constexpr int NCH = KLEN / 32;
    prefetch(0);
    if (NCH > 1) prefetch(1);
    if (NCH > 2) prefetch(2);

    for (int ch = 0; ch < NCH; ch++) {
        if (ch >= NCH - 1)      { CP_WAIT(0); }
        else if (ch == NCH - 2) { CP_WAIT(1); }
        else                    { CP_WAIT(2); }
        __syncthreads();
        if (ch + 3 < NCH) prefetch(ch + 3);

        uint32_t base = sb + (uint32_t)(ch & 3) * SMSTAGE;
        #pragma unroll
        for (int k16 = 0; k16 < 2; k16++) {
            uint32_t kb = (uint32_t)((k16 * 16 + kh) * 2);

            uint32_t a[2][4];
            #pragma unroll
            for (int mi = 0; mi < 2; mi++) {
                uint32_t off = (uint32_t)((warp_m + mi * 16 + ar) * SSTR * 2) + kb;
                ldsm_x4(a[mi][0], a[mi][1], a[mi][2], a[mi][3], base + off);
            }
            uint32_t b[8][2];
            #pragma unroll
            for (int ng = 0; ng < 4; ng++) {
                uint32_t off = (uint32_t)((warp_n + ng * 16 + ar) * SSTR * 2) + kb;
                uint32_t r0, r1, r2, r3;
                ldsm_x4(r0, r1, r2, r3, base + TILEB + off);
                b[ng * 2][0] = r0;     b[ng * 2][1] = r2;
                b[ng * 2 + 1][0] = r1; b[ng * 2 + 1][1] = r3;
            }
            #pragma unroll
            for (int mi = 0; mi < 2; mi++)
                #pragma unroll
                for (int nj = 0; nj < 8; nj++)
                    mma_f16(acc[mi][nj], a[mi], b[nj]);
        }
        // no trailing sync: stage rewrite happens >=3 barriers later
    }

    const int rg = lane >> 2;
    const int tg = lane & 3;
    #pragma unroll
    for (int mi = 0; mi < 2; mi++) {
        int r0 = m0 + warp_m + mi * 16 + rg;
        int r1 = r0 + 8;
        #pragma unroll
        for (int nj = 0; nj < 8; nj++) {
            int col = j0 + warp_n + nj * 8 + tg * 2;
            if (r0 < Mreal) {
                float2 v = {acc[mi][nj][0], acc[mi][nj][1]};
                *(float2*)(C + (size_t)r0 * ldc + col) = v;
            }
            if (r1 < Mreal) {
                float2 v = {acc[mi][nj][2], acc[mi][nj][3]};
                *(float2*)(C + (size_t)r1 * ldc + col) = v;
            }
        }
    }
}

// ---------------- split-K partial sum -> out ----------------
__global__ void k_addout(const float* __restrict__ p0, const float* __restrict__ p1,
                         float* __restrict__ out, int n4)
{
    int i = blockIdx.x * blockDim.x + threadIdx.x;
    if (i >= n4) return;
    float4 a = ((const float4*)p0)[i];
    float4 b = ((const float4*)p1)[i];
    float4 v = {a.x + b.x, a.y + b.y, a.z + b.z, a.w + b.w};
    ((float4*)out)[i] = v;
}

// ---------------- fused node kernel: fp16 x gathers (halved L1 traffic) ----------------
__global__ __launch_bounds__(256)
void k_node(int N)
{
    int warp = (blockIdx.x * blockDim.x + threadIdx.x) >> 5;
    int lane = threadIdx.x & 31;
    if (warp >= N) return;

    if (lane == 0) g_cursor[warp] = 0;   // self-clean for next graph replay

    const int start = g_rowptr[warp];
    const int end   = g_rowptr[warp + 1];

    float qt[6][4];
    {
        const float* qr = g_qt + (size_t)warp * YW;
        #pragma unroll
        for (int c = 0; c < 6; c++) {
            float4 v = *(const float4*)(qr + c * 128 + lane * 4);
            qt[c][0] = v.x; qt[c][1] = v.y; qt[c][2] = v.z; qt[c][3] = v.w;
        }
    }

    float y[3][2][4];
    #pragma unroll
    for (int r = 0; r < 3; r++)
        #pragma unroll
        for (int h = 0; h < 2; h++)
            #pragma unroll
            for (int i = 0; i < 4; i++) y[r][h][i] = 0.0f;

    float den0 = 0.0f, den1 = 0.0f;

    int j = start;
    int pk0 = (j < end)     ? g_pack[j]     : 0;
    int pk1 = (j + 1 < end) ? g_pack[j + 1] : 0;

    while (j + 1 < end) {
        int s0 = pk0 & 0x7FFF, r0 = pk0 >> 15;
        int s1 = pk1 & 0x7FFF, r1 = pk1 >> 15;
        int nj = j + 2;
        int npk0 = (nj < end)     ? g_pack[nj]     : 0;
        int npk1 = (nj + 1 < end) ? g_pack[nj + 1] : 0;

        uint2 u0 = *(const uint2*)(g_xf + (size_t)s0 * DD + lane * 4);
        uint2 u1 = *(const uint2*)(g_xf + (size_t)s1 * DD + lane * 4);
        float2 f00 = __half22float2(*(__half2*)&u0.x);
        float2 f01 = __half22float2(*(__half2*)&u0.y);
        float2 f10 = __half22float2(*(__half2*)&u1.x);
        float2 f11 = __half22float2(*(__half2*)&u1.y);
        float xa0[4] = {f00.x, f00.y, f01.x, f01.y};
        float xa1[4] = {f10.x, f10.y, f11.x, f11.y};

        float p00 = 0.f, p01 = 0.f, p10 = 0.f, p11 = 0.f;
        #pragma unroll
        for (int i = 0; i < 4; i++) {
            p00 = fmaf(qt[r0 * 2][i],     xa0[i], p00);
            p01 = fmaf(qt[r0 * 2 + 1][i], xa0[i], p01);
            p10 = fmaf(qt[r1 * 2][i],     xa1[i], p10);
            p11 = fmaf(qt[r1 * 2 + 1][i], xa1[i], p11);
        }
        #pragma unroll
        for (int off = 16; off >= 1; off >>= 1) {
            p00 += __shfl_xor_sync(0xffffffffu, p00, off);
            p01 += __shfl_xor_sync(0xffffffffu, p01, off);
            p10 += __shfl_xor_sync(0xffffffffu, p10, off);
            p11 += __shfl_xor_sync(0xffffffffu, p11, off);
        }
        float nuA0 = fmaxf(p00 / SCALE, 0.0f); nuA0 = nuA0 * nuA0 + 1e-10f;
        float nuA1 = fmaxf(p01 / SCALE, 0.0f); nuA1 = nuA1 * nuA1 + 1e-10f;
        float nuB0 = fmaxf(p10 / SCALE, 0.0f); nuB0 = nuB0 * nuB0 + 1e-10f;
        float nuB1 = fmaxf(p11 / SCALE, 0.0f); nuB1 = nuB1 * nuB1 + 1e-10f;
        den0 += nuA0 + nuB0;
        den1 += nuA1 + nuB1;

        if (r0 == 0) {
            #pragma unroll
            for (int i = 0; i < 4; i++) { y[0][0][i] += nuA0 * xa0[i]; y[0][1][i] += nuA1 * xa0[i]; }
        } else if (r0 == 1) {
            #pragma unroll
            for (int i = 0; i < 4; i++) { y[1][0][i] += nuA0 * xa0[i]; y[1][1][i] += nuA1 * xa0[i]; }
        } else {
            #pragma unroll
            for (int i = 0; i < 4; i++) { y[2][0][i] += nuA0 * xa0[i]; y[2][1][i] += nuA1 * xa0[i]; }
        }
        if (r1 == 0) {
            #pragma unroll
            for (int i = 0; i < 4; i++) { y[0][0][i] += nuB0 * xa1[i]; y[0][1][i] += nuB1 * xa1[i]; }
        } else if (r1 == 1) {
            #pragma unroll
            for (int i = 0; i < 4; i++) { y[1][0][i] += nuB0 * xa1[i]; y[1][1][i] += nuB1 * xa1[i]; }
        } else {
            #pragma unroll
            for (int i = 0; i < 4; i++) { y[2][0][i] += nuB0 * xa1[i]; y[2][1][i] += nuB1 * xa1[i]; }
        }

        j = nj; pk0 = npk0; pk1 = npk1;
    }

    if (j < end) {
        int s0 = pk0 & 0x7FFF, r0 = pk0 >> 15;
        uint2 u0 = *(const uint2*)(g_xf + (size_t)s0 * DD + lane * 4);
        float2 f0 = __half22float2(*(__half2*)&u0.x);
        float2 f1 = __half22float2(*(__half2*)&u0.y);
        float xa[4] = {f0.x, f0.y, f1.x, f1.y};
        float p0 = 0.f, p1 = 0.f;
        #pragma unroll
        for (int i = 0; i < 4; i++) {
            p0 = fmaf(qt[r0 * 2][i],     xa[i], p0);
            p1 = fmaf(qt[r0 * 2 + 1][i], xa[i], p1);
        }
        #pragma unroll
        for (int off = 16; off >= 1; off >>= 1) {
            p0 += __shfl_xor_sync(0xffffffffu, p0, off);
            p1 += __shfl_xor_sync(0xffffffffu, p1, off);
        }
        float nu0 = fmaxf(p0 / SCALE, 0.0f); nu0 = nu0 * nu0 + 1e-10f;
        float nu1 = fmaxf(p1 / SCALE, 0.0f); nu1 = nu1 * nu1 + 1e-10f;
        den0 += nu0;
        den1 += nu1;
        if (r0 == 0) {
            #pragma unroll
            for (int i = 0; i < 4; i++) { y[0][0][i] += nu0 * xa[i]; y[0][1][i] += nu1 * xa[i]; }
        } else if (r0 == 1) {
            #pragma unroll
            for (int i = 0; i < 4; i++) { y[1][0][i] += nu0 * xa[i]; y[1][1][i] += nu1 * xa[i]; }
        } else {
            #pragma unroll
            for (int i = 0; i < 4; i++) { y[2][0][i] += nu0 * xa[i]; y[2][1][i] += nu1 * xa[i]; }
        }
    }

    float inv0 = (den0 > 0.0f) ? 1.0f / den0 : 0.0f;
    float inv1 = (den1 > 0.0f) ? 1.0f / den1 : 0.0f;

    // writeout: single fp16 limb, 4 halfs (8B) per (r,h) per lane
    #pragma unroll
    for (int r = 0; r < 3; r++)
        #pragma unroll
        for (int h = 0; h < 2; h++) {
            float sc = h ? inv1 : inv0;
            size_t off = (size_t)warp * YW + (r * 2 + h) * 128 + lane * 4;
            __half hv[4];
            #pragma unroll
            for (int i = 0; i < 4; i++)
                hv[i] = __float2half(y[r][h][i] * sc);
            *(uint2*)(g_yf + off) = *(uint2*)hv;
        }
}

// ---------------- launch ----------------
extern "C" void kernel_launch(void* const* d_in, const int* in_sizes, int n_in,
                              void* d_out, int out_size)
{
    const float* X   = (const float*)d_in[0];
    const float* WQ  = (const float*)d_in[1];
    const float* WK  = (const float*)d_in[2];
    const float* WV  = (const float*)d_in[3];
    const float* WO  = (const float*)d_in[4];
    const int*  esrc = (const int*)d_in[5];
    const int*  edst = (const int*)d_in[6];
    const int*  erel = (const int*)d_in[7];
    float* out = (float*)d_out;

    const int N = NN;

    float* qt;
    cudaGetSymbolAddress((void**)&qt, g_qt);
    __half *xf, *wsc, *wf, *yf;
    cudaGetSymbolAddress((void**)&xf,  g_xf);
    cudaGetSymbolAddress((void**)&wsc, g_wsc);
    cudaGetSymbolAddress((void**)&wf,  g_wf);
    cudaGetSymbolAddress((void**)&yf,  g_yf);

    // split-K partial buffers carved out of g_qt (dead after k_node)
    float* part0 = qt;
    float* part1 = qt + (size_t)MPAD * DD;

    cudaFuncSetAttribute(k_mma_gemm<DD, DD, false, true>,
                         cudaFuncAttributeMaxDynamicSharedMemorySize, GSMEM);
    cudaFuncSetAttribute(k_mma_gemm<YW, YW / 2, true, false>,
                         cudaFuncAttributeMaxDynamicSharedMemorySize, GSMEM);

    // 1. merged prologue: x fp16 + y-pad zero + weight preprocessing + deg histogram
    k_prologue<<<PRO_BLKS, 256>>>(X, WQ, WK, WO, WV, edst);

    // 2. scan degrees -> rowptr (re-zeroes deg)
    k_scan<<<1, 1024>>>(N);

    // 3. transformed-query GEMM + fused CSR scatter (scatter blocks scheduled first)
    {
        dim3 grid(YW / 128, SC_BY + MPAD / 128);
        k_mma_gemm<DD, DD, false, true><<<grid, 256, GSMEM>>>(
            xf, wsc, qt, nullptr, N, YW, esrc, edst, erel);
    }

    // 4. fused node pass (re-zeroes cursor): scores + denom + weighted-x agg -> yf
    k_node<<<(N + 7) / 8, 256>>>(N);

    // 5. final GEMM, split-K 2-way: [MPAD,768] x [128,768]^T -> partials
    {
        dim3 grid(2, MPAD / 128);
        k_mma_gemm<YW, YW / 2, true, false><<<grid, 256, GSMEM>>>(
            yf, wf, part0, part1, N, DD, nullptr, nullptr, nullptr);
    }

    // 6. sum partials -> out
    k_addout<<<(N * DD / 4 + 255) / 256, 256>>>(part0, part1, out, N * DD / 4);
}